// round 4
// baseline (speedup 1.0000x reference)
#include <cuda_runtime.h>
#include <math.h>

#define TT 500
#define BB 128
#define NN 300
#define EE 128
#define CC 128
#define UU 64
#define FF 4
#define CLIPV 5.0f
#define SCAN_P 64
#define MROWS (TT*BB)   // 64000

// ---- static device scratch (no runtime alloc allowed) ----
__device__ float d_xpf[MROWS * 384];
__device__ float d_xpb[MROWS * 384];
__device__ float d_cp [MROWS * 384];
__device__ float d_g  [MROWS * 256];
__device__ float d_hc [MROWS * 128];
__device__ float d_mu [MROWS * 64];
__device__ float d_lv [MROWS * 64];
__device__ float d_uf [MROWS * 68];
__device__ float d_spk[MROWS * 300];
__device__ float d_hstate[2 * 2 * EE * BB];
__device__ int   d_ctr[4];

__device__ __forceinline__ float sigm(float x) { return 1.0f / (1.0f + expf(-x)); }

__global__ void zero_ctr_kernel() {
    if (threadIdx.x < 4) d_ctr[threadIdx.x] = 0;
}

// ---- SGEMM: C[M,Ncols] = A[M,K] @ W[Ncols,K]^T (+bias). flags bit0: accumulate, bit1: spike epilogue ----
__global__ __launch_bounds__(256) void sgemm_kernel(
    const float* __restrict__ A, int lda,
    const float* __restrict__ W, int ldw,
    const float* __restrict__ bias,
    float* __restrict__ C, int ldc,
    int N, int K, int flags)
{
    __shared__ float As[8][128];
    __shared__ float Ws[8][128];
    const int tid = threadIdx.x;
    const int m0 = blockIdx.y * 128;
    const int n0 = blockIdx.x * 128;
    const int lr = tid >> 1;
    const int lc = (tid & 1) << 2;
    const int tx = tid & 15;
    const int ty = tid >> 4;

    float acc[8][8];
#pragma unroll
    for (int i = 0; i < 8; i++)
#pragma unroll
        for (int j = 0; j < 8; j++) acc[i][j] = 0.0f;

    for (int k0 = 0; k0 < K; k0 += 8) {
        {
            float4 v = make_float4(0.f, 0.f, 0.f, 0.f);
            int kbase = k0 + lc;
            int rem = K - kbase;
            const float* Ap = A + (size_t)(m0 + lr) * lda + kbase;
            if (rem >= 4) v = *(const float4*)Ap;
            else if (rem > 0) {
                v.x = Ap[0];
                if (rem > 1) v.y = Ap[1];
                if (rem > 2) v.z = Ap[2];
            }
            As[lc + 0][lr] = v.x; As[lc + 1][lr] = v.y;
            As[lc + 2][lr] = v.z; As[lc + 3][lr] = v.w;
        }
        {
            float4 v = make_float4(0.f, 0.f, 0.f, 0.f);
            int n = n0 + lr;
            int kbase = k0 + lc;
            int rem = K - kbase;
            if (n < N && rem > 0) {
                const float* Wp = W + (size_t)n * ldw + kbase;
                if (rem >= 4) v = *(const float4*)Wp;
                else {
                    v.x = Wp[0];
                    if (rem > 1) v.y = Wp[1];
                    if (rem > 2) v.z = Wp[2];
                }
            }
            Ws[lc + 0][lr] = v.x; Ws[lc + 1][lr] = v.y;
            Ws[lc + 2][lr] = v.z; Ws[lc + 3][lr] = v.w;
        }
        __syncthreads();
#pragma unroll
        for (int k = 0; k < 8; k++) {
            float a[8], bb[8];
            *(float4*)&a[0]  = *(const float4*)&As[k][ty * 8];
            *(float4*)&a[4]  = *(const float4*)&As[k][ty * 8 + 4];
            *(float4*)&bb[0] = *(const float4*)&Ws[k][tx * 8];
            *(float4*)&bb[4] = *(const float4*)&Ws[k][tx * 8 + 4];
#pragma unroll
            for (int i = 0; i < 8; i++)
#pragma unroll
                for (int j = 0; j < 8; j++)
                    acc[i][j] = fmaf(a[i], bb[j], acc[i][j]);
        }
        __syncthreads();
    }

#pragma unroll
    for (int i = 0; i < 8; i++) {
        int m = m0 + ty * 8 + i;
#pragma unroll
        for (int j = 0; j < 8; j++) {
            int n = n0 + tx * 8 + j;
            if (n < N) {
                float v = acc[i][j];
                if (bias) v += bias[n];
                size_t off = (size_t)m * ldc + n;
                if (flags & 1) v += C[off];
                if (flags & 2) v = fmaxf(expf(v) - 1.0f, 0.0f);
                C[off] = v;
            }
        }
    }
}

// ---- persistent grid-synced GRU scan. Handles 1 or 2 directions (dir = blockIdx.x / SCAN_P). ----
// Each block owns 2 hidden units; 256 threads = (e_local, batch). State in global
// d_hstate, [feature][batch] layout; per-step copy into smem for reuse.
__global__ __launch_bounds__(256) void gru_scan_kernel(
    const float* __restrict__ xp_a, const float* __restrict__ xp_b,
    const float* __restrict__ W_a,  const float* __restrict__ W_b,
    const float* __restrict__ bh_a, const float* __restrict__ bh_b,
    const float* __restrict__ init_a, const float* __restrict__ init_b,
    float* __restrict__ out, int out_ld, int col_a, int col_b,
    int clip_state, int rev_b,
    int* __restrict__ ctrs, float* __restrict__ hstate)
{
    extern __shared__ float sm[];
    float* hs = sm;                 // [128 features][128 batch]
    float* sW = sm + EE * BB;       // [3][2][128]

    const int dir = blockIdx.x / SCAN_P;
    const int jb  = blockIdx.x % SCAN_P;
    const float* xp   = dir ? xp_b   : xp_a;
    const float* Whh  = dir ? W_b    : W_a;
    const float* bhh  = dir ? bh_b   : bh_a;
    const float* hini = dir ? init_b : init_a;
    const int colbase = dir ? col_b  : col_a;
    const int rev     = dir ? rev_b  : 0;
    int* ctr = ctrs + dir;
    float* hbuf0 = hstate + (size_t)dir * 2 * EE * BB;
    float* hbuf1 = hbuf0 + EE * BB;

    const int tid = threadIdx.x;
    const int e_l = tid >> 7;
    const int b   = tid & 127;
    const int e   = jb * 2 + e_l;

    for (int i = tid; i < 3 * 2 * 128; i += 256) {
        int g  = i >> 8;
        int el = (i >> 7) & 1;
        int k  = i & 127;
        sW[i] = Whh[(size_t)(g * EE + jb * 2 + el) * EE + k];
    }
    const float br = bhh[e];
    const float bz = bhh[EE + e];
    const float bn = bhh[2 * EE + e];

    if (e_l == 0) hbuf0[e * BB + b] = hini[e];
    if (e_l == 1) hbuf0[e * BB + b] = hini[e];
    __threadfence();
    __syncthreads();
    if (tid == 0) {
        atomicAdd(ctr, 1);
        while (*(volatile int*)ctr < SCAN_P) {}
    }
    __syncthreads();

    const float4* wr4 = (const float4*)(sW + 0 * 256 + e_l * 128);
    const float4* wz4 = (const float4*)(sW + 1 * 256 + e_l * 128);
    const float4* wn4 = (const float4*)(sW + 2 * 256 + e_l * 128);

    for (int s = 0; s < TT; s++) {
        const float* hin  = (s & 1) ? hbuf1 : hbuf0;
        float*       hout = (s & 1) ? hbuf0 : hbuf1;

        for (int i = tid * 4; i < EE * BB; i += 1024) {
            float4 v = __ldcg((const float4*)(hin + i));
            *(float4*)(hs + i) = v;
        }
        __syncthreads();

        float arr = 0.f, azz = 0.f, ann = 0.f;
#pragma unroll
        for (int kk = 0; kk < 32; kk++) {
            float4 wr = wr4[kk], wz = wz4[kk], wn = wn4[kk];
            int k4 = kk * 4;
            float h0 = hs[(k4 + 0) * BB + b];
            float h1 = hs[(k4 + 1) * BB + b];
            float h2 = hs[(k4 + 2) * BB + b];
            float h3 = hs[(k4 + 3) * BB + b];
            arr = fmaf(wr.x, h0, arr); arr = fmaf(wr.y, h1, arr);
            arr = fmaf(wr.z, h2, arr); arr = fmaf(wr.w, h3, arr);
            azz = fmaf(wz.x, h0, azz); azz = fmaf(wz.y, h1, azz);
            azz = fmaf(wz.z, h2, azz); azz = fmaf(wz.w, h3, azz);
            ann = fmaf(wn.x, h0, ann); ann = fmaf(wn.y, h1, ann);
            ann = fmaf(wn.z, h2, ann); ann = fmaf(wn.w, h3, ann);
        }

        const int t = rev ? (TT - 1 - s) : s;
        const float* xr = xp + ((size_t)t * BB + b) * 384;
        float r = sigm(xr[e] + arr + br);
        float z = sigm(xr[EE + e] + azz + bz);
        float n = tanhf(xr[2 * EE + e] + r * (ann + bn));
        float hp = hs[e * BB + b];
        float hn = (1.0f - z) * n + z * hp;
        if (clip_state) hn = fminf(fmaxf(hn, -CLIPV), CLIPV);
        hout[e * BB + b] = hn;
        out[((size_t)t * BB + b) * out_ld + colbase + e] =
            fminf(fmaxf(hn, -CLIPV), CLIPV);

        __threadfence();
        __syncthreads();
        if (tid == 0) {
            atomicAdd(ctr, 1);
            int target = SCAN_P * (s + 2);
            while (*(volatile int*)ctr < target) {}
        }
        __syncthreads();
    }
}

// ---- u = mu + exp(0.5 lv)*eps ; concat factors ----
__global__ void make_uf_kernel(const float* __restrict__ mu, const float* __restrict__ lv,
                               const float* __restrict__ eps, const float* __restrict__ factors,
                               float* __restrict__ uf)
{
    int idx = blockIdx.x * blockDim.x + threadIdx.x;
    if (idx >= MROWS * 68) return;
    int row = idx / 68;
    int c   = idx - row * 68;
    float v;
    if (c < UU) {
        int o = row * UU + c;
        v = mu[o] + expf(0.5f * lv[o]) * eps[o];
    } else {
        v = factors[row * FF + (c - UU)];
    }
    uf[idx] = v;
}

// ---- AR1 calcium, parallel over (b,n) ----
__global__ void calcium_kernel(const float* __restrict__ spk,
                               const float* __restrict__ gain,
                               const float* __restrict__ biasp,
                               const float* __restrict__ logtau,
                               float* __restrict__ out)
{
    int idx = blockIdx.x * blockDim.x + threadIdx.x;
    if (idx >= BB * NN) return;
    float decay = 1.0f - 1.0f / expf(logtau[0]);
    float gn = gain[0], bp = biasp[0];
    float c = 0.0f;
    for (int t = 0; t < TT; t++) {
        size_t off = (size_t)t * (BB * NN) + idx;
        c = c * decay + gn * spk[off] + bp;
        out[off] = c;
    }
}

extern "C" void kernel_launch(void* const* d_in, const int* in_sizes, int n_in,
                              void* d_out, int out_size)
{
    const float* x       = (const float*)d_in[0];
    const float* factors = (const float*)d_in[1];
    const float* eps     = (const float*)d_in[2];
    const float* eWihf   = (const float*)d_in[3];
    const float* eWhhf   = (const float*)d_in[4];
    const float* ebihf   = (const float*)d_in[5];
    const float* ebhhf   = (const float*)d_in[6];
    const float* eWihb   = (const float*)d_in[7];
    const float* eWhhb   = (const float*)d_in[8];
    const float* ebihb   = (const float*)d_in[9];
    const float* ebhhb   = (const float*)d_in[10];
    const float* einit   = (const float*)d_in[11];
    const float* cWih    = (const float*)d_in[12];
    const float* cWhh    = (const float*)d_in[13];
    const float* cbih    = (const float*)d_in[14];
    const float* cbhh    = (const float*)d_in[15];
    const float* cinit   = (const float*)d_in[16];
    const float* Wmu     = (const float*)d_in[17];
    const float* bmu     = (const float*)d_in[18];
    const float* Wlv     = (const float*)d_in[19];
    const float* blv     = (const float*)d_in[20];
    const float* Wspk    = (const float*)d_in[21];
    const float* bspk    = (const float*)d_in[22];
    const float* gain    = (const float*)d_in[23];
    const float* biasp   = (const float*)d_in[24];
    const float* logtau  = (const float*)d_in[25];
    float* out = (float*)d_out;

    float *p_xpf, *p_xpb, *p_cp, *p_g, *p_hc, *p_mu, *p_lv, *p_uf, *p_spk, *p_hs;
    int* p_ctr;
    cudaGetSymbolAddress((void**)&p_xpf, d_xpf);
    cudaGetSymbolAddress((void**)&p_xpb, d_xpb);
    cudaGetSymbolAddress((void**)&p_cp,  d_cp);
    cudaGetSymbolAddress((void**)&p_g,   d_g);
    cudaGetSymbolAddress((void**)&p_hc,  d_hc);
    cudaGetSymbolAddress((void**)&p_mu,  d_mu);
    cudaGetSymbolAddress((void**)&p_lv,  d_lv);
    cudaGetSymbolAddress((void**)&p_uf,  d_uf);
    cudaGetSymbolAddress((void**)&p_spk, d_spk);
    cudaGetSymbolAddress((void**)&p_hs,  d_hstate);
    cudaGetSymbolAddress((void**)&p_ctr, d_ctr);

    const int scan_smem = (EE * BB + 3 * 2 * EE) * (int)sizeof(float); // 68608 B
    cudaFuncSetAttribute(gru_scan_kernel, cudaFuncAttributeMaxDynamicSharedMemorySize, scan_smem);

    zero_ctr_kernel<<<1, 32>>>();

    const int MB = MROWS / 128; // 500

    // encoder input projections + controller x-part projection
    sgemm_kernel<<<dim3(3, MB), 256>>>(x, NN, eWihf, NN, ebihf, p_xpf, 384, 384, NN, 0);
    sgemm_kernel<<<dim3(3, MB), 256>>>(x, NN, eWihb, NN, ebihb, p_xpb, 384, 384, NN, 0);
    sgemm_kernel<<<dim3(3, MB), 256>>>(x, NN, cWih + 2 * EE, 2 * EE + NN, cbih, p_cp, 384, 384, NN, 0);

    // bidirectional encoder scan (fwd dir0 + bwd dir1 concurrently)
    gru_scan_kernel<<<2 * SCAN_P, 256, scan_smem>>>(
        p_xpf, p_xpb, eWhhf, eWhhb, ebhhf, ebhhb, einit, einit + EE,
        p_g, 256, 0, EE, /*clip_state=*/0, /*rev_b=*/1, p_ctr, p_hs);

    // controller projection, g part (accumulate into cp)
    sgemm_kernel<<<dim3(3, MB), 256>>>(p_g, 256, cWih, 2 * EE + NN, (const float*)0, p_cp, 384, 384, 256, 1);

    // controller scan (single direction, clipped state)
    gru_scan_kernel<<<SCAN_P, 256, scan_smem>>>(
        p_cp, p_cp, cWhh, cWhh, cbhh, cbhh, cinit, cinit,
        p_hc, 128, 0, 0, /*clip_state=*/1, /*rev_b=*/0, p_ctr + 2, p_hs);

    // latent heads
    sgemm_kernel<<<dim3(1, MB), 256>>>(p_hc, 128, Wmu, CC, bmu, p_mu, 64, UU, CC, 0);
    sgemm_kernel<<<dim3(1, MB), 256>>>(p_hc, 128, Wlv, CC, blv, p_lv, 64, UU, CC, 0);

    // sample + concat factors
    make_uf_kernel<<<(MROWS * 68 + 255) / 256, 256>>>(p_mu, p_lv, eps, factors, p_uf);

    // spike generator with fused exp-relu epilogue
    sgemm_kernel<<<dim3(3, MB), 256>>>(p_uf, 68, Wspk, UU + FF, bspk, p_spk, 300, NN, UU + FF, 2);

    // AR1 calcium
    calcium_kernel<<<(BB * NN + 255) / 256, 256>>>(p_spk, gain, biasp, logtau, out);
}

// round 5
// speedup vs baseline: 1.8001x; 1.8001x over previous
#include <cuda_runtime.h>
#include <math.h>

#define TT 500
#define BB 128
#define NN 300
#define EE 128
#define CC 128
#define UU 64
#define FF 4
#define CLIPV 5.0f
#define S2P 64              // blocks per scan direction (2 batch columns each)
#define MROWS (TT*BB)       // 64000

// ---- static device scratch ----
__device__ float d_xpf[MROWS * 384];
__device__ float d_xpb[MROWS * 384];
__device__ float d_cp [MROWS * 384];
__device__ float d_g  [MROWS * 256];
__device__ float d_hc [MROWS * 128];
__device__ float d_mu [MROWS * 64];
__device__ float d_lv [MROWS * 64];
__device__ float d_uf [MROWS * 68];
__device__ float d_spk[MROWS * 300];

__device__ __forceinline__ float sigm(float x) { return 1.0f / (1.0f + expf(-x)); }

// ---- SGEMM: C[M,N] = A[M,K] @ W[N,K]^T (+bias). flags bit0: accumulate, bit1: spike epilogue ----
__global__ __launch_bounds__(256) void sgemm_kernel(
    const float* __restrict__ A, int lda,
    const float* __restrict__ W, int ldw,
    const float* __restrict__ bias,
    float* __restrict__ C, int ldc,
    int N, int K, int flags)
{
    __shared__ float As[8][128];
    __shared__ float Ws[8][128];
    const int tid = threadIdx.x;
    const int m0 = blockIdx.y * 128;
    const int n0 = blockIdx.x * 128;
    const int lr = tid >> 1;
    const int lc = (tid & 1) << 2;
    const int tx = tid & 15;
    const int ty = tid >> 4;

    float acc[8][8];
#pragma unroll
    for (int i = 0; i < 8; i++)
#pragma unroll
        for (int j = 0; j < 8; j++) acc[i][j] = 0.0f;

    for (int k0 = 0; k0 < K; k0 += 8) {
        {
            float4 v = make_float4(0.f, 0.f, 0.f, 0.f);
            int kbase = k0 + lc;
            int rem = K - kbase;
            const float* Ap = A + (size_t)(m0 + lr) * lda + kbase;
            if (rem >= 4) v = *(const float4*)Ap;
            else if (rem > 0) {
                v.x = Ap[0];
                if (rem > 1) v.y = Ap[1];
                if (rem > 2) v.z = Ap[2];
            }
            As[lc + 0][lr] = v.x; As[lc + 1][lr] = v.y;
            As[lc + 2][lr] = v.z; As[lc + 3][lr] = v.w;
        }
        {
            float4 v = make_float4(0.f, 0.f, 0.f, 0.f);
            int n = n0 + lr;
            int kbase = k0 + lc;
            int rem = K - kbase;
            if (n < N && rem > 0) {
                const float* Wp = W + (size_t)n * ldw + kbase;
                if (rem >= 4) v = *(const float4*)Wp;
                else {
                    v.x = Wp[0];
                    if (rem > 1) v.y = Wp[1];
                    if (rem > 2) v.z = Wp[2];
                }
            }
            Ws[lc + 0][lr] = v.x; Ws[lc + 1][lr] = v.y;
            Ws[lc + 2][lr] = v.z; Ws[lc + 3][lr] = v.w;
        }
        __syncthreads();
#pragma unroll
        for (int k = 0; k < 8; k++) {
            float a[8], bb[8];
            *(float4*)&a[0]  = *(const float4*)&As[k][ty * 8];
            *(float4*)&a[4]  = *(const float4*)&As[k][ty * 8 + 4];
            *(float4*)&bb[0] = *(const float4*)&Ws[k][tx * 8];
            *(float4*)&bb[4] = *(const float4*)&Ws[k][tx * 8 + 4];
#pragma unroll
            for (int i = 0; i < 8; i++)
#pragma unroll
                for (int j = 0; j < 8; j++)
                    acc[i][j] = fmaf(a[i], bb[j], acc[i][j]);
        }
        __syncthreads();
    }

#pragma unroll
    for (int i = 0; i < 8; i++) {
        int m = m0 + ty * 8 + i;
#pragma unroll
        for (int j = 0; j < 8; j++) {
            int n = n0 + tx * 8 + j;
            if (n < N) {
                float v = acc[i][j];
                if (bias) v += bias[n];
                size_t off = (size_t)m * ldc + n;
                if (flags & 1) v += C[off];
                if (flags & 2) v = fmaxf(expf(v) - 1.0f, 0.0f);
                C[off] = v;
            }
        }
    }
}

// ---- batch-sliced GRU scan: NO grid sync. Each block owns 2 batch columns and the
// full Whh (196KB) in smem ([gate][k/4][e] float4 layout, conflict-free, weights read
// once per step). 128 threads = hidden unit e. h state lives in smem, broadcast reads. ----
__global__ __launch_bounds__(128) void gru_scan2_kernel(
    const float* __restrict__ xp_a, const float* __restrict__ xp_b,
    const float* __restrict__ W_a,  const float* __restrict__ W_b,
    const float* __restrict__ bh_a, const float* __restrict__ bh_b,
    const float* __restrict__ init_a, const float* __restrict__ init_b,
    float* __restrict__ out, int out_ld, int col_a, int col_b,
    int clip_state, int rev_b)
{
    extern __shared__ float sm[];
    float*  hcur = sm;                       // [2][128]
    float4* sW4  = (float4*)(sm + 256);      // [3][32][128] float4 over k

    const int dir = blockIdx.x / S2P;
    const int jb  = blockIdx.x % S2P;
    const float* xp   = dir ? xp_b   : xp_a;
    const float* Whh  = dir ? W_b    : W_a;
    const float* bhh  = dir ? bh_b   : bh_a;
    const float* hini = dir ? init_b : init_a;
    const int colbase = dir ? col_b  : col_a;
    const int rev     = dir ? rev_b  : 0;
    const int b0 = jb * 2;

    const int e = threadIdx.x;

    // stage weights transposed into [g][kk][e] float4 layout
    for (int idx = e; idx < 3 * 32 * 128; idx += 128) {
        int g  = idx >> 12;
        int r  = idx & 4095;
        int kk = r >> 7;
        int ee = r & 127;
        sW4[idx] = *(const float4*)(Whh + (size_t)(g * 128 + ee) * 128 + kk * 4);
    }
    const float br = bhh[e], bz = bhh[128 + e], bn = bhh[256 + e];
    hcur[e]       = hini[e];
    hcur[128 + e] = hini[e];
    __syncthreads();

    const float4* hc40 = (const float4*)(hcur);
    const float4* hc41 = (const float4*)(hcur + 128);

    for (int s = 0; s < TT; s++) {
        const int t = rev ? (TT - 1 - s) : s;
        const float* x0 = xp + ((size_t)t * BB + b0) * 384;
        const float* x1 = x0 + 384;
        // issue input-projection loads early; consumed only in epilogue
        float p0r = __ldg(x0 + e), p0z = __ldg(x0 + 128 + e), p0n = __ldg(x0 + 256 + e);
        float p1r = __ldg(x1 + e), p1z = __ldg(x1 + 128 + e), p1n = __ldg(x1 + 256 + e);

        float a0r = 0.f, a0z = 0.f, a0n = 0.f;
        float a1r = 0.f, a1z = 0.f, a1n = 0.f;
#pragma unroll
        for (int kk = 0; kk < 32; kk++) {
            float4 wr = sW4[(0 * 32 + kk) * 128 + e];
            float4 wz = sW4[(1 * 32 + kk) * 128 + e];
            float4 wn = sW4[(2 * 32 + kk) * 128 + e];
            float4 h0 = hc40[kk];
            float4 h1 = hc41[kk];
            a0r = fmaf(wr.x, h0.x, a0r); a0r = fmaf(wr.y, h0.y, a0r);
            a0r = fmaf(wr.z, h0.z, a0r); a0r = fmaf(wr.w, h0.w, a0r);
            a0z = fmaf(wz.x, h0.x, a0z); a0z = fmaf(wz.y, h0.y, a0z);
            a0z = fmaf(wz.z, h0.z, a0z); a0z = fmaf(wz.w, h0.w, a0z);
            a0n = fmaf(wn.x, h0.x, a0n); a0n = fmaf(wn.y, h0.y, a0n);
            a0n = fmaf(wn.z, h0.z, a0n); a0n = fmaf(wn.w, h0.w, a0n);
            a1r = fmaf(wr.x, h1.x, a1r); a1r = fmaf(wr.y, h1.y, a1r);
            a1r = fmaf(wr.z, h1.z, a1r); a1r = fmaf(wr.w, h1.w, a1r);
            a1z = fmaf(wz.x, h1.x, a1z); a1z = fmaf(wz.y, h1.y, a1z);
            a1z = fmaf(wz.z, h1.z, a1z); a1z = fmaf(wz.w, h1.w, a1z);
            a1n = fmaf(wn.x, h1.x, a1n); a1n = fmaf(wn.y, h1.y, a1n);
            a1n = fmaf(wn.z, h1.z, a1n); a1n = fmaf(wn.w, h1.w, a1n);
        }

        float hp0 = hcur[e], hp1 = hcur[128 + e];

        float r0 = sigm(p0r + a0r + br);
        float z0 = sigm(p0z + a0z + bz);
        float n0 = tanhf(p0n + r0 * (a0n + bn));
        float h0n = (1.0f - z0) * n0 + z0 * hp0;

        float r1 = sigm(p1r + a1r + br);
        float z1 = sigm(p1z + a1z + bz);
        float n1 = tanhf(p1n + r1 * (a1n + bn));
        float h1n = (1.0f - z1) * n1 + z1 * hp1;

        float c0 = fminf(fmaxf(h0n, -CLIPV), CLIPV);
        float c1 = fminf(fmaxf(h1n, -CLIPV), CLIPV);
        if (clip_state) { h0n = c0; h1n = c1; }

        __syncthreads();
        hcur[e]       = h0n;
        hcur[128 + e] = h1n;
        out[((size_t)t * BB + b0)     * out_ld + colbase + e] = c0;
        out[((size_t)t * BB + b0 + 1) * out_ld + colbase + e] = c1;
        __syncthreads();
    }
}

// ---- u = mu + exp(0.5 lv)*eps ; concat factors ----
__global__ void make_uf_kernel(const float* __restrict__ mu, const float* __restrict__ lv,
                               const float* __restrict__ eps, const float* __restrict__ factors,
                               float* __restrict__ uf)
{
    int idx = blockIdx.x * blockDim.x + threadIdx.x;
    if (idx >= MROWS * 68) return;
    int row = idx / 68;
    int c   = idx - row * 68;
    float v;
    if (c < UU) {
        int o = row * UU + c;
        v = mu[o] + expf(0.5f * lv[o]) * eps[o];
    } else {
        v = factors[row * FF + (c - UU)];
    }
    uf[idx] = v;
}

// ---- AR1 calcium, parallel over (b,n) ----
__global__ void calcium_kernel(const float* __restrict__ spk,
                               const float* __restrict__ gain,
                               const float* __restrict__ biasp,
                               const float* __restrict__ logtau,
                               float* __restrict__ out)
{
    int idx = blockIdx.x * blockDim.x + threadIdx.x;
    if (idx >= BB * NN) return;
    float decay = 1.0f - 1.0f / expf(logtau[0]);
    float gn = gain[0], bp = biasp[0];
    float c = 0.0f;
    for (int t = 0; t < TT; t++) {
        size_t off = (size_t)t * (BB * NN) + idx;
        c = c * decay + gn * spk[off] + bp;
        out[off] = c;
    }
}

extern "C" void kernel_launch(void* const* d_in, const int* in_sizes, int n_in,
                              void* d_out, int out_size)
{
    const float* x       = (const float*)d_in[0];
    const float* factors = (const float*)d_in[1];
    const float* eps     = (const float*)d_in[2];
    const float* eWihf   = (const float*)d_in[3];
    const float* eWhhf   = (const float*)d_in[4];
    const float* ebihf   = (const float*)d_in[5];
    const float* ebhhf   = (const float*)d_in[6];
    const float* eWihb   = (const float*)d_in[7];
    const float* eWhhb   = (const float*)d_in[8];
    const float* ebihb   = (const float*)d_in[9];
    const float* ebhhb   = (const float*)d_in[10];
    const float* einit   = (const float*)d_in[11];
    const float* cWih    = (const float*)d_in[12];
    const float* cWhh    = (const float*)d_in[13];
    const float* cbih    = (const float*)d_in[14];
    const float* cbhh    = (const float*)d_in[15];
    const float* cinit   = (const float*)d_in[16];
    const float* Wmu     = (const float*)d_in[17];
    const float* bmu     = (const float*)d_in[18];
    const float* Wlv     = (const float*)d_in[19];
    const float* blv     = (const float*)d_in[20];
    const float* Wspk    = (const float*)d_in[21];
    const float* bspk    = (const float*)d_in[22];
    const float* gain    = (const float*)d_in[23];
    const float* biasp   = (const float*)d_in[24];
    const float* logtau  = (const float*)d_in[25];
    float* out = (float*)d_out;

    float *p_xpf, *p_xpb, *p_cp, *p_g, *p_hc, *p_mu, *p_lv, *p_uf, *p_spk;
    cudaGetSymbolAddress((void**)&p_xpf, d_xpf);
    cudaGetSymbolAddress((void**)&p_xpb, d_xpb);
    cudaGetSymbolAddress((void**)&p_cp,  d_cp);
    cudaGetSymbolAddress((void**)&p_g,   d_g);
    cudaGetSymbolAddress((void**)&p_hc,  d_hc);
    cudaGetSymbolAddress((void**)&p_mu,  d_mu);
    cudaGetSymbolAddress((void**)&p_lv,  d_lv);
    cudaGetSymbolAddress((void**)&p_uf,  d_uf);
    cudaGetSymbolAddress((void**)&p_spk, d_spk);

    // smem: 256 floats h-state + 3*32*128 float4 weights = 1024 + 196608 B
    const int scan_smem = 1024 + 3 * 32 * 128 * 16;
    cudaFuncSetAttribute(gru_scan2_kernel, cudaFuncAttributeMaxDynamicSharedMemorySize, scan_smem);

    const int MB = MROWS / 128; // 500

    // encoder input projections + controller x-part projection
    sgemm_kernel<<<dim3(3, MB), 256>>>(x, NN, eWihf, NN, ebihf, p_xpf, 384, 384, NN, 0);
    sgemm_kernel<<<dim3(3, MB), 256>>>(x, NN, eWihb, NN, ebihb, p_xpb, 384, 384, NN, 0);
    sgemm_kernel<<<dim3(3, MB), 256>>>(x, NN, cWih + 2 * EE, 2 * EE + NN, cbih, p_cp, 384, 384, NN, 0);

    // bidirectional encoder scan: 128 fully independent blocks (64 fwd + 64 bwd)
    gru_scan2_kernel<<<2 * S2P, 128, scan_smem>>>(
        p_xpf, p_xpb, eWhhf, eWhhb, ebhhf, ebhhb, einit, einit + EE,
        p_g, 256, 0, EE, /*clip_state=*/0, /*rev_b=*/1);

    // controller projection, g part (accumulate into cp)
    sgemm_kernel<<<dim3(3, MB), 256>>>(p_g, 256, cWih, 2 * EE + NN, (const float*)0, p_cp, 384, 384, 256, 1);

    // controller scan (single direction, clipped state)
    gru_scan2_kernel<<<S2P, 128, scan_smem>>>(
        p_cp, p_cp, cWhh, cWhh, cbhh, cbhh, cinit, cinit,
        p_hc, 128, 0, 0, /*clip_state=*/1, /*rev_b=*/0);

    // latent heads
    sgemm_kernel<<<dim3(1, MB), 256>>>(p_hc, 128, Wmu, CC, bmu, p_mu, 64, UU, CC, 0);
    sgemm_kernel<<<dim3(1, MB), 256>>>(p_hc, 128, Wlv, CC, blv, p_lv, 64, UU, CC, 0);

    // sample + concat factors
    make_uf_kernel<<<(MROWS * 68 + 255) / 256, 256>>>(p_mu, p_lv, eps, factors, p_uf);

    // spike generator with fused exp-relu epilogue
    sgemm_kernel<<<dim3(3, MB), 256>>>(p_uf, 68, Wspk, UU + FF, bspk, p_spk, 300, NN, UU + FF, 2);

    // AR1 calcium
    calcium_kernel<<<(BB * NN + 255) / 256, 256>>>(p_spk, gain, biasp, logtau, out);
}

// round 7
// speedup vs baseline: 2.0077x; 1.1153x over previous
#include <cuda_runtime.h>
#include <math.h>

#define TT 500
#define BB 128
#define NN 300
#define EE 128
#define CC 128
#define UU 64
#define FF 4
#define CLIPV 5.0f
#define S2P 64              // blocks per scan direction (2 batch columns each)
#define MROWS (TT*BB)       // 64000

// ---- static device scratch ----
__device__ float d_xpf[MROWS * 384];
__device__ float d_xpb[MROWS * 384];
__device__ float d_cp [MROWS * 384];
__device__ float d_g  [MROWS * 256];
__device__ float d_hc [MROWS * 128];
__device__ float d_mu [MROWS * 64];
__device__ float d_lv [MROWS * 64];
__device__ float d_uf [MROWS * 68];
__device__ float d_spk[MROWS * 300];

__device__ __forceinline__ float sigm(float x) { return 1.0f / (1.0f + expf(-x)); }

// ---- SGEMM: C[M,N] = A[M,K] @ W[N,K]^T (+bias). flags bit0: accumulate, bit1: spike epilogue ----
__global__ __launch_bounds__(256) void sgemm_kernel(
    const float* __restrict__ A, int lda,
    const float* __restrict__ W, int ldw,
    const float* __restrict__ bias,
    float* __restrict__ C, int ldc,
    int N, int K, int flags)
{
    __shared__ float As[8][128];
    __shared__ float Ws[8][128];
    const int tid = threadIdx.x;
    const int m0 = blockIdx.y * 128;
    const int n0 = blockIdx.x * 128;
    const int lr = tid >> 1;
    const int lc = (tid & 1) << 2;
    const int tx = tid & 15;
    const int ty = tid >> 4;

    float acc[8][8];
#pragma unroll
    for (int i = 0; i < 8; i++)
#pragma unroll
        for (int j = 0; j < 8; j++) acc[i][j] = 0.0f;

    for (int k0 = 0; k0 < K; k0 += 8) {
        {
            float4 v = make_float4(0.f, 0.f, 0.f, 0.f);
            int kbase = k0 + lc;
            int rem = K - kbase;
            const float* Ap = A + (size_t)(m0 + lr) * lda + kbase;
            if (rem >= 4) v = *(const float4*)Ap;
            else if (rem > 0) {
                v.x = Ap[0];
                if (rem > 1) v.y = Ap[1];
                if (rem > 2) v.z = Ap[2];
            }
            As[lc + 0][lr] = v.x; As[lc + 1][lr] = v.y;
            As[lc + 2][lr] = v.z; As[lc + 3][lr] = v.w;
        }
        {
            float4 v = make_float4(0.f, 0.f, 0.f, 0.f);
            int n = n0 + lr;
            int kbase = k0 + lc;
            int rem = K - kbase;
            if (n < N && rem > 0) {
                const float* Wp = W + (size_t)n * ldw + kbase;
                if (rem >= 4) v = *(const float4*)Wp;
                else {
                    v.x = Wp[0];
                    if (rem > 1) v.y = Wp[1];
                    if (rem > 2) v.z = Wp[2];
                }
            }
            Ws[lc + 0][lr] = v.x; Ws[lc + 1][lr] = v.y;
            Ws[lc + 2][lr] = v.z; Ws[lc + 3][lr] = v.w;
        }
        __syncthreads();
#pragma unroll
        for (int k = 0; k < 8; k++) {
            float a[8], bb[8];
            *(float4*)&a[0]  = *(const float4*)&As[k][ty * 8];
            *(float4*)&a[4]  = *(const float4*)&As[k][ty * 8 + 4];
            *(float4*)&bb[0] = *(const float4*)&Ws[k][tx * 8];
            *(float4*)&bb[4] = *(const float4*)&Ws[k][tx * 8 + 4];
#pragma unroll
            for (int i = 0; i < 8; i++)
#pragma unroll
                for (int j = 0; j < 8; j++)
                    acc[i][j] = fmaf(a[i], bb[j], acc[i][j]);
        }
        __syncthreads();
    }

#pragma unroll
    for (int i = 0; i < 8; i++) {
        int m = m0 + ty * 8 + i;
#pragma unroll
        for (int j = 0; j < 8; j++) {
            int n = n0 + tx * 8 + j;
            if (n < N) {
                float v = acc[i][j];
                if (bias) v += bias[n];
                size_t off = (size_t)m * ldc + n;
                if (flags & 1) v += C[off];
                if (flags & 2) v = fmaxf(expf(v) - 1.0f, 0.0f);
                C[off] = v;
            }
        }
    }
}

// ---- batch-sliced, k-split GRU scan. Each block: 2 batch columns, full Whh in smem.
// 256 threads = (e, khalf). khalf 0 computes k in [0,64), khalf 1 k in [64,128);
// partials exchanged through smem; khalf b finalizes batch b. 2 warps/SMSP for
// LDS-latency hiding; weights read once per step (crossbar floor 1536cyc). ----
__global__ __launch_bounds__(256) void gru_scan3_kernel(
    const float* __restrict__ xp_a, const float* __restrict__ xp_b,
    const float* __restrict__ W_a,  const float* __restrict__ W_b,
    const float* __restrict__ bh_a, const float* __restrict__ bh_b,
    const float* __restrict__ init_a, const float* __restrict__ init_b,
    float* __restrict__ out, int out_ld, int col_a, int col_b,
    int clip_state, int rev_b)
{
    extern __shared__ float sm[];
    float*  hcur = sm;                       // [2 batch][128]
    float*  red  = sm + 256;                 // [3 gate][2 batch][128]
    float4* sW4  = (float4*)(sm + 1024);     // [3 gate][2 khalf][16 kk][128 e]

    const int dir = blockIdx.x / S2P;
    const int jb  = blockIdx.x % S2P;
    const float* xp   = dir ? xp_b   : xp_a;
    const float* Whh  = dir ? W_b    : W_a;
    const float* bhh  = dir ? bh_b   : bh_a;
    const float* hini = dir ? init_b : init_a;
    const int colbase = dir ? col_b  : col_a;
    const int rev     = dir ? rev_b  : 0;
    const int b0 = jb * 2;

    const int tid = threadIdx.x;
    const int e  = tid & 127;
    const int kh = tid >> 7;           // 0 or 1

    // stage weights: sW4[((g*2 + kh)*16 + kk)*128 + e] = W[g*128+e][ (kh*16+kk)*4 .. +3 ]
    for (int idx = tid; idx < 3 * 2 * 16 * 128; idx += 256) {
        int ee  = idx & 127;
        int kk  = (idx >> 7) & 15;
        int khh = (idx >> 11) & 1;
        int g   = idx >> 12;
        sW4[idx] = *(const float4*)(Whh + (size_t)(g * 128 + ee) * 128 + (khh * 16 + kk) * 4);
    }
    const float br = bhh[e], bz = bhh[128 + e], bn = bhh[256 + e];
    hcur[kh * 128 + e] = hini[e];
    __syncthreads();

    const float4* wrp = sW4 + (size_t)(0 * 2 + kh) * 16 * 128 + e;
    const float4* wzp = sW4 + (size_t)(1 * 2 + kh) * 16 * 128 + e;
    const float4* wnp = sW4 + (size_t)(2 * 2 + kh) * 16 * 128 + e;
    const float4* h0p = (const float4*)hcur + kh * 16;        // batch0, this k-half
    const float4* h1p = (const float4*)hcur + 32 + kh * 16;   // batch1, this k-half

    for (int s = 0; s < TT; s++) {
        const int t = rev ? (TT - 1 - s) : s;
        // each thread finalizes batch kh -> prefetch its xp row early
        const float* xr = xp + ((size_t)t * BB + b0 + kh) * 384;
        float pr = __ldg(xr + e), pz = __ldg(xr + 128 + e), pn = __ldg(xr + 256 + e);

        float a0r = 0.f, a0z = 0.f, a0n = 0.f;
        float a1r = 0.f, a1z = 0.f, a1n = 0.f;
#pragma unroll
        for (int kk = 0; kk < 16; kk++) {
            float4 wr = wrp[kk * 128];
            float4 wz = wzp[kk * 128];
            float4 wn = wnp[kk * 128];
            float4 h0 = h0p[kk];
            float4 h1 = h1p[kk];
            a0r = fmaf(wr.x, h0.x, a0r); a0r = fmaf(wr.y, h0.y, a0r);
            a0r = fmaf(wr.z, h0.z, a0r); a0r = fmaf(wr.w, h0.w, a0r);
            a0z = fmaf(wz.x, h0.x, a0z); a0z = fmaf(wz.y, h0.y, a0z);
            a0z = fmaf(wz.z, h0.z, a0z); a0z = fmaf(wz.w, h0.w, a0z);
            a0n = fmaf(wn.x, h0.x, a0n); a0n = fmaf(wn.y, h0.y, a0n);
            a0n = fmaf(wn.z, h0.z, a0n); a0n = fmaf(wn.w, h0.w, a0n);
            a1r = fmaf(wr.x, h1.x, a1r); a1r = fmaf(wr.y, h1.y, a1r);
            a1r = fmaf(wr.z, h1.z, a1r); a1r = fmaf(wr.w, h1.w, a1r);
            a1z = fmaf(wz.x, h1.x, a1z); a1z = fmaf(wz.y, h1.y, a1z);
            a1z = fmaf(wz.z, h1.z, a1z); a1z = fmaf(wz.w, h1.w, a1z);
            a1n = fmaf(wn.x, h1.x, a1n); a1n = fmaf(wn.y, h1.y, a1n);
            a1n = fmaf(wn.z, h1.z, a1n); a1n = fmaf(wn.w, h1.w, a1n);
        }

        // exchange: store partials for the batch this thread does NOT finalize.
        // kh finalizes batch kh; stores batch (1-kh) partials to red[g][1-kh][e].
        int ob = 1 - kh;
        float sr = kh ? a0r : a1r;
        float sz = kh ? a0z : a1z;
        float sn = kh ? a0n : a1n;
        red[(0 * 2 + ob) * 128 + e] = sr;
        red[(1 * 2 + ob) * 128 + e] = sz;
        red[(2 * 2 + ob) * 128 + e] = sn;
        __syncthreads();

        float fr = (kh ? a1r : a0r) + red[(0 * 2 + kh) * 128 + e];
        float fz = (kh ? a1z : a0z) + red[(1 * 2 + kh) * 128 + e];
        float fn = (kh ? a1n : a0n) + red[(2 * 2 + kh) * 128 + e];

        float hp = hcur[kh * 128 + e];
        float r = sigm(pr + fr + br);
        float z = sigm(pz + fz + bz);
        float n = tanhf(pn + r * (fn + bn));
        float hn = (1.0f - z) * n + z * hp;
        float c  = fminf(fmaxf(hn, -CLIPV), CLIPV);
        if (clip_state) hn = c;

        hcur[kh * 128 + e] = hn;
        out[((size_t)t * BB + b0 + kh) * out_ld + colbase + e] = c;
        __syncthreads();
    }
}

// ---- u = mu + exp(0.5 lv)*eps ; concat factors ----
__global__ void make_uf_kernel(const float* __restrict__ mu, const float* __restrict__ lv,
                               const float* __restrict__ eps, const float* __restrict__ factors,
                               float* __restrict__ uf)
{
    int idx = blockIdx.x * blockDim.x + threadIdx.x;
    if (idx >= MROWS * 68) return;
    int row = idx / 68;
    int c   = idx - row * 68;
    float v;
    if (c < UU) {
        int o = row * UU + c;
        v = mu[o] + expf(0.5f * lv[o]) * eps[o];
    } else {
        v = factors[row * FF + (c - UU)];
    }
    uf[idx] = v;
}

// ---- AR1 calcium, parallel over (b,n) ----
__global__ void calcium_kernel(const float* __restrict__ spk,
                               const float* __restrict__ gain,
                               const float* __restrict__ biasp,
                               const float* __restrict__ logtau,
                               float* __restrict__ out)
{
    int idx = blockIdx.x * blockDim.x + threadIdx.x;
    if (idx >= BB * NN) return;
    float decay = 1.0f - 1.0f / expf(logtau[0]);
    float gn = gain[0], bp = biasp[0];
    float c = 0.0f;
    for (int t = 0; t < TT; t++) {
        size_t off = (size_t)t * (BB * NN) + idx;
        c = c * decay + gn * spk[off] + bp;
        out[off] = c;
    }
}

extern "C" void kernel_launch(void* const* d_in, const int* in_sizes, int n_in,
                              void* d_out, int out_size)
{
    const float* x       = (const float*)d_in[0];
    const float* factors = (const float*)d_in[1];
    const float* eps     = (const float*)d_in[2];
    const float* eWihf   = (const float*)d_in[3];
    const float* eWhhf   = (const float*)d_in[4];
    const float* ebihf   = (const float*)d_in[5];
    const float* ebhhf   = (const float*)d_in[6];
    const float* eWihb   = (const float*)d_in[7];
    const float* eWhhb   = (const float*)d_in[8];
    const float* ebihb   = (const float*)d_in[9];
    const float* ebhhb   = (const float*)d_in[10];
    const float* einit   = (const float*)d_in[11];
    const float* cWih    = (const float*)d_in[12];
    const float* cWhh    = (const float*)d_in[13];
    const float* cbih    = (const float*)d_in[14];
    const float* cbhh    = (const float*)d_in[15];
    const float* cinit   = (const float*)d_in[16];
    const float* Wmu     = (const float*)d_in[17];
    const float* bmu     = (const float*)d_in[18];
    const float* Wlv     = (const float*)d_in[19];
    const float* blv     = (const float*)d_in[20];
    const float* Wspk    = (const float*)d_in[21];
    const float* bspk    = (const float*)d_in[22];
    const float* gain    = (const float*)d_in[23];
    const float* biasp   = (const float*)d_in[24];
    const float* logtau  = (const float*)d_in[25];
    float* out = (float*)d_out;

    float *p_xpf, *p_xpb, *p_cp, *p_g, *p_hc, *p_mu, *p_lv, *p_uf, *p_spk;
    cudaGetSymbolAddress((void**)&p_xpf, d_xpf);
    cudaGetSymbolAddress((void**)&p_xpb, d_xpb);
    cudaGetSymbolAddress((void**)&p_cp,  d_cp);
    cudaGetSymbolAddress((void**)&p_g,   d_g);
    cudaGetSymbolAddress((void**)&p_hc,  d_hc);
    cudaGetSymbolAddress((void**)&p_mu,  d_mu);
    cudaGetSymbolAddress((void**)&p_lv,  d_lv);
    cudaGetSymbolAddress((void**)&p_uf,  d_uf);
    cudaGetSymbolAddress((void**)&p_spk, d_spk);

    // smem: hcur(256f) + red(768f) + weights 3*2*16*128 float4
    const int scan_smem = 4096 + 3 * 2 * 16 * 128 * 16;   // 200704 B
    cudaFuncSetAttribute(gru_scan3_kernel, cudaFuncAttributeMaxDynamicSharedMemorySize, scan_smem);

    const int MB = MROWS / 128; // 500

    // encoder input projections + controller x-part projection
    sgemm_kernel<<<dim3(3, MB), 256>>>(x, NN, eWihf, NN, ebihf, p_xpf, 384, 384, NN, 0);
    sgemm_kernel<<<dim3(3, MB), 256>>>(x, NN, eWihb, NN, ebihb, p_xpb, 384, 384, NN, 0);
    sgemm_kernel<<<dim3(3, MB), 256>>>(x, NN, cWih + 2 * EE, 2 * EE + NN, cbih, p_cp, 384, 384, NN, 0);

    // bidirectional encoder scan: 128 independent blocks (64 fwd + 64 bwd)
    gru_scan3_kernel<<<2 * S2P, 256, scan_smem>>>(
        p_xpf, p_xpb, eWhhf, eWhhb, ebhhf, ebhhb, einit, einit + EE,
        p_g, 256, 0, EE, /*clip_state=*/0, /*rev_b=*/1);

    // controller projection, g part (accumulate into cp)
    sgemm_kernel<<<dim3(3, MB), 256>>>(p_g, 256, cWih, 2 * EE + NN, (const float*)0, p_cp, 384, 384, 256, 1);

    // controller scan (single direction, clipped state)
    gru_scan3_kernel<<<S2P, 256, scan_smem>>>(
        p_cp, p_cp, cWhh, cWhh, cbhh, cbhh, cinit, cinit,
        p_hc, 128, 0, 0, /*clip_state=*/1, /*rev_b=*/0);

    // latent heads
    sgemm_kernel<<<dim3(1, MB), 256>>>(p_hc, 128, Wmu, CC, bmu, p_mu, 64, UU, CC, 0);
    sgemm_kernel<<<dim3(1, MB), 256>>>(p_hc, 128, Wlv, CC, blv, p_lv, 64, UU, CC, 0);

    // sample + concat factors
    make_uf_kernel<<<(MROWS * 68 + 255) / 256, 256>>>(p_mu, p_lv, eps, factors, p_uf);

    // spike generator with fused exp-relu epilogue
    sgemm_kernel<<<dim3(3, MB), 256>>>(p_uf, 68, Wspk, UU + FF, bspk, p_spk, 300, NN, UU + FF, 2);

    // AR1 calcium
    calcium_kernel<<<(BB * NN + 255) / 256, 256>>>(p_spk, gain, biasp, logtau, out);
}

// round 8
// speedup vs baseline: 2.6245x; 1.3072x over previous
#include <cuda_runtime.h>
#include <math.h>

#define TT 500
#define BB 128
#define NN 300
#define EE 128
#define CC 128
#define UU 64
#define FF 4
#define CLIPV 5.0f
#define S2P 64              // blocks per scan direction (2 batch columns each)
#define MROWS (TT*BB)       // 64000

// ---- static device scratch ----
__device__ float d_xpf[MROWS * 384];
__device__ float d_xpb[MROWS * 384];
__device__ float d_cp [MROWS * 384];
__device__ float d_g  [MROWS * 256];
__device__ float d_hc [MROWS * 128];
__device__ float d_mu [MROWS * 64];
__device__ float d_lv [MROWS * 64];
__device__ float d_uf [MROWS * 68];
__device__ float d_spk[MROWS * 300];

__device__ __forceinline__ float sigm(float x) { return 1.0f / (1.0f + expf(-x)); }

// ---- SGEMM: C[M,N] = A[M,K] @ W[N,K]^T (+bias). flags bit0: accumulate, bit1: spike epilogue ----
__global__ __launch_bounds__(256) void sgemm_kernel(
    const float* __restrict__ A, int lda,
    const float* __restrict__ W, int ldw,
    const float* __restrict__ bias,
    float* __restrict__ C, int ldc,
    int N, int K, int flags)
{
    __shared__ float As[8][128];
    __shared__ float Ws[8][128];
    const int tid = threadIdx.x;
    const int m0 = blockIdx.y * 128;
    const int n0 = blockIdx.x * 128;
    const int lr = tid >> 1;
    const int lc = (tid & 1) << 2;
    const int tx = tid & 15;
    const int ty = tid >> 4;

    float acc[8][8];
#pragma unroll
    for (int i = 0; i < 8; i++)
#pragma unroll
        for (int j = 0; j < 8; j++) acc[i][j] = 0.0f;

    for (int k0 = 0; k0 < K; k0 += 8) {
        {
            float4 v = make_float4(0.f, 0.f, 0.f, 0.f);
            int kbase = k0 + lc;
            int rem = K - kbase;
            const float* Ap = A + (size_t)(m0 + lr) * lda + kbase;
            if (rem >= 4) v = *(const float4*)Ap;
            else if (rem > 0) {
                v.x = Ap[0];
                if (rem > 1) v.y = Ap[1];
                if (rem > 2) v.z = Ap[2];
            }
            As[lc + 0][lr] = v.x; As[lc + 1][lr] = v.y;
            As[lc + 2][lr] = v.z; As[lc + 3][lr] = v.w;
        }
        {
            float4 v = make_float4(0.f, 0.f, 0.f, 0.f);
            int n = n0 + lr;
            int kbase = k0 + lc;
            int rem = K - kbase;
            if (n < N && rem > 0) {
                const float* Wp = W + (size_t)n * ldw + kbase;
                if (rem >= 4) v = *(const float4*)Wp;
                else {
                    v.x = Wp[0];
                    if (rem > 1) v.y = Wp[1];
                    if (rem > 2) v.z = Wp[2];
                }
            }
            Ws[lc + 0][lr] = v.x; Ws[lc + 1][lr] = v.y;
            Ws[lc + 2][lr] = v.z; Ws[lc + 3][lr] = v.w;
        }
        __syncthreads();
#pragma unroll
        for (int k = 0; k < 8; k++) {
            float a[8], bb[8];
            *(float4*)&a[0]  = *(const float4*)&As[k][ty * 8];
            *(float4*)&a[4]  = *(const float4*)&As[k][ty * 8 + 4];
            *(float4*)&bb[0] = *(const float4*)&Ws[k][tx * 8];
            *(float4*)&bb[4] = *(const float4*)&Ws[k][tx * 8 + 4];
#pragma unroll
            for (int i = 0; i < 8; i++)
#pragma unroll
                for (int j = 0; j < 8; j++)
                    acc[i][j] = fmaf(a[i], bb[j], acc[i][j]);
        }
        __syncthreads();
    }

#pragma unroll
    for (int i = 0; i < 8; i++) {
        int m = m0 + ty * 8 + i;
#pragma unroll
        for (int j = 0; j < 8; j++) {
            int n = n0 + tx * 8 + j;
            if (n < N) {
                float v = acc[i][j];
                if (bias) v += bias[n];
                size_t off = (size_t)m * ldc + n;
                if (flags & 1) v += C[off];
                if (flags & 2) v = fmaxf(expf(v) - 1.0f, 0.0f);
                C[off] = v;
            }
        }
    }
}

// ---- register-weight GRU scan. 512 threads = (e in [0,128), kq in [0,4)).
// Each thread holds its 3x32 slice of Whh in registers (zero crossbar traffic in
// the loop). h state packed as (b0,b1) float2 pairs in smem -> broadcast LDS.64.
// 4-way k-reduction through smem; threads kq<2 finalize batch kq. ----
__global__ __launch_bounds__(512) void gru_scan4_kernel(
    const float* __restrict__ xp_a, const float* __restrict__ xp_b,
    const float* __restrict__ W_a,  const float* __restrict__ W_b,
    const float* __restrict__ bh_a, const float* __restrict__ bh_b,
    const float* __restrict__ init_a, const float* __restrict__ init_b,
    float* __restrict__ out, int out_ld, int col_a, int col_b,
    int clip_state, int rev_b)
{
    __shared__ float hc2[2 * 128];            // interleaved (b0,b1) per hidden k
    __shared__ float red[3 * 2 * 4 * 128];    // [gate][batch][kq][e]

    const int dir = blockIdx.x / S2P;
    const int jb  = blockIdx.x % S2P;
    const float* xp   = dir ? xp_b   : xp_a;
    const float* Whh  = dir ? W_b    : W_a;
    const float* bhh  = dir ? bh_b   : bh_a;
    const float* hini = dir ? init_b : init_a;
    const int colbase = dir ? col_b  : col_a;
    const int rev     = dir ? rev_b  : 0;
    const int b0 = jb * 2;

    const int tid = threadIdx.x;
    const int e  = tid & 127;
    const int kq = tid >> 7;            // 0..3 (uniform per warp)

    // weight slice into registers: w*[j] = Whh[g*128+e][kq*32+j]
    float wr[32], wz[32], wn[32];
    {
        const float* r0 = Whh + (size_t)(0 * 128 + e) * 128 + kq * 32;
        const float* r1 = Whh + (size_t)(1 * 128 + e) * 128 + kq * 32;
        const float* r2 = Whh + (size_t)(2 * 128 + e) * 128 + kq * 32;
#pragma unroll
        for (int j4 = 0; j4 < 8; j4++) {
            float4 a = *(const float4*)(r0 + j4 * 4);
            float4 b = *(const float4*)(r1 + j4 * 4);
            float4 c = *(const float4*)(r2 + j4 * 4);
            wr[j4*4+0]=a.x; wr[j4*4+1]=a.y; wr[j4*4+2]=a.z; wr[j4*4+3]=a.w;
            wz[j4*4+0]=b.x; wz[j4*4+1]=b.y; wz[j4*4+2]=b.z; wz[j4*4+3]=b.w;
            wn[j4*4+0]=c.x; wn[j4*4+1]=c.y; wn[j4*4+2]=c.z; wn[j4*4+3]=c.w;
        }
    }
    const float br = bhh[e], bz = bhh[128 + e], bn = bhh[256 + e];

    if (kq < 2) hc2[2 * e + kq] = hini[e];
    __syncthreads();

    const float2* h2 = (const float2*)hc2 + kq * 32;

    for (int s = 0; s < TT; s++) {
        const int t = rev ? (TT - 1 - s) : s;
        float pr = 0.f, pz = 0.f, pn = 0.f;
        if (kq < 2) {
            const float* xr = xp + ((size_t)t * BB + b0 + kq) * 384;
            pr = __ldg(xr + e); pz = __ldg(xr + 128 + e); pn = __ldg(xr + 256 + e);
        }

        float ar0 = 0.f, ar1 = 0.f, az0 = 0.f, az1 = 0.f, an0 = 0.f, an1 = 0.f;
#pragma unroll
        for (int j = 0; j < 32; j++) {
            float2 h = h2[j];
            ar0 = fmaf(wr[j], h.x, ar0); ar1 = fmaf(wr[j], h.y, ar1);
            az0 = fmaf(wz[j], h.x, az0); az1 = fmaf(wz[j], h.y, az1);
            an0 = fmaf(wn[j], h.x, an0); an1 = fmaf(wn[j], h.y, an1);
        }

        red[((0 * 2 + 0) * 4 + kq) * 128 + e] = ar0;
        red[((0 * 2 + 1) * 4 + kq) * 128 + e] = ar1;
        red[((1 * 2 + 0) * 4 + kq) * 128 + e] = az0;
        red[((1 * 2 + 1) * 4 + kq) * 128 + e] = az1;
        red[((2 * 2 + 0) * 4 + kq) * 128 + e] = an0;
        red[((2 * 2 + 1) * 4 + kq) * 128 + e] = an1;
        __syncthreads();

        if (kq < 2) {
            const int b = kq;
            const float* rr = red + ((0 * 2 + b) * 4) * 128 + e;
            const float* rz = red + ((1 * 2 + b) * 4) * 128 + e;
            const float* rn = red + ((2 * 2 + b) * 4) * 128 + e;
            float fr = rr[0] + rr[128] + rr[256] + rr[384];
            float fz = rz[0] + rz[128] + rz[256] + rz[384];
            float fn = rn[0] + rn[128] + rn[256] + rn[384];

            float hp = hc2[2 * e + b];
            float r = sigm(pr + fr + br);
            float z = sigm(pz + fz + bz);
            float n = tanhf(pn + r * (fn + bn));
            float hn = (1.0f - z) * n + z * hp;
            float c  = fminf(fmaxf(hn, -CLIPV), CLIPV);
            if (clip_state) hn = c;

            hc2[2 * e + b] = hn;
            out[((size_t)t * BB + b0 + b) * out_ld + colbase + e] = c;
        }
        __syncthreads();
    }
}

// ---- u = mu + exp(0.5 lv)*eps ; concat factors ----
__global__ void make_uf_kernel(const float* __restrict__ mu, const float* __restrict__ lv,
                               const float* __restrict__ eps, const float* __restrict__ factors,
                               float* __restrict__ uf)
{
    int idx = blockIdx.x * blockDim.x + threadIdx.x;
    if (idx >= MROWS * 68) return;
    int row = idx / 68;
    int c   = idx - row * 68;
    float v;
    if (c < UU) {
        int o = row * UU + c;
        v = mu[o] + expf(0.5f * lv[o]) * eps[o];
    } else {
        v = factors[row * FF + (c - UU)];
    }
    uf[idx] = v;
}

// ---- AR1 calcium, parallel over (b,n) ----
__global__ void calcium_kernel(const float* __restrict__ spk,
                               const float* __restrict__ gain,
                               const float* __restrict__ biasp,
                               const float* __restrict__ logtau,
                               float* __restrict__ out)
{
    int idx = blockIdx.x * blockDim.x + threadIdx.x;
    if (idx >= BB * NN) return;
    float decay = 1.0f - 1.0f / expf(logtau[0]);
    float gn = gain[0], bp = biasp[0];
    float c = 0.0f;
    for (int t = 0; t < TT; t++) {
        size_t off = (size_t)t * (BB * NN) + idx;
        c = c * decay + gn * spk[off] + bp;
        out[off] = c;
    }
}

extern "C" void kernel_launch(void* const* d_in, const int* in_sizes, int n_in,
                              void* d_out, int out_size)
{
    const float* x       = (const float*)d_in[0];
    const float* factors = (const float*)d_in[1];
    const float* eps     = (const float*)d_in[2];
    const float* eWihf   = (const float*)d_in[3];
    const float* eWhhf   = (const float*)d_in[4];
    const float* ebihf   = (const float*)d_in[5];
    const float* ebhhf   = (const float*)d_in[6];
    const float* eWihb   = (const float*)d_in[7];
    const float* eWhhb   = (const float*)d_in[8];
    const float* ebihb   = (const float*)d_in[9];
    const float* ebhhb   = (const float*)d_in[10];
    const float* einit   = (const float*)d_in[11];
    const float* cWih    = (const float*)d_in[12];
    const float* cWhh    = (const float*)d_in[13];
    const float* cbih    = (const float*)d_in[14];
    const float* cbhh    = (const float*)d_in[15];
    const float* cinit   = (const float*)d_in[16];
    const float* Wmu     = (const float*)d_in[17];
    const float* bmu     = (const float*)d_in[18];
    const float* Wlv     = (const float*)d_in[19];
    const float* blv     = (const float*)d_in[20];
    const float* Wspk    = (const float*)d_in[21];
    const float* bspk    = (const float*)d_in[22];
    const float* gain    = (const float*)d_in[23];
    const float* biasp   = (const float*)d_in[24];
    const float* logtau  = (const float*)d_in[25];
    float* out = (float*)d_out;

    float *p_xpf, *p_xpb, *p_cp, *p_g, *p_hc, *p_mu, *p_lv, *p_uf, *p_spk;
    cudaGetSymbolAddress((void**)&p_xpf, d_xpf);
    cudaGetSymbolAddress((void**)&p_xpb, d_xpb);
    cudaGetSymbolAddress((void**)&p_cp,  d_cp);
    cudaGetSymbolAddress((void**)&p_g,   d_g);
    cudaGetSymbolAddress((void**)&p_hc,  d_hc);
    cudaGetSymbolAddress((void**)&p_mu,  d_mu);
    cudaGetSymbolAddress((void**)&p_lv,  d_lv);
    cudaGetSymbolAddress((void**)&p_uf,  d_uf);
    cudaGetSymbolAddress((void**)&p_spk, d_spk);

    const int MB = MROWS / 128; // 500

    // encoder input projections + controller x-part projection
    sgemm_kernel<<<dim3(3, MB), 256>>>(x, NN, eWihf, NN, ebihf, p_xpf, 384, 384, NN, 0);
    sgemm_kernel<<<dim3(3, MB), 256>>>(x, NN, eWihb, NN, ebihb, p_xpb, 384, 384, NN, 0);
    sgemm_kernel<<<dim3(3, MB), 256>>>(x, NN, cWih + 2 * EE, 2 * EE + NN, cbih, p_cp, 384, 384, NN, 0);

    // bidirectional encoder scan: 128 independent blocks (64 fwd + 64 bwd)
    gru_scan4_kernel<<<2 * S2P, 512>>>(
        p_xpf, p_xpb, eWhhf, eWhhb, ebhhf, ebhhb, einit, einit + EE,
        p_g, 256, 0, EE, /*clip_state=*/0, /*rev_b=*/1);

    // controller projection, g part (accumulate into cp)
    sgemm_kernel<<<dim3(3, MB), 256>>>(p_g, 256, cWih, 2 * EE + NN, (const float*)0, p_cp, 384, 384, 256, 1);

    // controller scan (single direction, clipped state)
    gru_scan4_kernel<<<S2P, 512>>>(
        p_cp, p_cp, cWhh, cWhh, cbhh, cbhh, cinit, cinit,
        p_hc, 128, 0, 0, /*clip_state=*/1, /*rev_b=*/0);

    // latent heads
    sgemm_kernel<<<dim3(1, MB), 256>>>(p_hc, 128, Wmu, CC, bmu, p_mu, 64, UU, CC, 0);
    sgemm_kernel<<<dim3(1, MB), 256>>>(p_hc, 128, Wlv, CC, blv, p_lv, 64, UU, CC, 0);

    // sample + concat factors
    make_uf_kernel<<<(MROWS * 68 + 255) / 256, 256>>>(p_mu, p_lv, eps, factors, p_uf);

    // spike generator with fused exp-relu epilogue
    sgemm_kernel<<<dim3(3, MB), 256>>>(p_uf, 68, Wspk, UU + FF, bspk, p_spk, 300, NN, UU + FF, 2);

    // AR1 calcium
    calcium_kernel<<<(BB * NN + 255) / 256, 256>>>(p_spk, gain, biasp, logtau, out);
}

// round 10
// speedup vs baseline: 3.3720x; 1.2848x over previous
#include <cuda_runtime.h>
#include <cuda_bf16.h>
#include <math.h>
#include <stdint.h>

#define TT 500
#define BB 128
#define NN 300
#define EE 128
#define CC 128
#define UU 64
#define FF 4
#define CLIPV 5.0f
#define S2P 64
#define MROWS (TT*BB)       // 64000
#define KAUG_X 960          // 3 * Kpad(320) for K=300
#define KAUG_G 768          // 3 * Kpad(256) for K=256

// ---- static device scratch ----
__device__ float d_xpf[MROWS * 384];
__device__ float d_xpb[MROWS * 384];
__device__ float d_cp [MROWS * 384];
__device__ float d_g  [MROWS * 256];
__device__ float d_hc [MROWS * 128];
__device__ float d_mu [MROWS * 64];
__device__ float d_lv [MROWS * 64];
__device__ float d_uf [MROWS * 68];
__device__ float d_spk[MROWS * 300];
// bf16-split augmented operands, plain row-major [row][Kaug]
__device__ __nv_bfloat16 d_xaug[(size_t)MROWS * KAUG_X];
__device__ __nv_bfloat16 d_gaug[(size_t)MROWS * KAUG_G];
__device__ __nv_bfloat16 d_wfa[384 * KAUG_X];
__device__ __nv_bfloat16 d_wba[384 * KAUG_X];
__device__ __nv_bfloat16 d_wxa[384 * KAUG_X];
__device__ __nv_bfloat16 d_wga[384 * KAUG_G];

__device__ __forceinline__ float sigm(float x) { return 1.0f / (1.0f + expf(-x)); }

// ---- bf16 hi/lo split into augmented row-major matrix ----
// role 0 (A side): segments [hi, hi, lo]; role 1 (B side): [hi, lo, hi]
__global__ void aug_kernel(const float* __restrict__ src, int ld, int K, int rows,
                           __nv_bfloat16* __restrict__ dst, int Kaug, int role)
{
    int groups = Kaug / 8;
    int Kpad = Kaug / 3;
    long long idx = (long long)blockIdx.x * blockDim.x + threadIdx.x;
    if (idx >= (long long)rows * groups) return;
    int row = (int)(idx / groups);
    int j   = (int)(idx - (long long)row * groups);
    int kau0 = j * 8;
    int seg = kau0 / Kpad;
    int kk0 = kau0 - seg * Kpad;
    bool lo = (role == 0) ? (seg == 2) : (seg == 1);
    __nv_bfloat16 vals[8];
#pragma unroll
    for (int i = 0; i < 8; i++) {
        int kk = kk0 + i;
        float v = (kk < K) ? src[(size_t)row * ld + kk] : 0.0f;
        __nv_bfloat16 h = __float2bfloat16(v);
        vals[i] = lo ? __float2bfloat16(v - __bfloat162float(h)) : h;
    }
    *(uint4*)(dst + (size_t)row * Kaug + kau0) = *(uint4*)vals;
}

// ---- bf16 mma.sync GEMM: C[128 x 128 tile] = Aaug[M][Kaug] x Baug[N][Kaug]^T (+bias)
// flags bit0: accumulate into C. 256 threads, 8 warps (2m x 4n), warp = 64x32.
#define MMA16816(d, a, b) \
    asm volatile("mma.sync.aligned.m16n8k16.row.col.f32.bf16.bf16.f32 " \
        "{%0,%1,%2,%3}, {%4,%5,%6,%7}, {%8,%9}, {%0,%1,%2,%3};" \
        : "+f"((d)[0]), "+f"((d)[1]), "+f"((d)[2]), "+f"((d)[3]) \
        : "r"((a)[0]), "r"((a)[1]), "r"((a)[2]), "r"((a)[3]), \
          "r"((b)[0]), "r"((b)[1]))

__global__ __launch_bounds__(256) void hgemm_kernel(
    const __nv_bfloat16* __restrict__ A,   // [Mrows][Kaug]
    const __nv_bfloat16* __restrict__ B,   // [N][Kaug]
    const float* __restrict__ bias,
    float* __restrict__ C, int ldc, int Kaug, int flags)
{
    extern __shared__ __nv_bfloat16 smem[];
    // 4 k16-subtiles, each [128 rows][stride 24] bf16 (conflict-free fragment LDS)
    __nv_bfloat16* As = smem;            // 4*3072 = 12288 elems
    __nv_bfloat16* Bs = smem + 12288;

    const int tid = threadIdx.x;
    const int lane = tid & 31;
    const int wid = tid >> 5;
    const int warp_m = wid >> 2;         // 0..1
    const int warp_n = wid & 3;          // 0..3
    const int m0 = blockIdx.y * 128;
    const int n0 = blockIdx.x * 128;

    const int lrow = tid >> 1;           // 0..127
    const int lhalf = tid & 1;           // 0..1

    float acc[4][4][4];
#pragma unroll
    for (int mi = 0; mi < 4; mi++)
#pragma unroll
        for (int ni = 0; ni < 4; ni++)
#pragma unroll
            for (int q = 0; q < 4; q++) acc[mi][ni][q] = 0.0f;

    const int gr = lane >> 2;            // group row 0..7
    const int gc = (lane & 3) * 2;       // col pair base

    for (int kc = 0; kc < Kaug; kc += 64) {
        __syncthreads();
#pragma unroll
        for (int kk = 0; kk < 4; kk++) {
            *(uint4*)(As + kk * 3072 + lrow * 24 + lhalf * 8) =
                *(const uint4*)(A + (size_t)(m0 + lrow) * Kaug + kc + kk * 16 + lhalf * 8);
            *(uint4*)(Bs + kk * 3072 + lrow * 24 + lhalf * 8) =
                *(const uint4*)(B + (size_t)(n0 + lrow) * Kaug + kc + kk * 16 + lhalf * 8);
        }
        __syncthreads();
#pragma unroll
        for (int kk = 0; kk < 4; kk++) {
            uint32_t af[4][4];
#pragma unroll
            for (int mi = 0; mi < 4; mi++) {
                const __nv_bfloat16* ap = As + kk * 3072 + (warp_m * 64 + mi * 16 + gr) * 24 + gc;
                af[mi][0] = *(const uint32_t*)(ap);
                af[mi][1] = *(const uint32_t*)(ap + 8 * 24);
                af[mi][2] = *(const uint32_t*)(ap + 8);
                af[mi][3] = *(const uint32_t*)(ap + 8 * 24 + 8);
            }
            uint32_t bfr[4][2];
#pragma unroll
            for (int ni = 0; ni < 4; ni++) {
                const __nv_bfloat16* bp = Bs + kk * 3072 + (warp_n * 32 + ni * 8 + gr) * 24 + gc;
                bfr[ni][0] = *(const uint32_t*)(bp);
                bfr[ni][1] = *(const uint32_t*)(bp + 8);
            }
#pragma unroll
            for (int mi = 0; mi < 4; mi++)
#pragma unroll
                for (int ni = 0; ni < 4; ni++)
                    MMA16816(acc[mi][ni], af[mi], bfr[ni]);
        }
    }

    // epilogue
#pragma unroll
    for (int mi = 0; mi < 4; mi++) {
#pragma unroll
        for (int ni = 0; ni < 4; ni++) {
            const float* a = acc[mi][ni];
            int m = m0 + warp_m * 64 + mi * 16 + gr;
            int n = n0 + warp_n * 32 + ni * 8 + gc;
            float b0 = bias ? bias[n] : 0.0f;
            float b1 = bias ? bias[n + 1] : 0.0f;
#pragma unroll
            for (int h = 0; h < 2; h++) {
                int mm = m + h * 8;
                float v0 = a[h * 2 + 0] + b0;
                float v1 = a[h * 2 + 1] + b1;
                float* Cp = C + (size_t)mm * ldc + n;
                if (flags & 1) {
                    float2 o = *(float2*)Cp;
                    v0 += o.x; v1 += o.y;
                }
                float2 w; w.x = v0; w.y = v1;
                *(float2*)Cp = w;
            }
        }
    }
}

// ---- fp32 SGEMM (spike / mu / lv): C = A @ W^T (+bias); flags bit1: spike epilogue ----
__global__ __launch_bounds__(256) void sgemm_kernel(
    const float* __restrict__ A, int lda,
    const float* __restrict__ W, int ldw,
    const float* __restrict__ bias,
    float* __restrict__ C, int ldc,
    int N, int K, int flags)
{
    __shared__ float As[8][128];
    __shared__ float Ws[8][128];
    const int tid = threadIdx.x;
    const int m0 = blockIdx.y * 128;
    const int n0 = blockIdx.x * 128;
    const int lr = tid >> 1;
    const int lc = (tid & 1) << 2;
    const int tx = tid & 15;
    const int ty = tid >> 4;

    float acc[8][8];
#pragma unroll
    for (int i = 0; i < 8; i++)
#pragma unroll
        for (int j = 0; j < 8; j++) acc[i][j] = 0.0f;

    for (int k0 = 0; k0 < K; k0 += 8) {
        {
            float4 v = make_float4(0.f, 0.f, 0.f, 0.f);
            int kbase = k0 + lc;
            int rem = K - kbase;
            const float* Ap = A + (size_t)(m0 + lr) * lda + kbase;
            if (rem >= 4) v = *(const float4*)Ap;
            else if (rem > 0) {
                v.x = Ap[0];
                if (rem > 1) v.y = Ap[1];
                if (rem > 2) v.z = Ap[2];
            }
            As[lc + 0][lr] = v.x; As[lc + 1][lr] = v.y;
            As[lc + 2][lr] = v.z; As[lc + 3][lr] = v.w;
        }
        {
            float4 v = make_float4(0.f, 0.f, 0.f, 0.f);
            int n = n0 + lr;
            int kbase = k0 + lc;
            int rem = K - kbase;
            if (n < N && rem > 0) {
                const float* Wp = W + (size_t)n * ldw + kbase;
                if (rem >= 4) v = *(const float4*)Wp;
                else {
                    v.x = Wp[0];
                    if (rem > 1) v.y = Wp[1];
                    if (rem > 2) v.z = Wp[2];
                }
            }
            Ws[lc + 0][lr] = v.x; Ws[lc + 1][lr] = v.y;
            Ws[lc + 2][lr] = v.z; Ws[lc + 3][lr] = v.w;
        }
        __syncthreads();
#pragma unroll
        for (int k = 0; k < 8; k++) {
            float a[8], bb[8];
            *(float4*)&a[0]  = *(const float4*)&As[k][ty * 8];
            *(float4*)&a[4]  = *(const float4*)&As[k][ty * 8 + 4];
            *(float4*)&bb[0] = *(const float4*)&Ws[k][tx * 8];
            *(float4*)&bb[4] = *(const float4*)&Ws[k][tx * 8 + 4];
#pragma unroll
            for (int i = 0; i < 8; i++)
#pragma unroll
                for (int j = 0; j < 8; j++)
                    acc[i][j] = fmaf(a[i], bb[j], acc[i][j]);
        }
        __syncthreads();
    }

#pragma unroll
    for (int i = 0; i < 8; i++) {
        int m = m0 + ty * 8 + i;
#pragma unroll
        for (int j = 0; j < 8; j++) {
            int n = n0 + tx * 8 + j;
            if (n < N) {
                float v = acc[i][j];
                if (bias) v += bias[n];
                size_t off = (size_t)m * ldc + n;
                if (flags & 1) v += C[off];
                if (flags & 2) v = fmaxf(expf(v) - 1.0f, 0.0f);
                C[off] = v;
            }
        }
    }
}

// ---- register-weight GRU scan (R8 winner, unchanged) ----
__global__ __launch_bounds__(512) void gru_scan4_kernel(
    const float* __restrict__ xp_a, const float* __restrict__ xp_b,
    const float* __restrict__ W_a,  const float* __restrict__ W_b,
    const float* __restrict__ bh_a, const float* __restrict__ bh_b,
    const float* __restrict__ init_a, const float* __restrict__ init_b,
    float* __restrict__ out, int out_ld, int col_a, int col_b,
    int clip_state, int rev_b)
{
    __shared__ float hc2[2 * 128];
    __shared__ float red[3 * 2 * 4 * 128];

    const int dir = blockIdx.x / S2P;
    const int jb  = blockIdx.x % S2P;
    const float* xp   = dir ? xp_b   : xp_a;
    const float* Whh  = dir ? W_b    : W_a;
    const float* bhh  = dir ? bh_b   : bh_a;
    const float* hini = dir ? init_b : init_a;
    const int colbase = dir ? col_b  : col_a;
    const int rev     = dir ? rev_b  : 0;
    const int b0 = jb * 2;

    const int tid = threadIdx.x;
    const int e  = tid & 127;
    const int kq = tid >> 7;

    float wr[32], wz[32], wn[32];
    {
        const float* r0 = Whh + (size_t)(0 * 128 + e) * 128 + kq * 32;
        const float* r1 = Whh + (size_t)(1 * 128 + e) * 128 + kq * 32;
        const float* r2 = Whh + (size_t)(2 * 128 + e) * 128 + kq * 32;
#pragma unroll
        for (int j4 = 0; j4 < 8; j4++) {
            float4 a = *(const float4*)(r0 + j4 * 4);
            float4 b = *(const float4*)(r1 + j4 * 4);
            float4 c = *(const float4*)(r2 + j4 * 4);
            wr[j4*4+0]=a.x; wr[j4*4+1]=a.y; wr[j4*4+2]=a.z; wr[j4*4+3]=a.w;
            wz[j4*4+0]=b.x; wz[j4*4+1]=b.y; wz[j4*4+2]=b.z; wz[j4*4+3]=b.w;
            wn[j4*4+0]=c.x; wn[j4*4+1]=c.y; wn[j4*4+2]=c.z; wn[j4*4+3]=c.w;
        }
    }
    const float br = bhh[e], bz = bhh[128 + e], bn = bhh[256 + e];

    if (kq < 2) hc2[2 * e + kq] = hini[e];
    __syncthreads();

    const float2* h2 = (const float2*)hc2 + kq * 32;

    for (int s = 0; s < TT; s++) {
        const int t = rev ? (TT - 1 - s) : s;
        float pr = 0.f, pz = 0.f, pn = 0.f;
        if (kq < 2) {
            const float* xr = xp + ((size_t)t * BB + b0 + kq) * 384;
            pr = __ldg(xr + e); pz = __ldg(xr + 128 + e); pn = __ldg(xr + 256 + e);
        }

        float ar0 = 0.f, ar1 = 0.f, az0 = 0.f, az1 = 0.f, an0 = 0.f, an1 = 0.f;
#pragma unroll
        for (int j = 0; j < 32; j++) {
            float2 h = h2[j];
            ar0 = fmaf(wr[j], h.x, ar0); ar1 = fmaf(wr[j], h.y, ar1);
            az0 = fmaf(wz[j], h.x, az0); az1 = fmaf(wz[j], h.y, az1);
            an0 = fmaf(wn[j], h.x, an0); an1 = fmaf(wn[j], h.y, an1);
        }

        red[((0 * 2 + 0) * 4 + kq) * 128 + e] = ar0;
        red[((0 * 2 + 1) * 4 + kq) * 128 + e] = ar1;
        red[((1 * 2 + 0) * 4 + kq) * 128 + e] = az0;
        red[((1 * 2 + 1) * 4 + kq) * 128 + e] = az1;
        red[((2 * 2 + 0) * 4 + kq) * 128 + e] = an0;
        red[((2 * 2 + 1) * 4 + kq) * 128 + e] = an1;
        __syncthreads();

        if (kq < 2) {
            const int b = kq;
            const float* rr = red + ((0 * 2 + b) * 4) * 128 + e;
            const float* rz = red + ((1 * 2 + b) * 4) * 128 + e;
            const float* rn = red + ((2 * 2 + b) * 4) * 128 + e;
            float fr = rr[0] + rr[128] + rr[256] + rr[384];
            float fz = rz[0] + rz[128] + rz[256] + rz[384];
            float fn = rn[0] + rn[128] + rn[256] + rn[384];

            float hp = hc2[2 * e + b];
            float r = sigm(pr + fr + br);
            float z = sigm(pz + fz + bz);
            float n = tanhf(pn + r * (fn + bn));
            float hn = (1.0f - z) * n + z * hp;
            float c  = fminf(fmaxf(hn, -CLIPV), CLIPV);
            if (clip_state) hn = c;

            hc2[2 * e + b] = hn;
            out[((size_t)t * BB + b0 + b) * out_ld + colbase + e] = c;
        }
        __syncthreads();
    }
}

// ---- u = mu + exp(0.5 lv)*eps ; concat factors ----
__global__ void make_uf_kernel(const float* __restrict__ mu, const float* __restrict__ lv,
                               const float* __restrict__ eps, const float* __restrict__ factors,
                               float* __restrict__ uf)
{
    int idx = blockIdx.x * blockDim.x + threadIdx.x;
    if (idx >= MROWS * 68) return;
    int row = idx / 68;
    int c   = idx - row * 68;
    float v;
    if (c < UU) {
        int o = row * UU + c;
        v = mu[o] + expf(0.5f * lv[o]) * eps[o];
    } else {
        v = factors[row * FF + (c - UU)];
    }
    uf[idx] = v;
}

// ---- AR1 calcium ----
__global__ void calcium_kernel(const float* __restrict__ spk,
                               const float* __restrict__ gain,
                               const float* __restrict__ biasp,
                               const float* __restrict__ logtau,
                               float* __restrict__ out)
{
    int idx = blockIdx.x * blockDim.x + threadIdx.x;
    if (idx >= BB * NN) return;
    float decay = 1.0f - 1.0f / expf(logtau[0]);
    float gn = gain[0], bp = biasp[0];
    float c = 0.0f;
    for (int t = 0; t < TT; t++) {
        size_t off = (size_t)t * (BB * NN) + idx;
        c = c * decay + gn * spk[off] + bp;
        out[off] = c;
    }
}

extern "C" void kernel_launch(void* const* d_in, const int* in_sizes, int n_in,
                              void* d_out, int out_size)
{
    const float* x       = (const float*)d_in[0];
    const float* factors = (const float*)d_in[1];
    const float* eps     = (const float*)d_in[2];
    const float* eWihf   = (const float*)d_in[3];
    const float* eWhhf   = (const float*)d_in[4];
    const float* ebihf   = (const float*)d_in[5];
    const float* ebhhf   = (const float*)d_in[6];
    const float* eWihb   = (const float*)d_in[7];
    const float* eWhhb   = (const float*)d_in[8];
    const float* ebihb   = (const float*)d_in[9];
    const float* ebhhb   = (const float*)d_in[10];
    const float* einit   = (const float*)d_in[11];
    const float* cWih    = (const float*)d_in[12];
    const float* cWhh    = (const float*)d_in[13];
    const float* cbih    = (const float*)d_in[14];
    const float* cbhh    = (const float*)d_in[15];
    const float* cinit   = (const float*)d_in[16];
    const float* Wmu     = (const float*)d_in[17];
    const float* bmu     = (const float*)d_in[18];
    const float* Wlv     = (const float*)d_in[19];
    const float* blv     = (const float*)d_in[20];
    const float* Wspk    = (const float*)d_in[21];
    const float* bspk    = (const float*)d_in[22];
    const float* gain    = (const float*)d_in[23];
    const float* biasp   = (const float*)d_in[24];
    const float* logtau  = (const float*)d_in[25];
    float* out = (float*)d_out;

    float *p_xpf, *p_xpb, *p_cp, *p_g, *p_hc, *p_mu, *p_lv, *p_uf, *p_spk;
    __nv_bfloat16 *p_xaug, *p_gaug, *p_wfa, *p_wba, *p_wxa, *p_wga;
    cudaGetSymbolAddress((void**)&p_xpf, d_xpf);
    cudaGetSymbolAddress((void**)&p_xpb, d_xpb);
    cudaGetSymbolAddress((void**)&p_cp,  d_cp);
    cudaGetSymbolAddress((void**)&p_g,   d_g);
    cudaGetSymbolAddress((void**)&p_hc,  d_hc);
    cudaGetSymbolAddress((void**)&p_mu,  d_mu);
    cudaGetSymbolAddress((void**)&p_lv,  d_lv);
    cudaGetSymbolAddress((void**)&p_uf,  d_uf);
    cudaGetSymbolAddress((void**)&p_spk, d_spk);
    cudaGetSymbolAddress((void**)&p_xaug, d_xaug);
    cudaGetSymbolAddress((void**)&p_gaug, d_gaug);
    cudaGetSymbolAddress((void**)&p_wfa, d_wfa);
    cudaGetSymbolAddress((void**)&p_wba, d_wba);
    cudaGetSymbolAddress((void**)&p_wxa, d_wxa);
    cudaGetSymbolAddress((void**)&p_wga, d_wga);

    const int MB = MROWS / 128; // 500
    const int hg_smem = 2 * 12288 * (int)sizeof(__nv_bfloat16);  // 49152 B
    cudaFuncSetAttribute(hgemm_kernel, cudaFuncAttributeMaxDynamicSharedMemorySize, hg_smem);

    // ---- bf16-split conversions ----
    {
        long long na = (long long)MROWS * (KAUG_X / 8);
        aug_kernel<<<(int)((na + 255) / 256), 256>>>(x, NN, NN, MROWS, p_xaug, KAUG_X, 0);
        long long nw = 384LL * (KAUG_X / 8);
        aug_kernel<<<(int)((nw + 255) / 256), 256>>>(eWihf, NN, NN, 384, p_wfa, KAUG_X, 1);
        aug_kernel<<<(int)((nw + 255) / 256), 256>>>(eWihb, NN, NN, 384, p_wba, KAUG_X, 1);
        aug_kernel<<<(int)((nw + 255) / 256), 256>>>(cWih + 2 * EE, 2 * EE + NN, NN, 384, p_wxa, KAUG_X, 1);
        long long ng = 384LL * (KAUG_G / 8);
        aug_kernel<<<(int)((ng + 255) / 256), 256>>>(cWih, 2 * EE + NN, 2 * EE, 384, p_wga, KAUG_G, 1);
    }

    // ---- encoder input projections + controller x-part (bf16-split mma) ----
    hgemm_kernel<<<dim3(3, MB), 256, hg_smem>>>(p_xaug, p_wfa, ebihf, p_xpf, 384, KAUG_X, 0);
    hgemm_kernel<<<dim3(3, MB), 256, hg_smem>>>(p_xaug, p_wba, ebihb, p_xpb, 384, KAUG_X, 0);
    hgemm_kernel<<<dim3(3, MB), 256, hg_smem>>>(p_xaug, p_wxa, cbih,  p_cp,  384, KAUG_X, 0);

    // ---- bidirectional encoder scan ----
    gru_scan4_kernel<<<2 * S2P, 512>>>(
        p_xpf, p_xpb, eWhhf, eWhhb, ebhhf, ebhhb, einit, einit + EE,
        p_g, 256, 0, EE, /*clip_state=*/0, /*rev_b=*/1);

    // ---- controller projection, g part (bf16-split mma, accumulate) ----
    {
        long long ng2 = (long long)MROWS * (KAUG_G / 8);
        aug_kernel<<<(int)((ng2 + 255) / 256), 256>>>(p_g, 256, 256, MROWS, p_gaug, KAUG_G, 0);
    }
    hgemm_kernel<<<dim3(3, MB), 256, hg_smem>>>(p_gaug, p_wga, (const float*)0, p_cp, 384, KAUG_G, 1);

    // ---- controller scan ----
    gru_scan4_kernel<<<S2P, 512>>>(
        p_cp, p_cp, cWhh, cWhh, cbhh, cbhh, cinit, cinit,
        p_hc, 128, 0, 0, /*clip_state=*/1, /*rev_b=*/0);

    // ---- latent heads (fp32) ----
    sgemm_kernel<<<dim3(1, MB), 256>>>(p_hc, 128, Wmu, CC, bmu, p_mu, 64, UU, CC, 0);
    sgemm_kernel<<<dim3(1, MB), 256>>>(p_hc, 128, Wlv, CC, blv, p_lv, 64, UU, CC, 0);

    // ---- sample + concat factors ----
    make_uf_kernel<<<(MROWS * 68 + 255) / 256, 256>>>(p_mu, p_lv, eps, factors, p_uf);

    // ---- spike generator (fp32, fused exp-relu) ----
    sgemm_kernel<<<dim3(3, MB), 256>>>(p_uf, 68, Wspk, UU + FF, bspk, p_spk, 300, NN, UU + FF, 2);

    // ---- AR1 calcium ----
    calcium_kernel<<<(BB * NN + 255) / 256, 256>>>(p_spk, gain, biasp, logtau, out);
}

// round 12
// speedup vs baseline: 3.5347x; 1.0483x over previous
#include <cuda_runtime.h>
#include <cuda_bf16.h>
#include <math.h>
#include <stdint.h>

#define TT 500
#define BB 128
#define NN 300
#define EE 128
#define CC 128
#define UU 64
#define FF 4
#define CLIPV 5.0f
#define S2P 64
#define MROWS (TT*BB)       // 64000
#define KAUG_X 960          // 3 * Kpad(320) for K=300
#define KAUG_G 768          // 3 * Kpad(256) for K=256

// ---- static device scratch ----
__device__ float d_xpf[MROWS * 384];
__device__ float d_xpb[MROWS * 384];
__device__ float d_cp [MROWS * 384];
__device__ float d_g  [MROWS * 256];
__device__ float d_hc [MROWS * 128];
__device__ float d_mu [MROWS * 64];
__device__ float d_lv [MROWS * 64];
__device__ float d_uf [MROWS * 68];
__device__ float d_spk[MROWS * 300];
__device__ __nv_bfloat16 d_xaug[(size_t)MROWS * KAUG_X];
__device__ __nv_bfloat16 d_gaug[(size_t)MROWS * KAUG_G];
__device__ __nv_bfloat16 d_wfa[384 * KAUG_X];
__device__ __nv_bfloat16 d_wba[384 * KAUG_X];
__device__ __nv_bfloat16 d_wxa[384 * KAUG_X];
__device__ __nv_bfloat16 d_wga[384 * KAUG_G];

__device__ __forceinline__ float sigm(float x) { return 1.0f / (1.0f + expf(-x)); }

// ---- bf16 hi/lo split into augmented row-major matrix ----
// role 0 (A side): segments [hi, hi, lo]; role 1 (B side): [hi, lo, hi]
__global__ void aug_kernel(const float* __restrict__ src, int ld, int K, int rows,
                           __nv_bfloat16* __restrict__ dst, int Kaug, int role)
{
    int groups = Kaug / 8;
    int Kpad = Kaug / 3;
    long long idx = (long long)blockIdx.x * blockDim.x + threadIdx.x;
    if (idx >= (long long)rows * groups) return;
    int row = (int)(idx / groups);
    int j   = (int)(idx - (long long)row * groups);
    int kau0 = j * 8;
    int seg = kau0 / Kpad;
    int kk0 = kau0 - seg * Kpad;
    bool lo = (role == 0) ? (seg == 2) : (seg == 1);
    __nv_bfloat16 vals[8];
#pragma unroll
    for (int i = 0; i < 8; i++) {
        int kk = kk0 + i;
        float v = (kk < K) ? src[(size_t)row * ld + kk] : 0.0f;
        __nv_bfloat16 h = __float2bfloat16(v);
        vals[i] = lo ? __float2bfloat16(v - __bfloat162float(h)) : h;
    }
    *(uint4*)(dst + (size_t)row * Kaug + kau0) = *(uint4*)vals;
}

// ---- bf16 mma GEMM with cp.async double-buffering + ldmatrix fragments ----
#define MMA16816(d, a, b) \
    asm volatile("mma.sync.aligned.m16n8k16.row.col.f32.bf16.bf16.f32 " \
        "{%0,%1,%2,%3}, {%4,%5,%6,%7}, {%8,%9}, {%0,%1,%2,%3};" \
        : "+f"((d)[0]), "+f"((d)[1]), "+f"((d)[2]), "+f"((d)[3]) \
        : "r"((a)[0]), "r"((a)[1]), "r"((a)[2]), "r"((a)[3]), \
          "r"((b)[0]), "r"((b)[1]))
#define LDSM_X4(r0, r1, r2, r3, addr) \
    asm volatile("ldmatrix.sync.aligned.m8n8.x4.shared.b16 {%0,%1,%2,%3}, [%4];" \
        : "=r"(r0), "=r"(r1), "=r"(r2), "=r"(r3) : "r"(addr))
#define CP_ASYNC16(smem_addr, gptr) \
    asm volatile("cp.async.cg.shared.global [%0], [%1], 16;" :: "r"(smem_addr), "l"(gptr))
#define CP_COMMIT() asm volatile("cp.async.commit_group;")
#define CP_WAIT(N)  asm volatile("cp.async.wait_group %0;" :: "n"(N))

// stage layout (elems): [A: 4 kk-subtiles x 128 rows x 24 stride][B: same] = 24576/stage
__global__ __launch_bounds__(256) void hgemm_kernel(
    const __nv_bfloat16* __restrict__ A,   // [Mrows][Kaug]
    const __nv_bfloat16* __restrict__ B,   // [N][Kaug]
    const float* __restrict__ bias,
    float* __restrict__ C, int ldc, int Kaug, int flags)
{
    extern __shared__ __nv_bfloat16 smem[];
    const int STAGE = 24576;

    const int tid = threadIdx.x;
    const int lane = tid & 31;
    const int wid = tid >> 5;
    const int warp_m = wid >> 2;
    const int warp_n = wid & 3;
    const int m0 = blockIdx.y * 128;
    const int n0 = blockIdx.x * 128;
    const int lrow = tid >> 1;
    const int lhalf = tid & 1;

    uint32_t sb = (uint32_t)__cvta_generic_to_shared(smem);

    float acc[4][4][4];
#pragma unroll
    for (int mi = 0; mi < 4; mi++)
#pragma unroll
        for (int ni = 0; ni < 4; ni++)
#pragma unroll
            for (int q = 0; q < 4; q++) acc[mi][ni][q] = 0.0f;

    const __nv_bfloat16* Agp = A + (size_t)(m0 + lrow) * Kaug + lhalf * 8;
    const __nv_bfloat16* Bgp = B + (size_t)(n0 + lrow) * Kaug + lhalf * 8;
    const uint32_t sA = sb + (lrow * 24 + lhalf * 8) * 2;
    const uint32_t sB = sb + (12288 + lrow * 24 + lhalf * 8) * 2;

    const int nch = Kaug >> 6;

    // ldmatrix base addrs (lane-dependent)
    const int lr16 = lane & 15;
    const int lh16 = lane >> 4;
    const uint32_t aAddr0 = sb + ((warp_m * 64 + lr16) * 24) * 2 + lh16 * 16;
    const uint32_t bAddr0 = sb + (12288 + (warp_n * 32 + lr16) * 24) * 2 + lh16 * 16;

    // prefetch chunk 0 -> stage 0
#pragma unroll
    for (int kk = 0; kk < 4; kk++) {
        CP_ASYNC16(sA + kk * 3072 * 2, Agp + kk * 16);
        CP_ASYNC16(sB + kk * 3072 * 2, Bgp + kk * 16);
    }
    CP_COMMIT();

    for (int ci = 0; ci < nch; ci++) {
        int st = ci & 1;
        if (ci + 1 < nch) {
            int st2 = 1 - st;
            const __nv_bfloat16* Ag2 = Agp + (ci + 1) * 64;
            const __nv_bfloat16* Bg2 = Bgp + (ci + 1) * 64;
#pragma unroll
            for (int kk = 0; kk < 4; kk++) {
                CP_ASYNC16(sA + (st2 * STAGE + kk * 3072) * 2, Ag2 + kk * 16);
                CP_ASYNC16(sB + (st2 * STAGE + kk * 3072) * 2, Bg2 + kk * 16);
            }
            CP_COMMIT();
            CP_WAIT(1);
        } else {
            CP_WAIT(0);
        }
        __syncthreads();

        uint32_t stoff = (uint32_t)(st * STAGE) * 2;
#pragma unroll
        for (int kk = 0; kk < 4; kk++) {
            uint32_t af[4][4];
#pragma unroll
            for (int mi = 0; mi < 4; mi++) {
                uint32_t ad = aAddr0 + stoff + (kk * 3072 + mi * 16 * 24) * 2;
                LDSM_X4(af[mi][0], af[mi][1], af[mi][2], af[mi][3], ad);
            }
            uint32_t bfr[4][2];
#pragma unroll
            for (int np = 0; np < 2; np++) {
                uint32_t r0, r1, r2, r3;
                uint32_t bd = bAddr0 + stoff + (kk * 3072 + np * 16 * 24) * 2;
                LDSM_X4(r0, r1, r2, r3, bd);
                bfr[2 * np][0] = r0; bfr[2 * np + 1][0] = r1;
                bfr[2 * np][1] = r2; bfr[2 * np + 1][1] = r3;
            }
#pragma unroll
            for (int mi = 0; mi < 4; mi++)
#pragma unroll
                for (int ni = 0; ni < 4; ni++)
                    MMA16816(acc[mi][ni], af[mi], bfr[ni]);
        }
        __syncthreads();
    }

    // epilogue
    const int gr = lane >> 2;
    const int gc = (lane & 3) * 2;
#pragma unroll
    for (int mi = 0; mi < 4; mi++) {
#pragma unroll
        for (int ni = 0; ni < 4; ni++) {
            const float* a = acc[mi][ni];
            int m = m0 + warp_m * 64 + mi * 16 + gr;
            int n = n0 + warp_n * 32 + ni * 8 + gc;
            float b0 = bias ? bias[n] : 0.0f;
            float b1 = bias ? bias[n + 1] : 0.0f;
#pragma unroll
            for (int h = 0; h < 2; h++) {
                int mm = m + h * 8;
                float v0 = a[h * 2 + 0] + b0;
                float v1 = a[h * 2 + 1] + b1;
                float* Cp = C + (size_t)mm * ldc + n;
                if (flags & 1) {
                    float2 o = *(float2*)Cp;
                    v0 += o.x; v1 += o.y;
                }
                float2 w; w.x = v0; w.y = v1;
                *(float2*)Cp = w;
            }
        }
    }
}

// ---- fp32 SGEMM (spike / mu / lv) ----
__global__ __launch_bounds__(256) void sgemm_kernel(
    const float* __restrict__ A, int lda,
    const float* __restrict__ W, int ldw,
    const float* __restrict__ bias,
    float* __restrict__ C, int ldc,
    int N, int K, int flags)
{
    __shared__ float As[8][128];
    __shared__ float Ws[8][128];
    const int tid = threadIdx.x;
    const int m0 = blockIdx.y * 128;
    const int n0 = blockIdx.x * 128;
    const int lr = tid >> 1;
    const int lc = (tid & 1) << 2;
    const int tx = tid & 15;
    const int ty = tid >> 4;

    float acc[8][8];
#pragma unroll
    for (int i = 0; i < 8; i++)
#pragma unroll
        for (int j = 0; j < 8; j++) acc[i][j] = 0.0f;

    for (int k0 = 0; k0 < K; k0 += 8) {
        {
            float4 v = make_float4(0.f, 0.f, 0.f, 0.f);
            int kbase = k0 + lc;
            int rem = K - kbase;
            const float* Ap = A + (size_t)(m0 + lr) * lda + kbase;
            if (rem >= 4) v = *(const float4*)Ap;
            else if (rem > 0) {
                v.x = Ap[0];
                if (rem > 1) v.y = Ap[1];
                if (rem > 2) v.z = Ap[2];
            }
            As[lc + 0][lr] = v.x; As[lc + 1][lr] = v.y;
            As[lc + 2][lr] = v.z; As[lc + 3][lr] = v.w;
        }
        {
            float4 v = make_float4(0.f, 0.f, 0.f, 0.f);
            int n = n0 + lr;
            int kbase = k0 + lc;
            int rem = K - kbase;
            if (n < N && rem > 0) {
                const float* Wp = W + (size_t)n * ldw + kbase;
                if (rem >= 4) v = *(const float4*)Wp;
                else {
                    v.x = Wp[0];
                    if (rem > 1) v.y = Wp[1];
                    if (rem > 2) v.z = Wp[2];
                }
            }
            Ws[lc + 0][lr] = v.x; Ws[lc + 1][lr] = v.y;
            Ws[lc + 2][lr] = v.z; Ws[lc + 3][lr] = v.w;
        }
        __syncthreads();
#pragma unroll
        for (int k = 0; k < 8; k++) {
            float a[8], bb[8];
            *(float4*)&a[0]  = *(const float4*)&As[k][ty * 8];
            *(float4*)&a[4]  = *(const float4*)&As[k][ty * 8 + 4];
            *(float4*)&bb[0] = *(const float4*)&Ws[k][tx * 8];
            *(float4*)&bb[4] = *(const float4*)&Ws[k][tx * 8 + 4];
#pragma unroll
            for (int i = 0; i < 8; i++)
#pragma unroll
                for (int j = 0; j < 8; j++)
                    acc[i][j] = fmaf(a[i], bb[j], acc[i][j]);
        }
        __syncthreads();
    }

#pragma unroll
    for (int i = 0; i < 8; i++) {
        int m = m0 + ty * 8 + i;
#pragma unroll
        for (int j = 0; j < 8; j++) {
            int n = n0 + tx * 8 + j;
            if (n < N) {
                float v = acc[i][j];
                if (bias) v += bias[n];
                size_t off = (size_t)m * ldc + n;
                if (flags & 1) v += C[off];
                if (flags & 2) v = fmaxf(expf(v) - 1.0f, 0.0f);
                C[off] = v;
            }
        }
    }
}

// ---- register-weight GRU scan (R8 winner, unchanged) ----
__global__ __launch_bounds__(512) void gru_scan4_kernel(
    const float* __restrict__ xp_a, const float* __restrict__ xp_b,
    const float* __restrict__ W_a,  const float* __restrict__ W_b,
    const float* __restrict__ bh_a, const float* __restrict__ bh_b,
    const float* __restrict__ init_a, const float* __restrict__ init_b,
    float* __restrict__ out, int out_ld, int col_a, int col_b,
    int clip_state, int rev_b)
{
    __shared__ float hc2[2 * 128];
    __shared__ float red[3 * 2 * 4 * 128];

    const int dir = blockIdx.x / S2P;
    const int jb  = blockIdx.x % S2P;
    const float* xp   = dir ? xp_b   : xp_a;
    const float* Whh  = dir ? W_b    : W_a;
    const float* bhh  = dir ? bh_b   : bh_a;
    const float* hini = dir ? init_b : init_a;
    const int colbase = dir ? col_b  : col_a;
    const int rev     = dir ? rev_b  : 0;
    const int b0 = jb * 2;

    const int tid = threadIdx.x;
    const int e  = tid & 127;
    const int kq = tid >> 7;

    float wr[32], wz[32], wn[32];
    {
        const float* r0 = Whh + (size_t)(0 * 128 + e) * 128 + kq * 32;
        const float* r1 = Whh + (size_t)(1 * 128 + e) * 128 + kq * 32;
        const float* r2 = Whh + (size_t)(2 * 128 + e) * 128 + kq * 32;
#pragma unroll
        for (int j4 = 0; j4 < 8; j4++) {
            float4 a = *(const float4*)(r0 + j4 * 4);
            float4 b = *(const float4*)(r1 + j4 * 4);
            float4 c = *(const float4*)(r2 + j4 * 4);
            wr[j4*4+0]=a.x; wr[j4*4+1]=a.y; wr[j4*4+2]=a.z; wr[j4*4+3]=a.w;
            wz[j4*4+0]=b.x; wz[j4*4+1]=b.y; wz[j4*4+2]=b.z; wz[j4*4+3]=b.w;
            wn[j4*4+0]=c.x; wn[j4*4+1]=c.y; wn[j4*4+2]=c.z; wn[j4*4+3]=c.w;
        }
    }
    const float br = bhh[e], bz = bhh[128 + e], bn = bhh[256 + e];

    if (kq < 2) hc2[2 * e + kq] = hini[e];
    __syncthreads();

    const float2* h2 = (const float2*)hc2 + kq * 32;

    for (int s = 0; s < TT; s++) {
        const int t = rev ? (TT - 1 - s) : s;
        float pr = 0.f, pz = 0.f, pn = 0.f;
        if (kq < 2) {
            const float* xr = xp + ((size_t)t * BB + b0 + kq) * 384;
            pr = __ldg(xr + e); pz = __ldg(xr + 128 + e); pn = __ldg(xr + 256 + e);
        }

        float ar0 = 0.f, ar1 = 0.f, az0 = 0.f, az1 = 0.f, an0 = 0.f, an1 = 0.f;
#pragma unroll
        for (int j = 0; j < 32; j++) {
            float2 h = h2[j];
            ar0 = fmaf(wr[j], h.x, ar0); ar1 = fmaf(wr[j], h.y, ar1);
            az0 = fmaf(wz[j], h.x, az0); az1 = fmaf(wz[j], h.y, az1);
            an0 = fmaf(wn[j], h.x, an0); an1 = fmaf(wn[j], h.y, an1);
        }

        red[((0 * 2 + 0) * 4 + kq) * 128 + e] = ar0;
        red[((0 * 2 + 1) * 4 + kq) * 128 + e] = ar1;
        red[((1 * 2 + 0) * 4 + kq) * 128 + e] = az0;
        red[((1 * 2 + 1) * 4 + kq) * 128 + e] = az1;
        red[((2 * 2 + 0) * 4 + kq) * 128 + e] = an0;
        red[((2 * 2 + 1) * 4 + kq) * 128 + e] = an1;
        __syncthreads();

        if (kq < 2) {
            const int b = kq;
            const float* rr = red + ((0 * 2 + b) * 4) * 128 + e;
            const float* rz = red + ((1 * 2 + b) * 4) * 128 + e;
            const float* rn = red + ((2 * 2 + b) * 4) * 128 + e;
            float fr = rr[0] + rr[128] + rr[256] + rr[384];
            float fz = rz[0] + rz[128] + rz[256] + rz[384];
            float fn = rn[0] + rn[128] + rn[256] + rn[384];

            float hp = hc2[2 * e + b];
            float r = sigm(pr + fr + br);
            float z = sigm(pz + fz + bz);
            float n = tanhf(pn + r * (fn + bn));
            float hn = (1.0f - z) * n + z * hp;
            float c  = fminf(fmaxf(hn, -CLIPV), CLIPV);
            if (clip_state) hn = c;

            hc2[2 * e + b] = hn;
            out[((size_t)t * BB + b0 + b) * out_ld + colbase + e] = c;
        }
        __syncthreads();
    }
}

// ---- u = mu + exp(0.5 lv)*eps ; concat factors ----
__global__ void make_uf_kernel(const float* __restrict__ mu, const float* __restrict__ lv,
                               const float* __restrict__ eps, const float* __restrict__ factors,
                               float* __restrict__ uf)
{
    int idx = blockIdx.x * blockDim.x + threadIdx.x;
    if (idx >= MROWS * 68) return;
    int row = idx / 68;
    int c   = idx - row * 68;
    float v;
    if (c < UU) {
        int o = row * UU + c;
        v = mu[o] + expf(0.5f * lv[o]) * eps[o];
    } else {
        v = factors[row * FF + (c - UU)];
    }
    uf[idx] = v;
}

// ---- AR1 calcium ----
__global__ void calcium_kernel(const float* __restrict__ spk,
                               const float* __restrict__ gain,
                               const float* __restrict__ biasp,
                               const float* __restrict__ logtau,
                               float* __restrict__ out)
{
    int idx = blockIdx.x * blockDim.x + threadIdx.x;
    if (idx >= BB * NN) return;
    float decay = 1.0f - 1.0f / expf(logtau[0]);
    float gn = gain[0], bp = biasp[0];
    float c = 0.0f;
    for (int t = 0; t < TT; t++) {
        size_t off = (size_t)t * (BB * NN) + idx;
        c = c * decay + gn * spk[off] + bp;
        out[off] = c;
    }
}

extern "C" void kernel_launch(void* const* d_in, const int* in_sizes, int n_in,
                              void* d_out, int out_size)
{
    const float* x       = (const float*)d_in[0];
    const float* factors = (const float*)d_in[1];
    const float* eps     = (const float*)d_in[2];
    const float* eWihf   = (const float*)d_in[3];
    const float* eWhhf   = (const float*)d_in[4];
    const float* ebihf   = (const float*)d_in[5];
    const float* ebhhf   = (const float*)d_in[6];
    const float* eWihb   = (const float*)d_in[7];
    const float* eWhhb   = (const float*)d_in[8];
    const float* ebihb   = (const float*)d_in[9];
    const float* ebhhb   = (const float*)d_in[10];
    const float* einit   = (const float*)d_in[11];
    const float* cWih    = (const float*)d_in[12];
    const float* cWhh    = (const float*)d_in[13];
    const float* cbih    = (const float*)d_in[14];
    const float* cbhh    = (const float*)d_in[15];
    const float* cinit   = (const float*)d_in[16];
    const float* Wmu     = (const float*)d_in[17];
    const float* bmu     = (const float*)d_in[18];
    const float* Wlv     = (const float*)d_in[19];
    const float* blv     = (const float*)d_in[20];
    const float* Wspk    = (const float*)d_in[21];
    const float* bspk    = (const float*)d_in[22];
    const float* gain    = (const float*)d_in[23];
    const float* biasp   = (const float*)d_in[24];
    const float* logtau  = (const float*)d_in[25];
    float* out = (float*)d_out;

    float *p_xpf, *p_xpb, *p_cp, *p_g, *p_hc, *p_mu, *p_lv, *p_uf, *p_spk;
    __nv_bfloat16 *p_xaug, *p_gaug, *p_wfa, *p_wba, *p_wxa, *p_wga;
    cudaGetSymbolAddress((void**)&p_xpf, d_xpf);
    cudaGetSymbolAddress((void**)&p_xpb, d_xpb);
    cudaGetSymbolAddress((void**)&p_cp,  d_cp);
    cudaGetSymbolAddress((void**)&p_g,   d_g);
    cudaGetSymbolAddress((void**)&p_hc,  d_hc);
    cudaGetSymbolAddress((void**)&p_mu,  d_mu);
    cudaGetSymbolAddress((void**)&p_lv,  d_lv);
    cudaGetSymbolAddress((void**)&p_uf,  d_uf);
    cudaGetSymbolAddress((void**)&p_spk, d_spk);
    cudaGetSymbolAddress((void**)&p_xaug, d_xaug);
    cudaGetSymbolAddress((void**)&p_gaug, d_gaug);
    cudaGetSymbolAddress((void**)&p_wfa, d_wfa);
    cudaGetSymbolAddress((void**)&p_wba, d_wba);
    cudaGetSymbolAddress((void**)&p_wxa, d_wxa);
    cudaGetSymbolAddress((void**)&p_wga, d_wga);

    const int MB = MROWS / 128; // 500
    const int hg_smem = 2 * 24576 * (int)sizeof(__nv_bfloat16);  // 98304 B
    cudaFuncSetAttribute(hgemm_kernel, cudaFuncAttributeMaxDynamicSharedMemorySize, hg_smem);

    // ---- bf16-split conversions ----
    {
        long long na = (long long)MROWS * (KAUG_X / 8);
        aug_kernel<<<(int)((na + 255) / 256), 256>>>(x, NN, NN, MROWS, p_xaug, KAUG_X, 0);
        long long nw = 384LL * (KAUG_X / 8);
        aug_kernel<<<(int)((nw + 255) / 256), 256>>>(eWihf, NN, NN, 384, p_wfa, KAUG_X, 1);
        aug_kernel<<<(int)((nw + 255) / 256), 256>>>(eWihb, NN, NN, 384, p_wba, KAUG_X, 1);
        aug_kernel<<<(int)((nw + 255) / 256), 256>>>(cWih + 2 * EE, 2 * EE + NN, NN, 384, p_wxa, KAUG_X, 1);
        long long ng = 384LL * (KAUG_G / 8);
        aug_kernel<<<(int)((ng + 255) / 256), 256>>>(cWih, 2 * EE + NN, 2 * EE, 384, p_wga, KAUG_G, 1);
    }

    // ---- encoder input projections + controller x-part (bf16-split mma) ----
    hgemm_kernel<<<dim3(3, MB), 256, hg_smem>>>(p_xaug, p_wfa, ebihf, p_xpf, 384, KAUG_X, 0);
    hgemm_kernel<<<dim3(3, MB), 256, hg_smem>>>(p_xaug, p_wba, ebihb, p_xpb, 384, KAUG_X, 0);
    hgemm_kernel<<<dim3(3, MB), 256, hg_smem>>>(p_xaug, p_wxa, cbih,  p_cp,  384, KAUG_X, 0);

    // ---- bidirectional encoder scan ----
    gru_scan4_kernel<<<2 * S2P, 512>>>(
        p_xpf, p_xpb, eWhhf, eWhhb, ebhhf, ebhhb, einit, einit + EE,
        p_g, 256, 0, EE, /*clip_state=*/0, /*rev_b=*/1);

    // ---- controller projection, g part (bf16-split mma, accumulate) ----
    {
        long long ng2 = (long long)MROWS * (KAUG_G / 8);
        aug_kernel<<<(int)((ng2 + 255) / 256), 256>>>(p_g, 256, 256, MROWS, p_gaug, KAUG_G, 0);
    }
    hgemm_kernel<<<dim3(3, MB), 256, hg_smem>>>(p_gaug, p_wga, (const float*)0, p_cp, 384, KAUG_G, 1);

    // ---- controller scan ----
    gru_scan4_kernel<<<S2P, 512>>>(
        p_cp, p_cp, cWhh, cWhh, cbhh, cbhh, cinit, cinit,
        p_hc, 128, 0, 0, /*clip_state=*/1, /*rev_b=*/0);

    // ---- latent heads (fp32) ----
    sgemm_kernel<<<dim3(1, MB), 256>>>(p_hc, 128, Wmu, CC, bmu, p_mu, 64, UU, CC, 0);
    sgemm_kernel<<<dim3(1, MB), 256>>>(p_hc, 128, Wlv, CC, blv, p_lv, 64, UU, CC, 0);

    // ---- sample + concat factors ----
    make_uf_kernel<<<(MROWS * 68 + 255) / 256, 256>>>(p_mu, p_lv, eps, factors, p_uf);

    // ---- spike generator (fp32, fused exp-relu) ----
    sgemm_kernel<<<dim3(3, MB), 256>>>(p_uf, 68, Wspk, UU + FF, bspk, p_spk, 300, NN, UU + FF, 2);

    // ---- AR1 calcium ----
    calcium_kernel<<<(BB * NN + 255) / 256, 256>>>(p_spk, gain, biasp, logtau, out);
}

// round 13
// speedup vs baseline: 3.7098x; 1.0496x over previous
#include <cuda_runtime.h>
#include <cuda_bf16.h>
#include <math.h>
#include <stdint.h>

#define TT 500
#define BB 128
#define NN 300
#define EE 128
#define CC 128
#define UU 64
#define FF 4
#define CLIPV 5.0f
#define S2P 64
#define MROWS (TT*BB)       // 64000
#define KAUG_X 960          // 3 * Kpad(320) for K=300
#define KAUG_G 768          // 3 * Kpad(256) for K=256

// ---- static device scratch ----
__device__ float d_xpall[(size_t)MROWS * 1152];  // [xpf | xpb | cp] per row
__device__ float d_g  [MROWS * 256];
__device__ float d_hc [MROWS * 128];
__device__ float d_ml [MROWS * 128];             // [mu | lv] per row
__device__ float d_uf [MROWS * 68];
__device__ float d_spk[MROWS * 300];
__device__ __nv_bfloat16 d_xaug[(size_t)MROWS * KAUG_X];
__device__ __nv_bfloat16 d_gaug[(size_t)MROWS * KAUG_G];
__device__ __nv_bfloat16 d_wall[(size_t)1152 * KAUG_X];   // [wf | wb | wx] rows
__device__ __nv_bfloat16 d_wga[384 * KAUG_G];
__device__ float d_ball[1152];
__device__ float d_wml[128 * 128];
__device__ float d_bml[128];

__device__ __forceinline__ float sigm(float x) { return 1.0f / (1.0f + expf(-x)); }

// ---- bf16 hi/lo split into augmented row-major matrix ----
// role 0 (A side): segments [hi, hi, lo]; role 1 (B side): [hi, lo, hi]
__global__ void aug_kernel(const float* __restrict__ src, int ld, int K, int rows,
                           __nv_bfloat16* __restrict__ dst, int Kaug, int role)
{
    int groups = Kaug / 8;
    int Kpad = Kaug / 3;
    long long idx = (long long)blockIdx.x * blockDim.x + threadIdx.x;
    if (idx >= (long long)rows * groups) return;
    int row = (int)(idx / groups);
    int j   = (int)(idx - (long long)row * groups);
    int kau0 = j * 8;
    int seg = kau0 / Kpad;
    int kk0 = kau0 - seg * Kpad;
    bool lo = (role == 0) ? (seg == 2) : (seg == 1);
    __nv_bfloat16 vals[8];
#pragma unroll
    for (int i = 0; i < 8; i++) {
        int kk = kk0 + i;
        float v = (kk < K) ? src[(size_t)row * ld + kk] : 0.0f;
        __nv_bfloat16 h = __float2bfloat16(v);
        vals[i] = lo ? __float2bfloat16(v - __bfloat162float(h)) : h;
    }
    *(uint4*)(dst + (size_t)row * Kaug + kau0) = *(uint4*)vals;
}

// ---- build concatenated bias [ebihf|ebihb|cbih], W_ml = [Wmu;Wlv], b_ml ----
__global__ void prep_kernel(const float* __restrict__ bf, const float* __restrict__ bb,
                            const float* __restrict__ bc,
                            const float* __restrict__ Wmu, const float* __restrict__ bmu,
                            const float* __restrict__ Wlv, const float* __restrict__ blv,
                            float* __restrict__ ball, float* __restrict__ wml, float* __restrict__ bml)
{
    int i = blockIdx.x * blockDim.x + threadIdx.x;
    if (i < 384) ball[i] = bf[i];
    else if (i < 768) ball[i] = bb[i - 384];
    else if (i < 1152) ball[i] = bc[i - 768];
    if (i < 128) bml[i] = (i < 64) ? bmu[i] : blv[i - 64];
    if (i < 128 * 128) {
        int r = i >> 7, k = i & 127;
        wml[i] = (r < 64) ? Wmu[r * 128 + k] : Wlv[(r - 64) * 128 + k];
    }
}

// ---- bf16 mma GEMM with cp.async double-buffering + ldmatrix fragments ----
#define MMA16816(d, a, b) \
    asm volatile("mma.sync.aligned.m16n8k16.row.col.f32.bf16.bf16.f32 " \
        "{%0,%1,%2,%3}, {%4,%5,%6,%7}, {%8,%9}, {%0,%1,%2,%3};" \
        : "+f"((d)[0]), "+f"((d)[1]), "+f"((d)[2]), "+f"((d)[3]) \
        : "r"((a)[0]), "r"((a)[1]), "r"((a)[2]), "r"((a)[3]), \
          "r"((b)[0]), "r"((b)[1]))
#define LDSM_X4(r0, r1, r2, r3, addr) \
    asm volatile("ldmatrix.sync.aligned.m8n8.x4.shared.b16 {%0,%1,%2,%3}, [%4];" \
        : "=r"(r0), "=r"(r1), "=r"(r2), "=r"(r3) : "r"(addr))
#define CP_ASYNC16(smem_addr, gptr) \
    asm volatile("cp.async.cg.shared.global [%0], [%1], 16;" :: "r"(smem_addr), "l"(gptr))
#define CP_COMMIT() asm volatile("cp.async.commit_group;")
#define CP_WAIT(N)  asm volatile("cp.async.wait_group %0;" :: "n"(N))

__global__ __launch_bounds__(256) void hgemm_kernel(
    const __nv_bfloat16* __restrict__ A,   // [Mrows][Kaug]
    const __nv_bfloat16* __restrict__ B,   // [N][Kaug]
    const float* __restrict__ bias,
    float* __restrict__ C, int ldc, int Kaug, int flags)
{
    extern __shared__ __nv_bfloat16 smem[];
    const int STAGE = 24576;

    const int tid = threadIdx.x;
    const int lane = tid & 31;
    const int wid = tid >> 5;
    const int warp_m = wid >> 2;
    const int warp_n = wid & 3;
    const int m0 = blockIdx.y * 128;
    const int n0 = blockIdx.x * 128;
    const int lrow = tid >> 1;
    const int lhalf = tid & 1;

    uint32_t sb = (uint32_t)__cvta_generic_to_shared(smem);

    float acc[4][4][4];
#pragma unroll
    for (int mi = 0; mi < 4; mi++)
#pragma unroll
        for (int ni = 0; ni < 4; ni++)
#pragma unroll
            for (int q = 0; q < 4; q++) acc[mi][ni][q] = 0.0f;

    const __nv_bfloat16* Agp = A + (size_t)(m0 + lrow) * Kaug + lhalf * 8;
    const __nv_bfloat16* Bgp = B + (size_t)(n0 + lrow) * Kaug + lhalf * 8;
    const uint32_t sA = sb + (lrow * 24 + lhalf * 8) * 2;
    const uint32_t sB = sb + (12288 + lrow * 24 + lhalf * 8) * 2;

    const int nch = Kaug >> 6;

    const int lr16 = lane & 15;
    const int lh16 = lane >> 4;
    const uint32_t aAddr0 = sb + ((warp_m * 64 + lr16) * 24) * 2 + lh16 * 16;
    const uint32_t bAddr0 = sb + (12288 + (warp_n * 32 + lr16) * 24) * 2 + lh16 * 16;

#pragma unroll
    for (int kk = 0; kk < 4; kk++) {
        CP_ASYNC16(sA + kk * 3072 * 2, Agp + kk * 16);
        CP_ASYNC16(sB + kk * 3072 * 2, Bgp + kk * 16);
    }
    CP_COMMIT();

    for (int ci = 0; ci < nch; ci++) {
        int st = ci & 1;
        if (ci + 1 < nch) {
            int st2 = 1 - st;
            const __nv_bfloat16* Ag2 = Agp + (ci + 1) * 64;
            const __nv_bfloat16* Bg2 = Bgp + (ci + 1) * 64;
#pragma unroll
            for (int kk = 0; kk < 4; kk++) {
                CP_ASYNC16(sA + (st2 * STAGE + kk * 3072) * 2, Ag2 + kk * 16);
                CP_ASYNC16(sB + (st2 * STAGE + kk * 3072) * 2, Bg2 + kk * 16);
            }
            CP_COMMIT();
            CP_WAIT(1);
        } else {
            CP_WAIT(0);
        }
        __syncthreads();

        uint32_t stoff = (uint32_t)(st * STAGE) * 2;
#pragma unroll
        for (int kk = 0; kk < 4; kk++) {
            uint32_t af[4][4];
#pragma unroll
            for (int mi = 0; mi < 4; mi++) {
                uint32_t ad = aAddr0 + stoff + (kk * 3072 + mi * 16 * 24) * 2;
                LDSM_X4(af[mi][0], af[mi][1], af[mi][2], af[mi][3], ad);
            }
            uint32_t bfr[4][2];
#pragma unroll
            for (int np = 0; np < 2; np++) {
                uint32_t r0, r1, r2, r3;
                uint32_t bd = bAddr0 + stoff + (kk * 3072 + np * 16 * 24) * 2;
                LDSM_X4(r0, r1, r2, r3, bd);
                bfr[2 * np][0] = r0; bfr[2 * np + 1][0] = r1;
                bfr[2 * np][1] = r2; bfr[2 * np + 1][1] = r3;
            }
#pragma unroll
            for (int mi = 0; mi < 4; mi++)
#pragma unroll
                for (int ni = 0; ni < 4; ni++)
                    MMA16816(acc[mi][ni], af[mi], bfr[ni]);
        }
        __syncthreads();
    }

    const int gr = lane >> 2;
    const int gc = (lane & 3) * 2;
#pragma unroll
    for (int mi = 0; mi < 4; mi++) {
#pragma unroll
        for (int ni = 0; ni < 4; ni++) {
            const float* a = acc[mi][ni];
            int m = m0 + warp_m * 64 + mi * 16 + gr;
            int n = n0 + warp_n * 32 + ni * 8 + gc;
            float b0 = bias ? bias[n] : 0.0f;
            float b1 = bias ? bias[n + 1] : 0.0f;
#pragma unroll
            for (int h = 0; h < 2; h++) {
                int mm = m + h * 8;
                float v0 = a[h * 2 + 0] + b0;
                float v1 = a[h * 2 + 1] + b1;
                float* Cp = C + (size_t)mm * ldc + n;
                if (flags & 1) {
                    float2 o = *(float2*)Cp;
                    v0 += o.x; v1 += o.y;
                }
                float2 w; w.x = v0; w.y = v1;
                *(float2*)Cp = w;
            }
        }
    }
}

// ---- fp32 SGEMM (ml / spike) ----
__global__ __launch_bounds__(256) void sgemm_kernel(
    const float* __restrict__ A, int lda,
    const float* __restrict__ W, int ldw,
    const float* __restrict__ bias,
    float* __restrict__ C, int ldc,
    int N, int K, int flags)
{
    __shared__ float As[8][128];
    __shared__ float Ws[8][128];
    const int tid = threadIdx.x;
    const int m0 = blockIdx.y * 128;
    const int n0 = blockIdx.x * 128;
    const int lr = tid >> 1;
    const int lc = (tid & 1) << 2;
    const int tx = tid & 15;
    const int ty = tid >> 4;

    float acc[8][8];
#pragma unroll
    for (int i = 0; i < 8; i++)
#pragma unroll
        for (int j = 0; j < 8; j++) acc[i][j] = 0.0f;

    for (int k0 = 0; k0 < K; k0 += 8) {
        {
            float4 v = make_float4(0.f, 0.f, 0.f, 0.f);
            int kbase = k0 + lc;
            int rem = K - kbase;
            const float* Ap = A + (size_t)(m0 + lr) * lda + kbase;
            if (rem >= 4) v = *(const float4*)Ap;
            else if (rem > 0) {
                v.x = Ap[0];
                if (rem > 1) v.y = Ap[1];
                if (rem > 2) v.z = Ap[2];
            }
            As[lc + 0][lr] = v.x; As[lc + 1][lr] = v.y;
            As[lc + 2][lr] = v.z; As[lc + 3][lr] = v.w;
        }
        {
            float4 v = make_float4(0.f, 0.f, 0.f, 0.f);
            int n = n0 + lr;
            int kbase = k0 + lc;
            int rem = K - kbase;
            if (n < N && rem > 0) {
                const float* Wp = W + (size_t)n * ldw + kbase;
                if (rem >= 4) v = *(const float4*)Wp;
                else {
                    v.x = Wp[0];
                    if (rem > 1) v.y = Wp[1];
                    if (rem > 2) v.z = Wp[2];
                }
            }
            Ws[lc + 0][lr] = v.x; Ws[lc + 1][lr] = v.y;
            Ws[lc + 2][lr] = v.z; Ws[lc + 3][lr] = v.w;
        }
        __syncthreads();
#pragma unroll
        for (int k = 0; k < 8; k++) {
            float a[8], bb[8];
            *(float4*)&a[0]  = *(const float4*)&As[k][ty * 8];
            *(float4*)&a[4]  = *(const float4*)&As[k][ty * 8 + 4];
            *(float4*)&bb[0] = *(const float4*)&Ws[k][tx * 8];
            *(float4*)&bb[4] = *(const float4*)&Ws[k][tx * 8 + 4];
#pragma unroll
            for (int i = 0; i < 8; i++)
#pragma unroll
                for (int j = 0; j < 8; j++)
                    acc[i][j] = fmaf(a[i], bb[j], acc[i][j]);
        }
        __syncthreads();
    }

#pragma unroll
    for (int i = 0; i < 8; i++) {
        int m = m0 + ty * 8 + i;
#pragma unroll
        for (int j = 0; j < 8; j++) {
            int n = n0 + tx * 8 + j;
            if (n < N) {
                float v = acc[i][j];
                if (bias) v += bias[n];
                size_t off = (size_t)m * ldc + n;
                if (flags & 1) v += C[off];
                if (flags & 2) v = fmaxf(expf(v) - 1.0f, 0.0f);
                C[off] = v;
            }
        }
    }
}

// ---- register-weight GRU scan, 2 batches/block (encoder: 128 blocks, 2 dirs) ----
__global__ __launch_bounds__(512) void gru_scan4_kernel(
    const float* __restrict__ xp_a, const float* __restrict__ xp_b, int xp_ld,
    const float* __restrict__ W_a,  const float* __restrict__ W_b,
    const float* __restrict__ bh_a, const float* __restrict__ bh_b,
    const float* __restrict__ init_a, const float* __restrict__ init_b,
    float* __restrict__ out, int out_ld, int col_a, int col_b,
    int clip_state, int rev_b)
{
    __shared__ float hc2[2 * 128];
    __shared__ float red[3 * 2 * 4 * 128];

    const int dir = blockIdx.x / S2P;
    const int jb  = blockIdx.x % S2P;
    const float* xp   = dir ? xp_b   : xp_a;
    const float* Whh  = dir ? W_b    : W_a;
    const float* bhh  = dir ? bh_b   : bh_a;
    const float* hini = dir ? init_b : init_a;
    const int colbase = dir ? col_b  : col_a;
    const int rev     = dir ? rev_b  : 0;
    const int b0 = jb * 2;

    const int tid = threadIdx.x;
    const int e  = tid & 127;
    const int kq = tid >> 7;

    float wr[32], wz[32], wn[32];
    {
        const float* r0 = Whh + (size_t)(0 * 128 + e) * 128 + kq * 32;
        const float* r1 = Whh + (size_t)(1 * 128 + e) * 128 + kq * 32;
        const float* r2 = Whh + (size_t)(2 * 128 + e) * 128 + kq * 32;
#pragma unroll
        for (int j4 = 0; j4 < 8; j4++) {
            float4 a = *(const float4*)(r0 + j4 * 4);
            float4 b = *(const float4*)(r1 + j4 * 4);
            float4 c = *(const float4*)(r2 + j4 * 4);
            wr[j4*4+0]=a.x; wr[j4*4+1]=a.y; wr[j4*4+2]=a.z; wr[j4*4+3]=a.w;
            wz[j4*4+0]=b.x; wz[j4*4+1]=b.y; wz[j4*4+2]=b.z; wz[j4*4+3]=b.w;
            wn[j4*4+0]=c.x; wn[j4*4+1]=c.y; wn[j4*4+2]=c.z; wn[j4*4+3]=c.w;
        }
    }
    const float br = bhh[e], bz = bhh[128 + e], bn = bhh[256 + e];

    if (kq < 2) hc2[2 * e + kq] = hini[e];
    __syncthreads();

    const float2* h2 = (const float2*)hc2 + kq * 32;

    for (int s = 0; s < TT; s++) {
        const int t = rev ? (TT - 1 - s) : s;
        float pr = 0.f, pz = 0.f, pn = 0.f;
        if (kq < 2) {
            const float* xr = xp + ((size_t)t * BB + b0 + kq) * xp_ld;
            pr = __ldg(xr + e); pz = __ldg(xr + 128 + e); pn = __ldg(xr + 256 + e);
        }

        float ar0 = 0.f, ar1 = 0.f, az0 = 0.f, az1 = 0.f, an0 = 0.f, an1 = 0.f;
#pragma unroll
        for (int j = 0; j < 32; j++) {
            float2 h = h2[j];
            ar0 = fmaf(wr[j], h.x, ar0); ar1 = fmaf(wr[j], h.y, ar1);
            az0 = fmaf(wz[j], h.x, az0); az1 = fmaf(wz[j], h.y, az1);
            an0 = fmaf(wn[j], h.x, an0); an1 = fmaf(wn[j], h.y, an1);
        }

        red[((0 * 2 + 0) * 4 + kq) * 128 + e] = ar0;
        red[((0 * 2 + 1) * 4 + kq) * 128 + e] = ar1;
        red[((1 * 2 + 0) * 4 + kq) * 128 + e] = az0;
        red[((1 * 2 + 1) * 4 + kq) * 128 + e] = az1;
        red[((2 * 2 + 0) * 4 + kq) * 128 + e] = an0;
        red[((2 * 2 + 1) * 4 + kq) * 128 + e] = an1;
        __syncthreads();

        if (kq < 2) {
            const int b = kq;
            const float* rr = red + ((0 * 2 + b) * 4) * 128 + e;
            const float* rz = red + ((1 * 2 + b) * 4) * 128 + e;
            const float* rn = red + ((2 * 2 + b) * 4) * 128 + e;
            float fr = rr[0] + rr[128] + rr[256] + rr[384];
            float fz = rz[0] + rz[128] + rz[256] + rz[384];
            float fn = rn[0] + rn[128] + rn[256] + rn[384];

            float hp = hc2[2 * e + b];
            float r = sigm(pr + fr + br);
            float z = sigm(pz + fz + bz);
            float n = tanhf(pn + r * (fn + bn));
            float hn = (1.0f - z) * n + z * hp;
            float c  = fminf(fmaxf(hn, -CLIPV), CLIPV);
            if (clip_state) hn = c;

            hc2[2 * e + b] = hn;
            out[((size_t)t * BB + b0 + b) * out_ld + colbase + e] = c;
        }
        __syncthreads();
    }
}

// ---- register-weight GRU scan, 1 batch/block (controller: 128 blocks) ----
__global__ __launch_bounds__(512) void gru_scan1_kernel(
    const float* __restrict__ xp, int xp_ld,
    const float* __restrict__ Whh, const float* __restrict__ bhh,
    const float* __restrict__ hini,
    float* __restrict__ out, int out_ld, int clip_state)
{
    __shared__ float hc[128];
    __shared__ float red[3 * 4 * 128];
    const int b = blockIdx.x;
    const int tid = threadIdx.x;
    const int e = tid & 127;
    const int kq = tid >> 7;

    float wr[32], wz[32], wn[32];
    {
        const float* r0 = Whh + (size_t)(0 * 128 + e) * 128 + kq * 32;
        const float* r1 = Whh + (size_t)(1 * 128 + e) * 128 + kq * 32;
        const float* r2 = Whh + (size_t)(2 * 128 + e) * 128 + kq * 32;
#pragma unroll
        for (int j4 = 0; j4 < 8; j4++) {
            float4 a = *(const float4*)(r0 + j4 * 4);
            float4 bq = *(const float4*)(r1 + j4 * 4);
            float4 c = *(const float4*)(r2 + j4 * 4);
            wr[j4*4+0]=a.x;  wr[j4*4+1]=a.y;  wr[j4*4+2]=a.z;  wr[j4*4+3]=a.w;
            wz[j4*4+0]=bq.x; wz[j4*4+1]=bq.y; wz[j4*4+2]=bq.z; wz[j4*4+3]=bq.w;
            wn[j4*4+0]=c.x;  wn[j4*4+1]=c.y;  wn[j4*4+2]=c.z;  wn[j4*4+3]=c.w;
        }
    }
    const float br = bhh[e], bz = bhh[128 + e], bn = bhh[256 + e];

    if (kq == 0) hc[e] = hini[e];
    __syncthreads();

    const float4* h4 = (const float4*)hc + kq * 8;

    for (int s = 0; s < TT; s++) {
        float pr = 0.f, pz = 0.f, pn = 0.f;
        if (kq == 0) {
            const float* xr = xp + ((size_t)s * BB + b) * xp_ld;
            pr = __ldg(xr + e); pz = __ldg(xr + 128 + e); pn = __ldg(xr + 256 + e);
        }

        float ar = 0.f, az = 0.f, an = 0.f;
#pragma unroll
        for (int j = 0; j < 8; j++) {
            float4 h = h4[j];
            ar = fmaf(wr[j*4+0], h.x, ar); ar = fmaf(wr[j*4+1], h.y, ar);
            ar = fmaf(wr[j*4+2], h.z, ar); ar = fmaf(wr[j*4+3], h.w, ar);
            az = fmaf(wz[j*4+0], h.x, az); az = fmaf(wz[j*4+1], h.y, az);
            az = fmaf(wz[j*4+2], h.z, az); az = fmaf(wz[j*4+3], h.w, az);
            an = fmaf(wn[j*4+0], h.x, an); an = fmaf(wn[j*4+1], h.y, an);
            an = fmaf(wn[j*4+2], h.z, an); an = fmaf(wn[j*4+3], h.w, an);
        }

        red[(0 * 4 + kq) * 128 + e] = ar;
        red[(1 * 4 + kq) * 128 + e] = az;
        red[(2 * 4 + kq) * 128 + e] = an;
        __syncthreads();

        if (kq == 0) {
            const float* rr = red + e;
            const float* rz = red + 4 * 128 + e;
            const float* rn = red + 8 * 128 + e;
            float fr = rr[0] + rr[128] + rr[256] + rr[384];
            float fz = rz[0] + rz[128] + rz[256] + rz[384];
            float fn = rn[0] + rn[128] + rn[256] + rn[384];

            float hp = hc[e];
            float r = sigm(pr + fr + br);
            float z = sigm(pz + fz + bz);
            float n = tanhf(pn + r * (fn + bn));
            float hn = (1.0f - z) * n + z * hp;
            float c  = fminf(fmaxf(hn, -CLIPV), CLIPV);
            if (clip_state) hn = c;

            hc[e] = hn;
            out[((size_t)s * BB + b) * out_ld + e] = c;
        }
        __syncthreads();
    }
}

// ---- u = mu + exp(0.5 lv)*eps ; concat factors (ml = [mu|lv]) ----
__global__ void make_uf_kernel(const float* __restrict__ ml,
                               const float* __restrict__ eps, const float* __restrict__ factors,
                               float* __restrict__ uf)
{
    int idx = blockIdx.x * blockDim.x + threadIdx.x;
    if (idx >= MROWS * 68) return;
    int row = idx / 68;
    int c   = idx - row * 68;
    float v;
    if (c < UU) {
        float mu = ml[(size_t)row * 128 + c];
        float lv = ml[(size_t)row * 128 + 64 + c];
        v = mu + expf(0.5f * lv) * eps[(size_t)row * UU + c];
    } else {
        v = factors[(size_t)row * FF + (c - UU)];
    }
    uf[idx] = v;
}

// ---- AR1 calcium ----
__global__ void calcium_kernel(const float* __restrict__ spk,
                               const float* __restrict__ gain,
                               const float* __restrict__ biasp,
                               const float* __restrict__ logtau,
                               float* __restrict__ out)
{
    int idx = blockIdx.x * blockDim.x + threadIdx.x;
    if (idx >= BB * NN) return;
    float decay = 1.0f - 1.0f / expf(logtau[0]);
    float gn = gain[0], bp = biasp[0];
    float c = 0.0f;
    for (int t = 0; t < TT; t++) {
        size_t off = (size_t)t * (BB * NN) + idx;
        c = c * decay + gn * spk[off] + bp;
        out[off] = c;
    }
}

extern "C" void kernel_launch(void* const* d_in, const int* in_sizes, int n_in,
                              void* d_out, int out_size)
{
    const float* x       = (const float*)d_in[0];
    const float* factors = (const float*)d_in[1];
    const float* eps     = (const float*)d_in[2];
    const float* eWihf   = (const float*)d_in[3];
    const float* eWhhf   = (const float*)d_in[4];
    const float* ebihf   = (const float*)d_in[5];
    const float* ebhhf   = (const float*)d_in[6];
    const float* eWihb   = (const float*)d_in[7];
    const float* eWhhb   = (const float*)d_in[8];
    const float* ebihb   = (const float*)d_in[9];
    const float* ebhhb   = (const float*)d_in[10];
    const float* einit   = (const float*)d_in[11];
    const float* cWih    = (const float*)d_in[12];
    const float* cWhh    = (const float*)d_in[13];
    const float* cbih    = (const float*)d_in[14];
    const float* cbhh    = (const float*)d_in[15];
    const float* cinit   = (const float*)d_in[16];
    const float* Wmu     = (const float*)d_in[17];
    const float* bmu     = (const float*)d_in[18];
    const float* Wlv     = (const float*)d_in[19];
    const float* blv     = (const float*)d_in[20];
    const float* Wspk    = (const float*)d_in[21];
    const float* bspk    = (const float*)d_in[22];
    const float* gain    = (const float*)d_in[23];
    const float* biasp   = (const float*)d_in[24];
    const float* logtau  = (const float*)d_in[25];
    float* out = (float*)d_out;

    float *p_xpall, *p_g, *p_hc, *p_ml, *p_uf, *p_spk, *p_ball, *p_wml, *p_bml;
    __nv_bfloat16 *p_xaug, *p_gaug, *p_wall, *p_wga;
    cudaGetSymbolAddress((void**)&p_xpall, d_xpall);
    cudaGetSymbolAddress((void**)&p_g,   d_g);
    cudaGetSymbolAddress((void**)&p_hc,  d_hc);
    cudaGetSymbolAddress((void**)&p_ml,  d_ml);
    cudaGetSymbolAddress((void**)&p_uf,  d_uf);
    cudaGetSymbolAddress((void**)&p_spk, d_spk);
    cudaGetSymbolAddress((void**)&p_xaug, d_xaug);
    cudaGetSymbolAddress((void**)&p_gaug, d_gaug);
    cudaGetSymbolAddress((void**)&p_wall, d_wall);
    cudaGetSymbolAddress((void**)&p_wga, d_wga);
    cudaGetSymbolAddress((void**)&p_ball, d_ball);
    cudaGetSymbolAddress((void**)&p_wml, d_wml);
    cudaGetSymbolAddress((void**)&p_bml, d_bml);

    const int MB = MROWS / 128; // 500
    const int hg_smem = 2 * 24576 * (int)sizeof(__nv_bfloat16);  // 98304 B
    cudaFuncSetAttribute(hgemm_kernel, cudaFuncAttributeMaxDynamicSharedMemorySize, hg_smem);

    // ---- bf16-split conversions + small prep ----
    {
        long long na = (long long)MROWS * (KAUG_X / 8);
        aug_kernel<<<(int)((na + 255) / 256), 256>>>(x, NN, NN, MROWS, p_xaug, KAUG_X, 0);
        long long nw = 384LL * (KAUG_X / 8);
        aug_kernel<<<(int)((nw + 255) / 256), 256>>>(eWihf, NN, NN, 384, p_wall, KAUG_X, 1);
        aug_kernel<<<(int)((nw + 255) / 256), 256>>>(eWihb, NN, NN, 384, p_wall + (size_t)384 * KAUG_X, KAUG_X, 1);
        aug_kernel<<<(int)((nw + 255) / 256), 256>>>(cWih + 2 * EE, 2 * EE + NN, NN, 384, p_wall + (size_t)768 * KAUG_X, KAUG_X, 1);
        long long ng = 384LL * (KAUG_G / 8);
        aug_kernel<<<(int)((ng + 255) / 256), 256>>>(cWih, 2 * EE + NN, 2 * EE, 384, p_wga, KAUG_G, 1);
        prep_kernel<<<64, 256>>>(ebihf, ebihb, cbih, Wmu, bmu, Wlv, blv, p_ball, p_wml, p_bml);
    }

    // ---- single fused projection GEMM: [xpf | xpb | cp-x] = xaug @ wall^T + ball ----
    hgemm_kernel<<<dim3(9, MB), 256, hg_smem>>>(p_xaug, p_wall, p_ball, p_xpall, 1152, KAUG_X, 0);

    // ---- bidirectional encoder scan ----
    gru_scan4_kernel<<<2 * S2P, 512>>>(
        p_xpall, p_xpall + 384, 1152, eWhhf, eWhhb, ebhhf, ebhhb, einit, einit + EE,
        p_g, 256, 0, EE, /*clip_state=*/0, /*rev_b=*/1);

    // ---- controller projection, g part (accumulate into cp region) ----
    {
        long long ng2 = (long long)MROWS * (KAUG_G / 8);
        aug_kernel<<<(int)((ng2 + 255) / 256), 256>>>(p_g, 256, 256, MROWS, p_gaug, KAUG_G, 0);
    }
    hgemm_kernel<<<dim3(3, MB), 256, hg_smem>>>(p_gaug, p_wga, (const float*)0, p_xpall + 768, 1152, KAUG_G, 1);

    // ---- controller scan: 1 batch/block, 128 blocks ----
    gru_scan1_kernel<<<128, 512>>>(p_xpall + 768, 1152, cWhh, cbhh, cinit,
                                   p_hc, 128, /*clip_state=*/1);

    // ---- fused mu|lv head ----
    sgemm_kernel<<<dim3(1, MB), 256>>>(p_hc, 128, p_wml, 128, p_bml, p_ml, 128, 128, 128, 0);

    // ---- sample + concat factors ----
    make_uf_kernel<<<(MROWS * 68 + 255) / 256, 256>>>(p_ml, eps, factors, p_uf);

    // ---- spike generator (fp32, fused exp-relu) ----
    sgemm_kernel<<<dim3(3, MB), 256>>>(p_uf, 68, Wspk, UU + FF, bspk, p_spk, 300, NN, UU + FF, 2);

    // ---- AR1 calcium ----
    calcium_kernel<<<(BB * NN + 255) / 256, 256>>>(p_spk, gain, biasp, logtau, out);
}

// round 15
// speedup vs baseline: 3.8643x; 1.0416x over previous
#include <cuda_runtime.h>
#include <cuda_bf16.h>
#include <math.h>
#include <stdint.h>

#define TT 500
#define BB 128
#define NN 300
#define EE 128
#define CC 128
#define UU 64
#define FF 4
#define CLIPV 5.0f
#define S2P 64
#define MROWS (TT*BB)       // 64000
#define KAUG_X 960          // 3 * Kpad(320) for K=300
#define KAUG_G 768          // 3 * Kpad(256) for K=256

// ---- static device scratch ----
__device__ float d_xpall[(size_t)MROWS * 1152];  // [xpf | xpb | cp] per row
__device__ float d_hc [MROWS * 128];
__device__ float d_uf [MROWS * 68];
__device__ float d_spk[MROWS * 300];
__device__ __nv_bfloat16 d_xaug[(size_t)MROWS * KAUG_X];
__device__ __nv_bfloat16 d_gaug[(size_t)MROWS * KAUG_G];
__device__ __nv_bfloat16 d_wall[(size_t)1152 * KAUG_X];   // [wf | wb | wx] rows
__device__ __nv_bfloat16 d_wga[384 * KAUG_G];
__device__ float d_ball[1152];
__device__ float d_wml[128 * 128];   // interleaved [mu0,lv0,mu1,lv1,...] rows
__device__ float d_bml[128];

__device__ __forceinline__ float sigm(float x) { return 1.0f / (1.0f + expf(-x)); }

// ================= combined aug + prep launch =================
struct AugJob {
    const float* src; int ld, K, rows;
    __nv_bfloat16* dst; int Kaug, role, blk_start;
};
struct AugParams {
    AugJob job[5];
    int prep_start;
    const float *bf, *bb, *bc, *Wmu, *bmu, *Wlv, *blv;
    float *ball, *wml, *bml;
};

__global__ void aug_all_kernel(AugParams P)
{
    int blk = blockIdx.x;
    if (blk >= P.prep_start) {
        int i = (blk - P.prep_start) * 256 + threadIdx.x;
        if (i < 384) P.ball[i] = P.bf[i];
        else if (i < 768) P.ball[i] = P.bb[i - 384];
        else if (i < 1152) P.ball[i] = P.bc[i - 768];
        if (i < 128) {
            int u = i >> 1, h = i & 1;
            P.bml[i] = h ? P.blv[u] : P.bmu[u];
        }
        if (i < 128 * 128) {
            int r = i >> 7, k = i & 127;
            int u = r >> 1, h = r & 1;
            P.wml[i] = h ? P.Wlv[u * 128 + k] : P.Wmu[u * 128 + k];
        }
        return;
    }
    int j = 0;
    if (blk >= P.job[4].blk_start) j = 4;
    else if (blk >= P.job[3].blk_start) j = 3;
    else if (blk >= P.job[2].blk_start) j = 2;
    else if (blk >= P.job[1].blk_start) j = 1;

    const AugJob J = P.job[j];
    int groups = J.Kaug / 8;
    int Kpad = J.Kaug / 3;
    long long idx = (long long)(blk - J.blk_start) * 256 + threadIdx.x;
    if (idx >= (long long)J.rows * groups) return;
    int row = (int)(idx / groups);
    int jj  = (int)(idx - (long long)row * groups);
    int kau0 = jj * 8;
    int seg = kau0 / Kpad;
    int kk0 = kau0 - seg * Kpad;
    bool lo = (J.role == 0) ? (seg == 2) : (seg == 1);
    __nv_bfloat16 vals[8];
#pragma unroll
    for (int i = 0; i < 8; i++) {
        int kk = kk0 + i;
        float v = (kk < J.K) ? J.src[(size_t)row * J.ld + kk] : 0.0f;
        __nv_bfloat16 h = __float2bfloat16(v);
        vals[i] = lo ? __float2bfloat16(v - __bfloat162float(h)) : h;
    }
    *(uint4*)(J.dst + (size_t)row * J.Kaug + kau0) = *(uint4*)vals;
}

// ---- bf16 mma GEMM with cp.async double-buffering + ldmatrix fragments ----
#define MMA16816(d, a, b) \
    asm volatile("mma.sync.aligned.m16n8k16.row.col.f32.bf16.bf16.f32 " \
        "{%0,%1,%2,%3}, {%4,%5,%6,%7}, {%8,%9}, {%0,%1,%2,%3};" \
        : "+f"((d)[0]), "+f"((d)[1]), "+f"((d)[2]), "+f"((d)[3]) \
        : "r"((a)[0]), "r"((a)[1]), "r"((a)[2]), "r"((a)[3]), \
          "r"((b)[0]), "r"((b)[1]))
#define LDSM_X4(r0, r1, r2, r3, addr) \
    asm volatile("ldmatrix.sync.aligned.m8n8.x4.shared.b16 {%0,%1,%2,%3}, [%4];" \
        : "=r"(r0), "=r"(r1), "=r"(r2), "=r"(r3) : "r"(addr))
#define CP_ASYNC16(smem_addr, gptr) \
    asm volatile("cp.async.cg.shared.global [%0], [%1], 16;" :: "r"(smem_addr), "l"(gptr))
#define CP_COMMIT() asm volatile("cp.async.commit_group;")
#define CP_WAIT(N)  asm volatile("cp.async.wait_group %0;" :: "n"(N))

__global__ __launch_bounds__(256) void hgemm_kernel(
    const __nv_bfloat16* __restrict__ A,
    const __nv_bfloat16* __restrict__ B,
    const float* __restrict__ bias,
    float* __restrict__ C, int ldc, int Kaug, int flags)
{
    extern __shared__ __nv_bfloat16 smem[];
    const int STAGE = 24576;

    const int tid = threadIdx.x;
    const int lane = tid & 31;
    const int wid = tid >> 5;
    const int warp_m = wid >> 2;
    const int warp_n = wid & 3;
    const int m0 = blockIdx.y * 128;
    const int n0 = blockIdx.x * 128;
    const int lrow = tid >> 1;
    const int lhalf = tid & 1;

    uint32_t sb = (uint32_t)__cvta_generic_to_shared(smem);

    float acc[4][4][4];
#pragma unroll
    for (int mi = 0; mi < 4; mi++)
#pragma unroll
        for (int ni = 0; ni < 4; ni++)
#pragma unroll
            for (int q = 0; q < 4; q++) acc[mi][ni][q] = 0.0f;

    const __nv_bfloat16* Agp = A + (size_t)(m0 + lrow) * Kaug + lhalf * 8;
    const __nv_bfloat16* Bgp = B + (size_t)(n0 + lrow) * Kaug + lhalf * 8;
    const uint32_t sA = sb + (lrow * 24 + lhalf * 8) * 2;
    const uint32_t sB = sb + (12288 + lrow * 24 + lhalf * 8) * 2;

    const int nch = Kaug >> 6;

    const int lr16 = lane & 15;
    const int lh16 = lane >> 4;
    const uint32_t aAddr0 = sb + ((warp_m * 64 + lr16) * 24) * 2 + lh16 * 16;
    const uint32_t bAddr0 = sb + (12288 + (warp_n * 32 + lr16) * 24) * 2 + lh16 * 16;

#pragma unroll
    for (int kk = 0; kk < 4; kk++) {
        CP_ASYNC16(sA + kk * 3072 * 2, Agp + kk * 16);
        CP_ASYNC16(sB + kk * 3072 * 2, Bgp + kk * 16);
    }
    CP_COMMIT();

    for (int ci = 0; ci < nch; ci++) {
        int st = ci & 1;
        if (ci + 1 < nch) {
            int st2 = 1 - st;
            const __nv_bfloat16* Ag2 = Agp + (ci + 1) * 64;
            const __nv_bfloat16* Bg2 = Bgp + (ci + 1) * 64;
#pragma unroll
            for (int kk = 0; kk < 4; kk++) {
                CP_ASYNC16(sA + (st2 * STAGE + kk * 3072) * 2, Ag2 + kk * 16);
                CP_ASYNC16(sB + (st2 * STAGE + kk * 3072) * 2, Bg2 + kk * 16);
            }
            CP_COMMIT();
            CP_WAIT(1);
        } else {
            CP_WAIT(0);
        }
        __syncthreads();

        uint32_t stoff = (uint32_t)(st * STAGE) * 2;
#pragma unroll
        for (int kk = 0; kk < 4; kk++) {
            uint32_t af[4][4];
#pragma unroll
            for (int mi = 0; mi < 4; mi++) {
                uint32_t ad = aAddr0 + stoff + (kk * 3072 + mi * 16 * 24) * 2;
                LDSM_X4(af[mi][0], af[mi][1], af[mi][2], af[mi][3], ad);
            }
            uint32_t bfr[4][2];
#pragma unroll
            for (int np = 0; np < 2; np++) {
                uint32_t r0, r1, r2, r3;
                uint32_t bd = bAddr0 + stoff + (kk * 3072 + np * 16 * 24) * 2;
                LDSM_X4(r0, r1, r2, r3, bd);
                bfr[2 * np][0] = r0; bfr[2 * np + 1][0] = r1;
                bfr[2 * np][1] = r2; bfr[2 * np + 1][1] = r3;
            }
#pragma unroll
            for (int mi = 0; mi < 4; mi++)
#pragma unroll
                for (int ni = 0; ni < 4; ni++)
                    MMA16816(acc[mi][ni], af[mi], bfr[ni]);
        }
        __syncthreads();
    }

    const int gr = lane >> 2;
    const int gc = (lane & 3) * 2;
#pragma unroll
    for (int mi = 0; mi < 4; mi++) {
#pragma unroll
        for (int ni = 0; ni < 4; ni++) {
            const float* a = acc[mi][ni];
            int m = m0 + warp_m * 64 + mi * 16 + gr;
            int n = n0 + warp_n * 32 + ni * 8 + gc;
            float b0 = bias ? bias[n] : 0.0f;
            float b1 = bias ? bias[n + 1] : 0.0f;
#pragma unroll
            for (int h = 0; h < 2; h++) {
                int mm = m + h * 8;
                float v0 = a[h * 2 + 0] + b0;
                float v1 = a[h * 2 + 1] + b1;
                float* Cp = C + (size_t)mm * ldc + n;
                if (flags & 1) {
                    float2 o = *(float2*)Cp;
                    v0 += o.x; v1 += o.y;
                }
                float2 w; w.x = v0; w.y = v1;
                *(float2*)Cp = w;
            }
        }
    }
}

// ---- fp32 SGEMM. flags bit1: spike epilogue; bit2: fused mu/lv sampling epilogue ----
__global__ __launch_bounds__(256) void sgemm_kernel(
    const float* __restrict__ A, int lda,
    const float* __restrict__ W, int ldw,
    const float* __restrict__ bias,
    float* __restrict__ C, int ldc,
    int N, int K, int flags,
    const float* __restrict__ eps, const float* __restrict__ factors)
{
    __shared__ float As[8][128];
    __shared__ float Ws[8][128];
    const int tid = threadIdx.x;
    const int m0 = blockIdx.y * 128;
    const int n0 = blockIdx.x * 128;
    const int lr = tid >> 1;
    const int lc = (tid & 1) << 2;
    const int tx = tid & 15;
    const int ty = tid >> 4;

    float acc[8][8];
#pragma unroll
    for (int i = 0; i < 8; i++)
#pragma unroll
        for (int j = 0; j < 8; j++) acc[i][j] = 0.0f;

    for (int k0 = 0; k0 < K; k0 += 8) {
        {
            float4 v = make_float4(0.f, 0.f, 0.f, 0.f);
            int kbase = k0 + lc;
            int rem = K - kbase;
            const float* Ap = A + (size_t)(m0 + lr) * lda + kbase;
            if (rem >= 4) v = *(const float4*)Ap;
            else if (rem > 0) {
                v.x = Ap[0];
                if (rem > 1) v.y = Ap[1];
                if (rem > 2) v.z = Ap[2];
            }
            As[lc + 0][lr] = v.x; As[lc + 1][lr] = v.y;
            As[lc + 2][lr] = v.z; As[lc + 3][lr] = v.w;
        }
        {
            float4 v = make_float4(0.f, 0.f, 0.f, 0.f);
            int n = n0 + lr;
            int kbase = k0 + lc;
            int rem = K - kbase;
            if (n < N && rem > 0) {
                const float* Wp = W + (size_t)n * ldw + kbase;
                if (rem >= 4) v = *(const float4*)Wp;
                else {
                    v.x = Wp[0];
                    if (rem > 1) v.y = Wp[1];
                    if (rem > 2) v.z = Wp[2];
                }
            }
            Ws[lc + 0][lr] = v.x; Ws[lc + 1][lr] = v.y;
            Ws[lc + 2][lr] = v.z; Ws[lc + 3][lr] = v.w;
        }
        __syncthreads();
#pragma unroll
        for (int k = 0; k < 8; k++) {
            float a[8], bb[8];
            *(float4*)&a[0]  = *(const float4*)&As[k][ty * 8];
            *(float4*)&a[4]  = *(const float4*)&As[k][ty * 8 + 4];
            *(float4*)&bb[0] = *(const float4*)&Ws[k][tx * 8];
            *(float4*)&bb[4] = *(const float4*)&Ws[k][tx * 8 + 4];
#pragma unroll
            for (int i = 0; i < 8; i++)
#pragma unroll
                for (int j = 0; j < 8; j++)
                    acc[i][j] = fmaf(a[i], bb[j], acc[i][j]);
        }
        __syncthreads();
    }

    if (flags & 4) {
        // fused mu/lv sampling: W rows interleaved [mu0,lv0,mu1,lv1,...]; C = uf (ld 68)
#pragma unroll
        for (int i = 0; i < 8; i++) {
            int m = m0 + ty * 8 + i;
#pragma unroll
            for (int j = 0; j < 8; j += 2) {
                int n = tx * 8 + j;
                float mu = acc[i][j] + bias[n];
                float lv = acc[i][j + 1] + bias[n + 1];
                int u = n >> 1;
                C[(size_t)m * ldc + u] = mu + expf(0.5f * lv) * eps[(size_t)m * 64 + u];
            }
            if (tx == 15) {
#pragma unroll
                for (int q = 0; q < 4; q++)
                    C[(size_t)m * ldc + 64 + q] = factors[(size_t)m * 4 + q];
            }
        }
        return;
    }

#pragma unroll
    for (int i = 0; i < 8; i++) {
        int m = m0 + ty * 8 + i;
#pragma unroll
        for (int j = 0; j < 8; j++) {
            int n = n0 + tx * 8 + j;
            if (n < N) {
                float v = acc[i][j];
                if (bias) v += bias[n];
                size_t off = (size_t)m * ldc + n;
                if (flags & 1) v += C[off];
                if (flags & 2) v = fmaxf(expf(v) - 1.0f, 0.0f);
                C[off] = v;
            }
        }
    }
}

// ---- encoder GRU scan: 2 batches/block, register weights, xp prefetch,
//      writes gaug (bf16 hi/hi/lo) directly ----
__global__ __launch_bounds__(512) void gru_scan4_kernel(
    const float* __restrict__ xp_a, const float* __restrict__ xp_b, int xp_ld,
    const float* __restrict__ W_a,  const float* __restrict__ W_b,
    const float* __restrict__ bh_a, const float* __restrict__ bh_b,
    const float* __restrict__ init_a, const float* __restrict__ init_b,
    __nv_bfloat16* __restrict__ gaug)
{
    __shared__ float hc2[2 * 128];
    __shared__ float red[3 * 2 * 4 * 128];

    const int dir = blockIdx.x / S2P;
    const int jb  = blockIdx.x % S2P;
    const float* xp   = dir ? xp_b   : xp_a;
    const float* Whh  = dir ? W_b    : W_a;
    const float* bhh  = dir ? bh_b   : bh_a;
    const float* hini = dir ? init_b : init_a;
    const int colbase = dir ? 128 : 0;
    const int rev     = dir;
    const int b0 = jb * 2;

    const int tid = threadIdx.x;
    const int e  = tid & 127;
    const int kq = tid >> 7;

    float wr[32], wz[32], wn[32];
    {
        const float* r0 = Whh + (size_t)(0 * 128 + e) * 128 + kq * 32;
        const float* r1 = Whh + (size_t)(1 * 128 + e) * 128 + kq * 32;
        const float* r2 = Whh + (size_t)(2 * 128 + e) * 128 + kq * 32;
#pragma unroll
        for (int j4 = 0; j4 < 8; j4++) {
            float4 a = *(const float4*)(r0 + j4 * 4);
            float4 b = *(const float4*)(r1 + j4 * 4);
            float4 c = *(const float4*)(r2 + j4 * 4);
            wr[j4*4+0]=a.x; wr[j4*4+1]=a.y; wr[j4*4+2]=a.z; wr[j4*4+3]=a.w;
            wz[j4*4+0]=b.x; wz[j4*4+1]=b.y; wz[j4*4+2]=b.z; wz[j4*4+3]=b.w;
            wn[j4*4+0]=c.x; wn[j4*4+1]=c.y; wn[j4*4+2]=c.z; wn[j4*4+3]=c.w;
        }
    }
    const float br = bhh[e], bz = bhh[128 + e], bn = bhh[256 + e];

    if (kq < 2) hc2[2 * e + kq] = hini[e];
    __syncthreads();

    const float2* h2 = (const float2*)hc2 + kq * 32;

    // prefetch step-0 xp
    float pr = 0.f, pz = 0.f, pn = 0.f;
    if (kq < 2) {
        int t0 = rev ? (TT - 1) : 0;
        const float* xr = xp + ((size_t)t0 * BB + b0 + kq) * xp_ld;
        pr = __ldg(xr + e); pz = __ldg(xr + 128 + e); pn = __ldg(xr + 256 + e);
    }

    for (int s = 0; s < TT; s++) {
        const int t = rev ? (TT - 1 - s) : s;
        float npr = 0.f, npz = 0.f, npn = 0.f;
        if (kq < 2 && s + 1 < TT) {
            int t2 = rev ? (TT - 2 - s) : (s + 1);
            const float* xr = xp + ((size_t)t2 * BB + b0 + kq) * xp_ld;
            npr = __ldg(xr + e); npz = __ldg(xr + 128 + e); npn = __ldg(xr + 256 + e);
        }

        float ar0 = 0.f, ar1 = 0.f, az0 = 0.f, az1 = 0.f, an0 = 0.f, an1 = 0.f;
#pragma unroll
        for (int j = 0; j < 32; j++) {
            float2 h = h2[j];
            ar0 = fmaf(wr[j], h.x, ar0); ar1 = fmaf(wr[j], h.y, ar1);
            az0 = fmaf(wz[j], h.x, az0); az1 = fmaf(wz[j], h.y, az1);
            an0 = fmaf(wn[j], h.x, an0); an1 = fmaf(wn[j], h.y, an1);
        }

        red[((0 * 2 + 0) * 4 + kq) * 128 + e] = ar0;
        red[((0 * 2 + 1) * 4 + kq) * 128 + e] = ar1;
        red[((1 * 2 + 0) * 4 + kq) * 128 + e] = az0;
        red[((1 * 2 + 1) * 4 + kq) * 128 + e] = az1;
        red[((2 * 2 + 0) * 4 + kq) * 128 + e] = an0;
        red[((2 * 2 + 1) * 4 + kq) * 128 + e] = an1;
        __syncthreads();

        if (kq < 2) {
            const int b = kq;
            const float* rr = red + ((0 * 2 + b) * 4) * 128 + e;
            const float* rz = red + ((1 * 2 + b) * 4) * 128 + e;
            const float* rn = red + ((2 * 2 + b) * 4) * 128 + e;
            float fr = rr[0] + rr[128] + rr[256] + rr[384];
            float fz = rz[0] + rz[128] + rz[256] + rz[384];
            float fn = rn[0] + rn[128] + rn[256] + rn[384];

            float hp = hc2[2 * e + b];
            float r = sigm(pr + fr + br);
            float z = sigm(pz + fz + bz);
            float n = tanhf(pn + r * (fn + bn));
            float hn = (1.0f - z) * n + z * hp;
            float c  = fminf(fmaxf(hn, -CLIPV), CLIPV);

            hc2[2 * e + b] = hn;

            // direct bf16 hi/lo split write into gaug [hi | hi | lo]
            size_t rbase = ((size_t)t * BB + b0 + b) * KAUG_G;
            __nv_bfloat16 hi = __float2bfloat16(c);
            __nv_bfloat16 lo = __float2bfloat16(c - __bfloat162float(hi));
            int col = colbase + e;
            gaug[rbase + col] = hi;
            gaug[rbase + 256 + col] = hi;
            gaug[rbase + 512 + col] = lo;
        }
        pr = npr; pz = npz; pn = npn;
        __syncthreads();
    }
}

// ---- controller GRU scan: 1 batch/block, xp prefetch ----
__global__ __launch_bounds__(512) void gru_scan1_kernel(
    const float* __restrict__ xp, int xp_ld,
    const float* __restrict__ Whh, const float* __restrict__ bhh,
    const float* __restrict__ hini,
    float* __restrict__ out, int out_ld)
{
    __shared__ float hc[128];
    __shared__ float red[3 * 4 * 128];
    const int b = blockIdx.x;
    const int tid = threadIdx.x;
    const int e = tid & 127;
    const int kq = tid >> 7;

    float wr[32], wz[32], wn[32];
    {
        const float* r0 = Whh + (size_t)(0 * 128 + e) * 128 + kq * 32;
        const float* r1 = Whh + (size_t)(1 * 128 + e) * 128 + kq * 32;
        const float* r2 = Whh + (size_t)(2 * 128 + e) * 128 + kq * 32;
#pragma unroll
        for (int j4 = 0; j4 < 8; j4++) {
            float4 a = *(const float4*)(r0 + j4 * 4);
            float4 bq = *(const float4*)(r1 + j4 * 4);
            float4 c = *(const float4*)(r2 + j4 * 4);
            wr[j4*4+0]=a.x;  wr[j4*4+1]=a.y;  wr[j4*4+2]=a.z;  wr[j4*4+3]=a.w;
            wz[j4*4+0]=bq.x; wz[j4*4+1]=bq.y; wz[j4*4+2]=bq.z; wz[j4*4+3]=bq.w;
            wn[j4*4+0]=c.x;  wn[j4*4+1]=c.y;  wn[j4*4+2]=c.z;  wn[j4*4+3]=c.w;
        }
    }
    const float br = bhh[e], bz = bhh[128 + e], bn = bhh[256 + e];

    if (kq == 0) hc[e] = hini[e];
    __syncthreads();

    const float4* h4 = (const float4*)hc + kq * 8;

    float pr = 0.f, pz = 0.f, pn = 0.f;
    if (kq == 0) {
        const float* xr = xp + ((size_t)0 * BB + b) * xp_ld;
        pr = __ldg(xr + e); pz = __ldg(xr + 128 + e); pn = __ldg(xr + 256 + e);
    }

    for (int s = 0; s < TT; s++) {
        float npr = 0.f, npz = 0.f, npn = 0.f;
        if (kq == 0 && s + 1 < TT) {
            const float* xr = xp + ((size_t)(s + 1) * BB + b) * xp_ld;
            npr = __ldg(xr + e); npz = __ldg(xr + 128 + e); npn = __ldg(xr + 256 + e);
        }

        float ar = 0.f, az = 0.f, an = 0.f;
#pragma unroll
        for (int j = 0; j < 8; j++) {
            float4 h = h4[j];
            ar = fmaf(wr[j*4+0], h.x, ar); ar = fmaf(wr[j*4+1], h.y, ar);
            ar = fmaf(wr[j*4+2], h.z, ar); ar = fmaf(wr[j*4+3], h.w, ar);
            az = fmaf(wz[j*4+0], h.x, az); az = fmaf(wz[j*4+1], h.y, az);
            az = fmaf(wz[j*4+2], h.z, az); az = fmaf(wz[j*4+3], h.w, az);
            an = fmaf(wn[j*4+0], h.x, an); an = fmaf(wn[j*4+1], h.y, an);
            an = fmaf(wn[j*4+2], h.z, an); an = fmaf(wn[j*4+3], h.w, an);
        }

        red[(0 * 4 + kq) * 128 + e] = ar;
        red[(1 * 4 + kq) * 128 + e] = az;
        red[(2 * 4 + kq) * 128 + e] = an;
        __syncthreads();

        if (kq == 0) {
            const float* rr = red + e;
            const float* rz = red + 4 * 128 + e;
            const float* rn = red + 8 * 128 + e;
            float fr = rr[0] + rr[128] + rr[256] + rr[384];
            float fz = rz[0] + rz[128] + rz[256] + rz[384];
            float fn = rn[0] + rn[128] + rn[256] + rn[384];

            float hp = hc[e];
            float r = sigm(pr + fr + br);
            float z = sigm(pz + fz + bz);
            float n = tanhf(pn + r * (fn + bn));
            float hn = (1.0f - z) * n + z * hp;
            float c  = fminf(fmaxf(hn, -CLIPV), CLIPV);
            hn = c;  // controller state is clipped

            hc[e] = hn;
            out[((size_t)s * BB + b) * out_ld + e] = c;
        }
        pr = npr; pz = npz; pn = npn;
        __syncthreads();
    }
}

// ---- AR1 calcium ----
__global__ void calcium_kernel(const float* __restrict__ spk,
                               const float* __restrict__ gain,
                               const float* __restrict__ biasp,
                               const float* __restrict__ logtau,
                               float* __restrict__ out)
{
    int idx = blockIdx.x * blockDim.x + threadIdx.x;
    if (idx >= BB * NN) return;
    float decay = 1.0f - 1.0f / expf(logtau[0]);
    float gn = gain[0], bp = biasp[0];
    float c = 0.0f;
    for (int t = 0; t < TT; t++) {
        size_t off = (size_t)t * (BB * NN) + idx;
        c = c * decay + gn * spk[off] + bp;
        out[off] = c;
    }
}

extern "C" void kernel_launch(void* const* d_in, const int* in_sizes, int n_in,
                              void* d_out, int out_size)
{
    const float* x       = (const float*)d_in[0];
    const float* factors = (const float*)d_in[1];
    const float* eps     = (const float*)d_in[2];
    const float* eWihf   = (const float*)d_in[3];
    const float* eWhhf   = (const float*)d_in[4];
    const float* ebihf   = (const float*)d_in[5];
    const float* ebhhf   = (const float*)d_in[6];
    const float* eWihb   = (const float*)d_in[7];
    const float* eWhhb   = (const float*)d_in[8];
    const float* ebihb   = (const float*)d_in[9];
    const float* ebhhb   = (const float*)d_in[10];
    const float* einit   = (const float*)d_in[11];
    const float* cWih    = (const float*)d_in[12];
    const float* cWhh    = (const float*)d_in[13];
    const float* cbih    = (const float*)d_in[14];
    const float* cbhh    = (const float*)d_in[15];
    const float* cinit   = (const float*)d_in[16];
    const float* Wmu     = (const float*)d_in[17];
    const float* bmu     = (const float*)d_in[18];
    const float* Wlv     = (const float*)d_in[19];
    const float* blv     = (const float*)d_in[20];
    const float* Wspk    = (const float*)d_in[21];
    const float* bspk    = (const float*)d_in[22];
    const float* gain    = (const float*)d_in[23];
    const float* biasp   = (const float*)d_in[24];
    const float* logtau  = (const float*)d_in[25];
    float* out = (float*)d_out;

    float *p_xpall, *p_hc, *p_uf, *p_spk, *p_ball, *p_wml, *p_bml;
    __nv_bfloat16 *p_xaug, *p_gaug, *p_wall, *p_wga;
    cudaGetSymbolAddress((void**)&p_xpall, d_xpall);
    cudaGetSymbolAddress((void**)&p_hc,  d_hc);
    cudaGetSymbolAddress((void**)&p_uf,  d_uf);
    cudaGetSymbolAddress((void**)&p_spk, d_spk);
    cudaGetSymbolAddress((void**)&p_xaug, d_xaug);
    cudaGetSymbolAddress((void**)&p_gaug, d_gaug);
    cudaGetSymbolAddress((void**)&p_wall, d_wall);
    cudaGetSymbolAddress((void**)&p_wga, d_wga);
    cudaGetSymbolAddress((void**)&p_ball, d_ball);
    cudaGetSymbolAddress((void**)&p_wml, d_wml);
    cudaGetSymbolAddress((void**)&p_bml, d_bml);

    const int MB = MROWS / 128; // 500
    const int hg_smem = 2 * 24576 * (int)sizeof(__nv_bfloat16);  // 98304 B
    cudaFuncSetAttribute(hgemm_kernel, cudaFuncAttributeMaxDynamicSharedMemorySize, hg_smem);

    // ---- single combined aug + prep launch ----
    {
        AugParams P;
        int start = 0;
        // job 0: x -> xaug
        P.job[0] = { x, NN, NN, MROWS, p_xaug, KAUG_X, 0, start };
        start += (int)(((long long)MROWS * (KAUG_X / 8) + 255) / 256);           // 30000
        P.job[1] = { eWihf, NN, NN, 384, p_wall, KAUG_X, 1, start };
        start += (int)((384LL * (KAUG_X / 8) + 255) / 256);                      // 180
        P.job[2] = { eWihb, NN, NN, 384, p_wall + (size_t)384 * KAUG_X, KAUG_X, 1, start };
        start += (int)((384LL * (KAUG_X / 8) + 255) / 256);
        P.job[3] = { cWih + 2 * EE, 2 * EE + NN, NN, 384, p_wall + (size_t)768 * KAUG_X, KAUG_X, 1, start };
        start += (int)((384LL * (KAUG_X / 8) + 255) / 256);
        P.job[4] = { cWih, 2 * EE + NN, 2 * EE, 384, p_wga, KAUG_G, 1, start };
        start += (int)((384LL * (KAUG_G / 8) + 255) / 256);                      // 144
        P.prep_start = start;
        start += 64;
        P.bf = ebihf; P.bb = ebihb; P.bc = cbih;
        P.Wmu = Wmu; P.bmu = bmu; P.Wlv = Wlv; P.blv = blv;
        P.ball = p_ball; P.wml = p_wml; P.bml = p_bml;
        aug_all_kernel<<<start, 256>>>(P);
    }

    // ---- fused projection GEMM: [xpf | xpb | cp-x] = xaug @ wall^T + ball ----
    hgemm_kernel<<<dim3(9, MB), 256, hg_smem>>>(p_xaug, p_wall, p_ball, p_xpall, 1152, KAUG_X, 0);

    // ---- bidirectional encoder scan (writes gaug directly) ----
    gru_scan4_kernel<<<2 * S2P, 512>>>(
        p_xpall, p_xpall + 384, 1152, eWhhf, eWhhb, ebhhf, ebhhb, einit, einit + EE,
        p_gaug);

    // ---- controller projection, g part (accumulate into cp region) ----
    hgemm_kernel<<<dim3(3, MB), 256, hg_smem>>>(p_gaug, p_wga, (const float*)0, p_xpall + 768, 1152, KAUG_G, 1);

    // ---- controller scan ----
    gru_scan1_kernel<<<128, 512>>>(p_xpall + 768, 1152, cWhh, cbhh, cinit, p_hc, 128);

    // ---- fused mu/lv + sampling -> uf ----
    sgemm_kernel<<<dim3(1, MB), 256>>>(p_hc, 128, p_wml, 128, p_bml, p_uf, 68, 128, 128, 4, eps, factors);

    // ---- spike generator (fp32, fused exp-relu) ----
    sgemm_kernel<<<dim3(3, MB), 256>>>(p_uf, 68, Wspk, UU + FF, bspk, p_spk, 300, NN, UU + FF, 2,
                                       (const float*)0, (const float*)0);

    // ---- AR1 calcium ----
    calcium_kernel<<<(BB * NN + 255) / 256, 256>>>(p_spk, gain, biasp, logtau, out);
}

// round 16
// speedup vs baseline: 4.3096x; 1.1152x over previous
#include <cuda_runtime.h>
#include <cuda_bf16.h>
#include <math.h>
#include <stdint.h>

#define TT 500
#define BB 128
#define NN 300
#define EE 128
#define CC 128
#define UU 64
#define FF 4
#define CLIPV 5.0f
#define S2P 64
#define MROWS (TT*BB)       // 64000
#define KAUG_X 640          // [hi|lo], Kpad=320 for K=300
#define KAUG_G 512          // [hi|lo], Kpad=256 for K=256

// ---- static device scratch ----
__device__ float d_xpall[(size_t)MROWS * 1152];  // [xpf | xpb | cp] per row
__device__ float d_hc [MROWS * 128];
__device__ float d_uf [MROWS * 68];
__device__ float d_spk[MROWS * 300];
__device__ __nv_bfloat16 d_xaug[(size_t)MROWS * KAUG_X];
__device__ __nv_bfloat16 d_gaug[(size_t)MROWS * KAUG_G];
__device__ __nv_bfloat16 d_wall[(size_t)1152 * KAUG_X];   // [wf | wb | wx] rows
__device__ __nv_bfloat16 d_wga[384 * KAUG_G];
__device__ float d_ball[1152];
__device__ float d_wml[128 * 128];   // interleaved [mu0,lv0,...] rows
__device__ float d_bml[128];

__device__ __forceinline__ float sigm(float x) { return 1.0f / (1.0f + expf(-x)); }

// ================= combined aug + prep launch =================
// layout both operands: [hi(Kpad) | lo(Kpad)], Kaug = 2*Kpad
struct AugJob {
    const float* src; int ld, K, rows;
    __nv_bfloat16* dst; int Kaug, blk_start;
};
struct AugParams {
    AugJob job[5];
    int prep_start;
    const float *bf, *bb, *bc, *Wmu, *bmu, *Wlv, *blv;
    float *ball, *wml, *bml;
};

__global__ void aug_all_kernel(AugParams P)
{
    int blk = blockIdx.x;
    if (blk >= P.prep_start) {
        int i = (blk - P.prep_start) * 256 + threadIdx.x;
        if (i < 384) P.ball[i] = P.bf[i];
        else if (i < 768) P.ball[i] = P.bb[i - 384];
        else if (i < 1152) P.ball[i] = P.bc[i - 768];
        if (i < 128) {
            int u = i >> 1, h = i & 1;
            P.bml[i] = h ? P.blv[u] : P.bmu[u];
        }
        if (i < 128 * 128) {
            int r = i >> 7, k = i & 127;
            int u = r >> 1, h = r & 1;
            P.wml[i] = h ? P.Wlv[u * 128 + k] : P.Wmu[u * 128 + k];
        }
        return;
    }
    int j = 0;
    if (blk >= P.job[4].blk_start) j = 4;
    else if (blk >= P.job[3].blk_start) j = 3;
    else if (blk >= P.job[2].blk_start) j = 2;
    else if (blk >= P.job[1].blk_start) j = 1;

    const AugJob J = P.job[j];
    int groups = J.Kaug / 8;
    int Kpad = J.Kaug / 2;
    long long idx = (long long)(blk - J.blk_start) * 256 + threadIdx.x;
    if (idx >= (long long)J.rows * groups) return;
    int row = (int)(idx / groups);
    int jj  = (int)(idx - (long long)row * groups);
    int kau0 = jj * 8;
    int seg = kau0 / Kpad;
    int kk0 = kau0 - seg * Kpad;
    bool lo = (seg == 1);
    __nv_bfloat16 vals[8];
#pragma unroll
    for (int i = 0; i < 8; i++) {
        int kk = kk0 + i;
        float v = (kk < J.K) ? J.src[(size_t)row * J.ld + kk] : 0.0f;
        __nv_bfloat16 h = __float2bfloat16(v);
        vals[i] = lo ? __float2bfloat16(v - __bfloat162float(h)) : h;
    }
    *(uint4*)(J.dst + (size_t)row * J.Kaug + kau0) = *(uint4*)vals;
}

// ---- 3-product bf16 mma GEMM: C = Ahi·Bhi + Ahi·Blo + Alo·Bhi (+bias) ----
#define MMA16816(d, a, b) \
    asm volatile("mma.sync.aligned.m16n8k16.row.col.f32.bf16.bf16.f32 " \
        "{%0,%1,%2,%3}, {%4,%5,%6,%7}, {%8,%9}, {%0,%1,%2,%3};" \
        : "+f"((d)[0]), "+f"((d)[1]), "+f"((d)[2]), "+f"((d)[3]) \
        : "r"((a)[0]), "r"((a)[1]), "r"((a)[2]), "r"((a)[3]), \
          "r"((b)[0]), "r"((b)[1]))
#define LDSM_X4(r0, r1, r2, r3, addr) \
    asm volatile("ldmatrix.sync.aligned.m8n8.x4.shared.b16 {%0,%1,%2,%3}, [%4];" \
        : "=r"(r0), "=r"(r1), "=r"(r2), "=r"(r3) : "r"(addr))
#define CP_ASYNC16(smem_addr, gptr) \
    asm volatile("cp.async.cg.shared.global [%0], [%1], 16;" :: "r"(smem_addr), "l"(gptr))
#define CP_COMMIT() asm volatile("cp.async.commit_group;")
#define CP_WAIT(N)  asm volatile("cp.async.wait_group %0;" :: "n"(N))

// stage: 4 tiles {Ahi, Alo, Bhi, Blo}, each 2 kk-subtiles x [128 rows][24 stride]
// tile = 6144 elems; stage = 24576 elems (49KB); 2 stages -> 2 blocks/SM
__global__ __launch_bounds__(256, 2) void hgemm_kernel(
    const __nv_bfloat16* __restrict__ A,   // [Mrows][Kaug]  [hi|lo]
    const __nv_bfloat16* __restrict__ B,   // [N][Kaug]      [hi|lo]
    const float* __restrict__ bias,
    float* __restrict__ C, int ldc, int Kaug, int flags)
{
    extern __shared__ __nv_bfloat16 smem[];
    const int STAGE = 24576;
    const int TILE = 6144;

    const int tid = threadIdx.x;
    const int lane = tid & 31;
    const int wid = tid >> 5;
    const int warp_m = wid >> 2;
    const int warp_n = wid & 3;
    const int m0 = blockIdx.y * 128;
    const int n0 = blockIdx.x * 128;
    const int lrow = tid >> 1;
    const int lhalf = tid & 1;
    const int Kpad = Kaug >> 1;
    const int nch = Kpad >> 5;          // 32 k-cols per chunk

    uint32_t sb = (uint32_t)__cvta_generic_to_shared(smem);

    float acc[4][4][4];
#pragma unroll
    for (int mi = 0; mi < 4; mi++)
#pragma unroll
        for (int ni = 0; ni < 4; ni++)
#pragma unroll
            for (int q = 0; q < 4; q++) acc[mi][ni][q] = 0.0f;

    const __nv_bfloat16* Agp = A + (size_t)(m0 + lrow) * Kaug + lhalf * 8;
    const __nv_bfloat16* Bgp = B + (size_t)(n0 + lrow) * Kaug + lhalf * 8;
    const uint32_t sW = sb + (lrow * 24 + lhalf * 8) * 2;   // within-tile write addr

    const int lr16 = lane & 15;
    const int lh16 = lane >> 4;
    const uint32_t aRd0 = sb + ((warp_m * 64 + lr16) * 24) * 2 + lh16 * 16;
    const uint32_t bRd0 = sb + ((warp_n * 32 + lr16) * 24) * 2 + lh16 * 16;

    // prefetch chunk 0 -> stage 0
#pragma unroll
    for (int kk = 0; kk < 2; kk++) {
        int kg = kk * 16;
        CP_ASYNC16(sW + (0 * TILE + kk * 3072) * 2, Agp + kg);             // A hi
        CP_ASYNC16(sW + (1 * TILE + kk * 3072) * 2, Agp + Kpad + kg);      // A lo
        CP_ASYNC16(sW + (2 * TILE + kk * 3072) * 2, Bgp + kg);             // B hi
        CP_ASYNC16(sW + (3 * TILE + kk * 3072) * 2, Bgp + Kpad + kg);      // B lo
    }
    CP_COMMIT();

    for (int ci = 0; ci < nch; ci++) {
        int st = ci & 1;
        if (ci + 1 < nch) {
            int st2 = 1 - st;
            int kb = (ci + 1) * 32;
#pragma unroll
            for (int kk = 0; kk < 2; kk++) {
                int kg = kb + kk * 16;
                CP_ASYNC16(sW + (st2 * STAGE + 0 * TILE + kk * 3072) * 2, Agp + kg);
                CP_ASYNC16(sW + (st2 * STAGE + 1 * TILE + kk * 3072) * 2, Agp + Kpad + kg);
                CP_ASYNC16(sW + (st2 * STAGE + 2 * TILE + kk * 3072) * 2, Bgp + kg);
                CP_ASYNC16(sW + (st2 * STAGE + 3 * TILE + kk * 3072) * 2, Bgp + Kpad + kg);
            }
            CP_COMMIT();
            CP_WAIT(1);
        } else {
            CP_WAIT(0);
        }
        __syncthreads();

        uint32_t stoff = (uint32_t)(st * STAGE) * 2;
#pragma unroll
        for (int kk = 0; kk < 2; kk++) {
            uint32_t afh[4][4], afl[4][4];
#pragma unroll
            for (int mi = 0; mi < 4; mi++) {
                uint32_t ad = aRd0 + stoff + (0 * TILE + kk * 3072 + mi * 16 * 24) * 2;
                LDSM_X4(afh[mi][0], afh[mi][1], afh[mi][2], afh[mi][3], ad);
                uint32_t al = aRd0 + stoff + (1 * TILE + kk * 3072 + mi * 16 * 24) * 2;
                LDSM_X4(afl[mi][0], afl[mi][1], afl[mi][2], afl[mi][3], al);
            }
            uint32_t bfh[4][2], bfl[4][2];
#pragma unroll
            for (int np = 0; np < 2; np++) {
                uint32_t r0, r1, r2, r3;
                uint32_t bd = bRd0 + stoff + (2 * TILE + kk * 3072 + np * 16 * 24) * 2;
                LDSM_X4(r0, r1, r2, r3, bd);
                bfh[2 * np][0] = r0; bfh[2 * np + 1][0] = r1;
                bfh[2 * np][1] = r2; bfh[2 * np + 1][1] = r3;
                uint32_t bl = bRd0 + stoff + (3 * TILE + kk * 3072 + np * 16 * 24) * 2;
                LDSM_X4(r0, r1, r2, r3, bl);
                bfl[2 * np][0] = r0; bfl[2 * np + 1][0] = r1;
                bfl[2 * np][1] = r2; bfl[2 * np + 1][1] = r3;
            }
#pragma unroll
            for (int mi = 0; mi < 4; mi++)
#pragma unroll
                for (int ni = 0; ni < 4; ni++) {
                    MMA16816(acc[mi][ni], afh[mi], bfh[ni]);
                    MMA16816(acc[mi][ni], afh[mi], bfl[ni]);
                    MMA16816(acc[mi][ni], afl[mi], bfh[ni]);
                }
        }
        __syncthreads();
    }

    const int gr = lane >> 2;
    const int gc = (lane & 3) * 2;
#pragma unroll
    for (int mi = 0; mi < 4; mi++) {
#pragma unroll
        for (int ni = 0; ni < 4; ni++) {
            const float* a = acc[mi][ni];
            int m = m0 + warp_m * 64 + mi * 16 + gr;
            int n = n0 + warp_n * 32 + ni * 8 + gc;
            float b0 = bias ? bias[n] : 0.0f;
            float b1 = bias ? bias[n + 1] : 0.0f;
#pragma unroll
            for (int h = 0; h < 2; h++) {
                int mm = m + h * 8;
                float v0 = a[h * 2 + 0] + b0;
                float v1 = a[h * 2 + 1] + b1;
                float* Cp = C + (size_t)mm * ldc + n;
                if (flags & 1) {
                    float2 o = *(float2*)Cp;
                    v0 += o.x; v1 += o.y;
                }
                float2 w; w.x = v0; w.y = v1;
                *(float2*)Cp = w;
            }
        }
    }
}

// ---- fp32 SGEMM. flags bit1: spike epilogue; bit2: fused mu/lv sampling epilogue ----
__global__ __launch_bounds__(256) void sgemm_kernel(
    const float* __restrict__ A, int lda,
    const float* __restrict__ W, int ldw,
    const float* __restrict__ bias,
    float* __restrict__ C, int ldc,
    int N, int K, int flags,
    const float* __restrict__ eps, const float* __restrict__ factors)
{
    __shared__ float As[8][128];
    __shared__ float Ws[8][128];
    const int tid = threadIdx.x;
    const int m0 = blockIdx.y * 128;
    const int n0 = blockIdx.x * 128;
    const int lr = tid >> 1;
    const int lc = (tid & 1) << 2;
    const int tx = tid & 15;
    const int ty = tid >> 4;

    float acc[8][8];
#pragma unroll
    for (int i = 0; i < 8; i++)
#pragma unroll
        for (int j = 0; j < 8; j++) acc[i][j] = 0.0f;

    for (int k0 = 0; k0 < K; k0 += 8) {
        {
            float4 v = make_float4(0.f, 0.f, 0.f, 0.f);
            int kbase = k0 + lc;
            int rem = K - kbase;
            const float* Ap = A + (size_t)(m0 + lr) * lda + kbase;
            if (rem >= 4) v = *(const float4*)Ap;
            else if (rem > 0) {
                v.x = Ap[0];
                if (rem > 1) v.y = Ap[1];
                if (rem > 2) v.z = Ap[2];
            }
            As[lc + 0][lr] = v.x; As[lc + 1][lr] = v.y;
            As[lc + 2][lr] = v.z; As[lc + 3][lr] = v.w;
        }
        {
            float4 v = make_float4(0.f, 0.f, 0.f, 0.f);
            int n = n0 + lr;
            int kbase = k0 + lc;
            int rem = K - kbase;
            if (n < N && rem > 0) {
                const float* Wp = W + (size_t)n * ldw + kbase;
                if (rem >= 4) v = *(const float4*)Wp;
                else {
                    v.x = Wp[0];
                    if (rem > 1) v.y = Wp[1];
                    if (rem > 2) v.z = Wp[2];
                }
            }
            Ws[lc + 0][lr] = v.x; Ws[lc + 1][lr] = v.y;
            Ws[lc + 2][lr] = v.z; Ws[lc + 3][lr] = v.w;
        }
        __syncthreads();
#pragma unroll
        for (int k = 0; k < 8; k++) {
            float a[8], bb[8];
            *(float4*)&a[0]  = *(const float4*)&As[k][ty * 8];
            *(float4*)&a[4]  = *(const float4*)&As[k][ty * 8 + 4];
            *(float4*)&bb[0] = *(const float4*)&Ws[k][tx * 8];
            *(float4*)&bb[4] = *(const float4*)&Ws[k][tx * 8 + 4];
#pragma unroll
            for (int i = 0; i < 8; i++)
#pragma unroll
                for (int j = 0; j < 8; j++)
                    acc[i][j] = fmaf(a[i], bb[j], acc[i][j]);
        }
        __syncthreads();
    }

    if (flags & 4) {
#pragma unroll
        for (int i = 0; i < 8; i++) {
            int m = m0 + ty * 8 + i;
#pragma unroll
            for (int j = 0; j < 8; j += 2) {
                int n = tx * 8 + j;
                float mu = acc[i][j] + bias[n];
                float lv = acc[i][j + 1] + bias[n + 1];
                int u = n >> 1;
                C[(size_t)m * ldc + u] = mu + expf(0.5f * lv) * eps[(size_t)m * 64 + u];
            }
            if (tx == 15) {
#pragma unroll
                for (int q = 0; q < 4; q++)
                    C[(size_t)m * ldc + 64 + q] = factors[(size_t)m * 4 + q];
            }
        }
        return;
    }

#pragma unroll
    for (int i = 0; i < 8; i++) {
        int m = m0 + ty * 8 + i;
#pragma unroll
        for (int j = 0; j < 8; j++) {
            int n = n0 + tx * 8 + j;
            if (n < N) {
                float v = acc[i][j];
                if (bias) v += bias[n];
                size_t off = (size_t)m * ldc + n;
                if (flags & 1) v += C[off];
                if (flags & 2) v = fmaxf(expf(v) - 1.0f, 0.0f);
                C[off] = v;
            }
        }
    }
}

// ---- encoder GRU scan: 2 batches/block, register weights, xp prefetch,
//      writes gaug (bf16 [hi|lo], Kaug=512) directly ----
__global__ __launch_bounds__(512) void gru_scan4_kernel(
    const float* __restrict__ xp_a, const float* __restrict__ xp_b, int xp_ld,
    const float* __restrict__ W_a,  const float* __restrict__ W_b,
    const float* __restrict__ bh_a, const float* __restrict__ bh_b,
    const float* __restrict__ init_a, const float* __restrict__ init_b,
    __nv_bfloat16* __restrict__ gaug)
{
    __shared__ float hc2[2 * 128];
    __shared__ float red[3 * 2 * 4 * 128];

    const int dir = blockIdx.x / S2P;
    const int jb  = blockIdx.x % S2P;
    const float* xp   = dir ? xp_b   : xp_a;
    const float* Whh  = dir ? W_b    : W_a;
    const float* bhh  = dir ? bh_b   : bh_a;
    const float* hini = dir ? init_b : init_a;
    const int colbase = dir ? 128 : 0;
    const int rev     = dir;
    const int b0 = jb * 2;

    const int tid = threadIdx.x;
    const int e  = tid & 127;
    const int kq = tid >> 7;

    float wr[32], wz[32], wn[32];
    {
        const float* r0 = Whh + (size_t)(0 * 128 + e) * 128 + kq * 32;
        const float* r1 = Whh + (size_t)(1 * 128 + e) * 128 + kq * 32;
        const float* r2 = Whh + (size_t)(2 * 128 + e) * 128 + kq * 32;
#pragma unroll
        for (int j4 = 0; j4 < 8; j4++) {
            float4 a = *(const float4*)(r0 + j4 * 4);
            float4 b = *(const float4*)(r1 + j4 * 4);
            float4 c = *(const float4*)(r2 + j4 * 4);
            wr[j4*4+0]=a.x; wr[j4*4+1]=a.y; wr[j4*4+2]=a.z; wr[j4*4+3]=a.w;
            wz[j4*4+0]=b.x; wz[j4*4+1]=b.y; wz[j4*4+2]=b.z; wz[j4*4+3]=b.w;
            wn[j4*4+0]=c.x; wn[j4*4+1]=c.y; wn[j4*4+2]=c.z; wn[j4*4+3]=c.w;
        }
    }
    const float br = bhh[e], bz = bhh[128 + e], bn = bhh[256 + e];

    if (kq < 2) hc2[2 * e + kq] = hini[e];
    __syncthreads();

    const float2* h2 = (const float2*)hc2 + kq * 32;

    float pr = 0.f, pz = 0.f, pn = 0.f;
    if (kq < 2) {
        int t0 = rev ? (TT - 1) : 0;
        const float* xr = xp + ((size_t)t0 * BB + b0 + kq) * xp_ld;
        pr = __ldg(xr + e); pz = __ldg(xr + 128 + e); pn = __ldg(xr + 256 + e);
    }

    for (int s = 0; s < TT; s++) {
        const int t = rev ? (TT - 1 - s) : s;
        float npr = 0.f, npz = 0.f, npn = 0.f;
        if (kq < 2 && s + 1 < TT) {
            int t2 = rev ? (TT - 2 - s) : (s + 1);
            const float* xr = xp + ((size_t)t2 * BB + b0 + kq) * xp_ld;
            npr = __ldg(xr + e); npz = __ldg(xr + 128 + e); npn = __ldg(xr + 256 + e);
        }

        float ar0 = 0.f, ar1 = 0.f, az0 = 0.f, az1 = 0.f, an0 = 0.f, an1 = 0.f;
#pragma unroll
        for (int j = 0; j < 32; j++) {
            float2 h = h2[j];
            ar0 = fmaf(wr[j], h.x, ar0); ar1 = fmaf(wr[j], h.y, ar1);
            az0 = fmaf(wz[j], h.x, az0); az1 = fmaf(wz[j], h.y, az1);
            an0 = fmaf(wn[j], h.x, an0); an1 = fmaf(wn[j], h.y, an1);
        }

        red[((0 * 2 + 0) * 4 + kq) * 128 + e] = ar0;
        red[((0 * 2 + 1) * 4 + kq) * 128 + e] = ar1;
        red[((1 * 2 + 0) * 4 + kq) * 128 + e] = az0;
        red[((1 * 2 + 1) * 4 + kq) * 128 + e] = az1;
        red[((2 * 2 + 0) * 4 + kq) * 128 + e] = an0;
        red[((2 * 2 + 1) * 4 + kq) * 128 + e] = an1;
        __syncthreads();

        if (kq < 2) {
            const int b = kq;
            const float* rr = red + ((0 * 2 + b) * 4) * 128 + e;
            const float* rz = red + ((1 * 2 + b) * 4) * 128 + e;
            const float* rn = red + ((2 * 2 + b) * 4) * 128 + e;
            float fr = rr[0] + rr[128] + rr[256] + rr[384];
            float fz = rz[0] + rz[128] + rz[256] + rz[384];
            float fn = rn[0] + rn[128] + rn[256] + rn[384];

            float hp = hc2[2 * e + b];
            float r = sigm(pr + fr + br);
            float z = sigm(pz + fz + bz);
            float n = tanhf(pn + r * (fn + bn));
            float hn = (1.0f - z) * n + z * hp;
            float c  = fminf(fmaxf(hn, -CLIPV), CLIPV);

            hc2[2 * e + b] = hn;

            // bf16 [hi|lo] split write into gaug (Kaug=512)
            size_t rbase = ((size_t)t * BB + b0 + b) * KAUG_G;
            __nv_bfloat16 hi = __float2bfloat16(c);
            __nv_bfloat16 lo = __float2bfloat16(c - __bfloat162float(hi));
            int col = colbase + e;
            gaug[rbase + col] = hi;
            gaug[rbase + 256 + col] = lo;
        }
        pr = npr; pz = npz; pn = npn;
        __syncthreads();
    }
}

// ---- controller GRU scan: 1 batch/block, xp prefetch ----
__global__ __launch_bounds__(512) void gru_scan1_kernel(
    const float* __restrict__ xp, int xp_ld,
    const float* __restrict__ Whh, const float* __restrict__ bhh,
    const float* __restrict__ hini,
    float* __restrict__ out, int out_ld)
{
    __shared__ float hc[128];
    __shared__ float red[3 * 4 * 128];
    const int b = blockIdx.x;
    const int tid = threadIdx.x;
    const int e = tid & 127;
    const int kq = tid >> 7;

    float wr[32], wz[32], wn[32];
    {
        const float* r0 = Whh + (size_t)(0 * 128 + e) * 128 + kq * 32;
        const float* r1 = Whh + (size_t)(1 * 128 + e) * 128 + kq * 32;
        const float* r2 = Whh + (size_t)(2 * 128 + e) * 128 + kq * 32;
#pragma unroll
        for (int j4 = 0; j4 < 8; j4++) {
            float4 a = *(const float4*)(r0 + j4 * 4);
            float4 bq = *(const float4*)(r1 + j4 * 4);
            float4 c = *(const float4*)(r2 + j4 * 4);
            wr[j4*4+0]=a.x;  wr[j4*4+1]=a.y;  wr[j4*4+2]=a.z;  wr[j4*4+3]=a.w;
            wz[j4*4+0]=bq.x; wz[j4*4+1]=bq.y; wz[j4*4+2]=bq.z; wz[j4*4+3]=bq.w;
            wn[j4*4+0]=c.x;  wn[j4*4+1]=c.y;  wn[j4*4+2]=c.z;  wn[j4*4+3]=c.w;
        }
    }
    const float br = bhh[e], bz = bhh[128 + e], bn = bhh[256 + e];

    if (kq == 0) hc[e] = hini[e];
    __syncthreads();

    const float4* h4 = (const float4*)hc + kq * 8;

    float pr = 0.f, pz = 0.f, pn = 0.f;
    if (kq == 0) {
        const float* xr = xp + ((size_t)0 * BB + b) * xp_ld;
        pr = __ldg(xr + e); pz = __ldg(xr + 128 + e); pn = __ldg(xr + 256 + e);
    }

    for (int s = 0; s < TT; s++) {
        float npr = 0.f, npz = 0.f, npn = 0.f;
        if (kq == 0 && s + 1 < TT) {
            const float* xr = xp + ((size_t)(s + 1) * BB + b) * xp_ld;
            npr = __ldg(xr + e); npz = __ldg(xr + 128 + e); npn = __ldg(xr + 256 + e);
        }

        float ar = 0.f, az = 0.f, an = 0.f;
#pragma unroll
        for (int j = 0; j < 8; j++) {
            float4 h = h4[j];
            ar = fmaf(wr[j*4+0], h.x, ar); ar = fmaf(wr[j*4+1], h.y, ar);
            ar = fmaf(wr[j*4+2], h.z, ar); ar = fmaf(wr[j*4+3], h.w, ar);
            az = fmaf(wz[j*4+0], h.x, az); az = fmaf(wz[j*4+1], h.y, az);
            az = fmaf(wz[j*4+2], h.z, az); az = fmaf(wz[j*4+3], h.w, az);
            an = fmaf(wn[j*4+0], h.x, an); an = fmaf(wn[j*4+1], h.y, an);
            an = fmaf(wn[j*4+2], h.z, an); an = fmaf(wn[j*4+3], h.w, an);
        }

        red[(0 * 4 + kq) * 128 + e] = ar;
        red[(1 * 4 + kq) * 128 + e] = az;
        red[(2 * 4 + kq) * 128 + e] = an;
        __syncthreads();

        if (kq == 0) {
            const float* rr = red + e;
            const float* rz = red + 4 * 128 + e;
            const float* rn = red + 8 * 128 + e;
            float fr = rr[0] + rr[128] + rr[256] + rr[384];
            float fz = rz[0] + rz[128] + rz[256] + rz[384];
            float fn = rn[0] + rn[128] + rn[256] + rn[384];

            float hp = hc[e];
            float r = sigm(pr + fr + br);
            float z = sigm(pz + fz + bz);
            float n = tanhf(pn + r * (fn + bn));
            float hn = (1.0f - z) * n + z * hp;
            float c  = fminf(fmaxf(hn, -CLIPV), CLIPV);
            hn = c;

            hc[e] = hn;
            out[((size_t)s * BB + b) * out_ld + e] = c;
        }
        pr = npr; pz = npz; pn = npn;
        __syncthreads();
    }
}

// ---- AR1 calcium ----
__global__ void calcium_kernel(const float* __restrict__ spk,
                               const float* __restrict__ gain,
                               const float* __restrict__ biasp,
                               const float* __restrict__ logtau,
                               float* __restrict__ out)
{
    int idx = blockIdx.x * blockDim.x + threadIdx.x;
    if (idx >= BB * NN) return;
    float decay = 1.0f - 1.0f / expf(logtau[0]);
    float gn = gain[0], bp = biasp[0];
    float c = 0.0f;
    for (int t = 0; t < TT; t++) {
        size_t off = (size_t)t * (BB * NN) + idx;
        c = c * decay + gn * spk[off] + bp;
        out[off] = c;
    }
}

extern "C" void kernel_launch(void* const* d_in, const int* in_sizes, int n_in,
                              void* d_out, int out_size)
{
    const float* x       = (const float*)d_in[0];
    const float* factors = (const float*)d_in[1];
    const float* eps     = (const float*)d_in[2];
    const float* eWihf   = (const float*)d_in[3];
    const float* eWhhf   = (const float*)d_in[4];
    const float* ebihf   = (const float*)d_in[5];
    const float* ebhhf   = (const float*)d_in[6];
    const float* eWihb   = (const float*)d_in[7];
    const float* eWhhb   = (const float*)d_in[8];
    const float* ebihb   = (const float*)d_in[9];
    const float* ebhhb   = (const float*)d_in[10];
    const float* einit   = (const float*)d_in[11];
    const float* cWih    = (const float*)d_in[12];
    const float* cWhh    = (const float*)d_in[13];
    const float* cbih    = (const float*)d_in[14];
    const float* cbhh    = (const float*)d_in[15];
    const float* cinit   = (const float*)d_in[16];
    const float* Wmu     = (const float*)d_in[17];
    const float* bmu     = (const float*)d_in[18];
    const float* Wlv     = (const float*)d_in[19];
    const float* blv     = (const float*)d_in[20];
    const float* Wspk    = (const float*)d_in[21];
    const float* bspk    = (const float*)d_in[22];
    const float* gain    = (const float*)d_in[23];
    const float* biasp   = (const float*)d_in[24];
    const float* logtau  = (const float*)d_in[25];
    float* out = (float*)d_out;

    float *p_xpall, *p_hc, *p_uf, *p_spk, *p_ball, *p_wml, *p_bml;
    __nv_bfloat16 *p_xaug, *p_gaug, *p_wall, *p_wga;
    cudaGetSymbolAddress((void**)&p_xpall, d_xpall);
    cudaGetSymbolAddress((void**)&p_hc,  d_hc);
    cudaGetSymbolAddress((void**)&p_uf,  d_uf);
    cudaGetSymbolAddress((void**)&p_spk, d_spk);
    cudaGetSymbolAddress((void**)&p_xaug, d_xaug);
    cudaGetSymbolAddress((void**)&p_gaug, d_gaug);
    cudaGetSymbolAddress((void**)&p_wall, d_wall);
    cudaGetSymbolAddress((void**)&p_wga, d_wga);
    cudaGetSymbolAddress((void**)&p_ball, d_ball);
    cudaGetSymbolAddress((void**)&p_wml, d_wml);
    cudaGetSymbolAddress((void**)&p_bml, d_bml);

    const int MB = MROWS / 128; // 500
    const int hg_smem = 2 * 24576 * (int)sizeof(__nv_bfloat16);  // 98304 B
    cudaFuncSetAttribute(hgemm_kernel, cudaFuncAttributeMaxDynamicSharedMemorySize, hg_smem);

    // ---- single combined aug + prep launch ----
    {
        AugParams P;
        int start = 0;
        P.job[0] = { x, NN, NN, MROWS, p_xaug, KAUG_X, start };
        start += (int)(((long long)MROWS * (KAUG_X / 8) + 255) / 256);           // 20000
        P.job[1] = { eWihf, NN, NN, 384, p_wall, KAUG_X, start };
        start += (int)((384LL * (KAUG_X / 8) + 255) / 256);                      // 120
        P.job[2] = { eWihb, NN, NN, 384, p_wall + (size_t)384 * KAUG_X, KAUG_X, start };
        start += (int)((384LL * (KAUG_X / 8) + 255) / 256);
        P.job[3] = { cWih + 2 * EE, 2 * EE + NN, NN, 384, p_wall + (size_t)768 * KAUG_X, KAUG_X, start };
        start += (int)((384LL * (KAUG_X / 8) + 255) / 256);
        P.job[4] = { cWih, 2 * EE + NN, 2 * EE, 384, p_wga, KAUG_G, start };
        start += (int)((384LL * (KAUG_G / 8) + 255) / 256);                      // 96
        P.prep_start = start;
        start += 64;
        P.bf = ebihf; P.bb = ebihb; P.bc = cbih;
        P.Wmu = Wmu; P.bmu = bmu; P.Wlv = Wlv; P.blv = blv;
        P.ball = p_ball; P.wml = p_wml; P.bml = p_bml;
        aug_all_kernel<<<start, 256>>>(P);
    }

    // ---- fused projection GEMM: [xpf | xpb | cp-x] = xaug @ wall^T + ball ----
    hgemm_kernel<<<dim3(9, MB), 256, hg_smem>>>(p_xaug, p_wall, p_ball, p_xpall, 1152, KAUG_X, 0);

    // ---- bidirectional encoder scan (writes gaug [hi|lo] directly) ----
    gru_scan4_kernel<<<2 * S2P, 512>>>(
        p_xpall, p_xpall + 384, 1152, eWhhf, eWhhb, ebhhf, ebhhb, einit, einit + EE,
        p_gaug);

    // ---- controller projection, g part (accumulate into cp region) ----
    hgemm_kernel<<<dim3(3, MB), 256, hg_smem>>>(p_gaug, p_wga, (const float*)0, p_xpall + 768, 1152, KAUG_G, 1);

    // ---- controller scan ----
    gru_scan1_kernel<<<128, 512>>>(p_xpall + 768, 1152, cWhh, cbhh, cinit, p_hc, 128);

    // ---- fused mu/lv + sampling -> uf ----
    sgemm_kernel<<<dim3(1, MB), 256>>>(p_hc, 128, p_wml, 128, p_bml, p_uf, 68, 128, 128, 4, eps, factors);

    // ---- spike generator (fp32, fused exp-relu) ----
    sgemm_kernel<<<dim3(3, MB), 256>>>(p_uf, 68, Wspk, UU + FF, bspk, p_spk, 300, NN, UU + FF, 2,
                                       (const float*)0, (const float*)0);

    // ---- AR1 calcium ----
    calcium_kernel<<<(BB * NN + 255) / 256, 256>>>(p_spk, gain, biasp, logtau, out);
}

// round 17
// speedup vs baseline: 4.3277x; 1.0042x over previous
#include <cuda_runtime.h>
#include <cuda_bf16.h>
#include <math.h>
#include <stdint.h>

#define TT 500
#define BB 128
#define NN 300
#define EE 128
#define CC 128
#define UU 64
#define FF 4
#define CLIPV 5.0f
#define S2P 64
#define MROWS (TT*BB)       // 64000
#define KAUG_X 640          // [hi|lo], Kpad=320 for K=300
#define KAUG_G 512          // [hi|lo], Kpad=256 for K=256

// ---- static device scratch ----
__device__ float d_xpall[(size_t)MROWS * 1152];  // [xpf | xpb | cp] per row
__device__ float d_hc [MROWS * 128];
__device__ float d_uf [MROWS * 68];
__device__ float d_spk[MROWS * 300];
__device__ __nv_bfloat16 d_xaug[(size_t)MROWS * KAUG_X];
__device__ __nv_bfloat16 d_gaug[(size_t)MROWS * KAUG_G];
__device__ __nv_bfloat16 d_wall[(size_t)1152 * KAUG_X];   // [wf | wb | wx] rows
__device__ __nv_bfloat16 d_wga[384 * KAUG_G];
__device__ float d_ball[1152];
__device__ float d_wml[128 * 128];   // interleaved [mu0,lv0,...] rows
__device__ float d_bml[128];

__device__ __forceinline__ float sigm(float x) { return 1.0f / (1.0f + expf(-x)); }

// ================= combined aug + prep launch =================
struct AugJob {
    const float* src; int ld, K, rows;
    __nv_bfloat16* dst; int Kaug, blk_start;
};
struct AugParams {
    AugJob job[5];
    int prep_start;
    const float *bf, *bb, *bc, *Wmu, *bmu, *Wlv, *blv;
    float *ball, *wml, *bml;
};

__global__ void aug_all_kernel(AugParams P)
{
    int blk = blockIdx.x;
    if (blk >= P.prep_start) {
        int i = (blk - P.prep_start) * 256 + threadIdx.x;
        if (i < 384) P.ball[i] = P.bf[i];
        else if (i < 768) P.ball[i] = P.bb[i - 384];
        else if (i < 1152) P.ball[i] = P.bc[i - 768];
        if (i < 128) {
            int u = i >> 1, h = i & 1;
            P.bml[i] = h ? P.blv[u] : P.bmu[u];
        }
        if (i < 128 * 128) {
            int r = i >> 7, k = i & 127;
            int u = r >> 1, h = r & 1;
            P.wml[i] = h ? P.Wlv[u * 128 + k] : P.Wmu[u * 128 + k];
        }
        return;
    }
    int j = 0;
    if (blk >= P.job[4].blk_start) j = 4;
    else if (blk >= P.job[3].blk_start) j = 3;
    else if (blk >= P.job[2].blk_start) j = 2;
    else if (blk >= P.job[1].blk_start) j = 1;

    const AugJob J = P.job[j];
    int groups = J.Kaug / 8;
    int Kpad = J.Kaug / 2;
    long long idx = (long long)(blk - J.blk_start) * 256 + threadIdx.x;
    if (idx >= (long long)J.rows * groups) return;
    int row = (int)(idx / groups);
    int jj  = (int)(idx - (long long)row * groups);
    int kau0 = jj * 8;
    int seg = kau0 / Kpad;
    int kk0 = kau0 - seg * Kpad;
    bool lo = (seg == 1);
    __nv_bfloat16 vals[8];
#pragma unroll
    for (int i = 0; i < 8; i++) {
        int kk = kk0 + i;
        float v = (kk < J.K) ? J.src[(size_t)row * J.ld + kk] : 0.0f;
        __nv_bfloat16 h = __float2bfloat16(v);
        vals[i] = lo ? __float2bfloat16(v - __bfloat162float(h)) : h;
    }
    *(uint4*)(J.dst + (size_t)row * J.Kaug + kau0) = *(uint4*)vals;
}

// ---- 3-product bf16 mma GEMM: C = Ahi·Bhi + Ahi·Blo + Alo·Bhi (+bias) ----
#define MMA16816(d, a, b) \
    asm volatile("mma.sync.aligned.m16n8k16.row.col.f32.bf16.bf16.f32 " \
        "{%0,%1,%2,%3}, {%4,%5,%6,%7}, {%8,%9}, {%0,%1,%2,%3};" \
        : "+f"((d)[0]), "+f"((d)[1]), "+f"((d)[2]), "+f"((d)[3]) \
        : "r"((a)[0]), "r"((a)[1]), "r"((a)[2]), "r"((a)[3]), \
          "r"((b)[0]), "r"((b)[1]))
#define LDSM_X4(r0, r1, r2, r3, addr) \
    asm volatile("ldmatrix.sync.aligned.m8n8.x4.shared.b16 {%0,%1,%2,%3}, [%4];" \
        : "=r"(r0), "=r"(r1), "=r"(r2), "=r"(r3) : "r"(addr))
#define CP_ASYNC16(smem_addr, gptr) \
    asm volatile("cp.async.cg.shared.global [%0], [%1], 16;" :: "r"(smem_addr), "l"(gptr))
#define CP_COMMIT() asm volatile("cp.async.commit_group;")
#define CP_WAIT(N)  asm volatile("cp.async.wait_group %0;" :: "n"(N))

// stage: 4 tiles {Ahi, Alo, Bhi, Blo}, each 2 kk-subtiles x [128 rows][24 stride]
__global__ __launch_bounds__(256, 2) void hgemm_kernel(
    const __nv_bfloat16* __restrict__ A,   // [Mrows][Kaug]  [hi|lo]
    const __nv_bfloat16* __restrict__ B,   // [N][Kaug]      [hi|lo]
    const float* __restrict__ bias,
    float* __restrict__ C, int ldc, int Kaug, int flags)
{
    extern __shared__ __nv_bfloat16 smem[];
    const int STAGE = 24576;
    const int TILE = 6144;

    const int tid = threadIdx.x;
    const int lane = tid & 31;
    const int wid = tid >> 5;
    const int warp_m = wid >> 2;
    const int warp_n = wid & 3;
    const int m0 = blockIdx.y * 128;
    const int n0 = blockIdx.x * 128;
    const int lrow = tid >> 1;
    const int lhalf = tid & 1;
    const int Kpad = Kaug >> 1;
    const int nch = Kpad >> 5;          // 32 k-cols per chunk

    uint32_t sb = (uint32_t)__cvta_generic_to_shared(smem);

    float acc[4][4][4];
#pragma unroll
    for (int mi = 0; mi < 4; mi++)
#pragma unroll
        for (int ni = 0; ni < 4; ni++)
#pragma unroll
            for (int q = 0; q < 4; q++) acc[mi][ni][q] = 0.0f;

    const __nv_bfloat16* Agp = A + (size_t)(m0 + lrow) * Kaug + lhalf * 8;
    const __nv_bfloat16* Bgp = B + (size_t)(n0 + lrow) * Kaug + lhalf * 8;
    const uint32_t sW = sb + (lrow * 24 + lhalf * 8) * 2;

    const int lr16 = lane & 15;
    const int lh16 = lane >> 4;
    const uint32_t aRd0 = sb + ((warp_m * 64 + lr16) * 24) * 2 + lh16 * 16;
    const uint32_t bRd0 = sb + ((warp_n * 32 + lr16) * 24) * 2 + lh16 * 16;

    // prefetch chunk 0 -> stage 0
#pragma unroll
    for (int kk = 0; kk < 2; kk++) {
        int kg = kk * 16;
        CP_ASYNC16(sW + (0 * TILE + kk * 3072) * 2, Agp + kg);
        CP_ASYNC16(sW + (1 * TILE + kk * 3072) * 2, Agp + Kpad + kg);
        CP_ASYNC16(sW + (2 * TILE + kk * 3072) * 2, Bgp + kg);
        CP_ASYNC16(sW + (3 * TILE + kk * 3072) * 2, Bgp + Kpad + kg);
    }
    CP_COMMIT();

    for (int ci = 0; ci < nch; ci++) {
        int st = ci & 1;
        if (ci + 1 < nch) {
            int st2 = 1 - st;
            int kb = (ci + 1) * 32;
#pragma unroll
            for (int kk = 0; kk < 2; kk++) {
                int kg = kb + kk * 16;
                CP_ASYNC16(sW + (st2 * STAGE + 0 * TILE + kk * 3072) * 2, Agp + kg);
                CP_ASYNC16(sW + (st2 * STAGE + 1 * TILE + kk * 3072) * 2, Agp + Kpad + kg);
                CP_ASYNC16(sW + (st2 * STAGE + 2 * TILE + kk * 3072) * 2, Bgp + kg);
                CP_ASYNC16(sW + (st2 * STAGE + 3 * TILE + kk * 3072) * 2, Bgp + Kpad + kg);
            }
            CP_COMMIT();
            CP_WAIT(1);
        } else {
            CP_WAIT(0);
        }
        __syncthreads();

        uint32_t stoff = (uint32_t)(st * STAGE) * 2;
#pragma unroll
        for (int kk = 0; kk < 2; kk++) {
            uint32_t afh[4][4], afl[4][4];
#pragma unroll
            for (int mi = 0; mi < 4; mi++) {
                uint32_t ad = aRd0 + stoff + (0 * TILE + kk * 3072 + mi * 16 * 24) * 2;
                LDSM_X4(afh[mi][0], afh[mi][1], afh[mi][2], afh[mi][3], ad);
                uint32_t al = aRd0 + stoff + (1 * TILE + kk * 3072 + mi * 16 * 24) * 2;
                LDSM_X4(afl[mi][0], afl[mi][1], afl[mi][2], afl[mi][3], al);
            }
            uint32_t bfh[4][2], bfl[4][2];
#pragma unroll
            for (int np = 0; np < 2; np++) {
                uint32_t r0, r1, r2, r3;
                uint32_t bd = bRd0 + stoff + (2 * TILE + kk * 3072 + np * 16 * 24) * 2;
                LDSM_X4(r0, r1, r2, r3, bd);
                bfh[2 * np][0] = r0; bfh[2 * np + 1][0] = r1;
                bfh[2 * np][1] = r2; bfh[2 * np + 1][1] = r3;
                uint32_t bl = bRd0 + stoff + (3 * TILE + kk * 3072 + np * 16 * 24) * 2;
                LDSM_X4(r0, r1, r2, r3, bl);
                bfl[2 * np][0] = r0; bfl[2 * np + 1][0] = r1;
                bfl[2 * np][1] = r2; bfl[2 * np + 1][1] = r3;
            }
            // product-major order: consecutive MMAs hit different accumulators;
            // per-acc order stays hh -> hl -> lh (bitwise-identical results)
#pragma unroll
            for (int mi = 0; mi < 4; mi++)
#pragma unroll
                for (int ni = 0; ni < 4; ni++)
                    MMA16816(acc[mi][ni], afh[mi], bfh[ni]);
#pragma unroll
            for (int mi = 0; mi < 4; mi++)
#pragma unroll
                for (int ni = 0; ni < 4; ni++)
                    MMA16816(acc[mi][ni], afh[mi], bfl[ni]);
#pragma unroll
            for (int mi = 0; mi < 4; mi++)
#pragma unroll
                for (int ni = 0; ni < 4; ni++)
                    MMA16816(acc[mi][ni], afl[mi], bfh[ni]);
        }
        __syncthreads();
    }

    const int gr = lane >> 2;
    const int gc = (lane & 3) * 2;
#pragma unroll
    for (int mi = 0; mi < 4; mi++) {
#pragma unroll
        for (int ni = 0; ni < 4; ni++) {
            const float* a = acc[mi][ni];
            int m = m0 + warp_m * 64 + mi * 16 + gr;
            int n = n0 + warp_n * 32 + ni * 8 + gc;
            float b0 = bias ? bias[n] : 0.0f;
            float b1 = bias ? bias[n + 1] : 0.0f;
#pragma unroll
            for (int h = 0; h < 2; h++) {
                int mm = m + h * 8;
                float v0 = a[h * 2 + 0] + b0;
                float v1 = a[h * 2 + 1] + b1;
                float* Cp = C + (size_t)mm * ldc + n;
                if (flags & 1) {
                    float2 o = *(float2*)Cp;
                    v0 += o.x; v1 += o.y;
                }
                float2 w; w.x = v0; w.y = v1;
                *(float2*)Cp = w;
            }
        }
    }
}

// ---- fp32 SGEMM. flags bit1: spike epilogue; bit2: fused mu/lv sampling epilogue ----
__global__ __launch_bounds__(256) void sgemm_kernel(
    const float* __restrict__ A, int lda,
    const float* __restrict__ W, int ldw,
    const float* __restrict__ bias,
    float* __restrict__ C, int ldc,
    int N, int K, int flags,
    const float* __restrict__ eps, const float* __restrict__ factors)
{
    __shared__ float As[8][128];
    __shared__ float Ws[8][128];
    const int tid = threadIdx.x;
    const int m0 = blockIdx.y * 128;
    const int n0 = blockIdx.x * 128;
    const int lr = tid >> 1;
    const int lc = (tid & 1) << 2;
    const int tx = tid & 15;
    const int ty = tid >> 4;

    float acc[8][8];
#pragma unroll
    for (int i = 0; i < 8; i++)
#pragma unroll
        for (int j = 0; j < 8; j++) acc[i][j] = 0.0f;

    for (int k0 = 0; k0 < K; k0 += 8) {
        {
            float4 v = make_float4(0.f, 0.f, 0.f, 0.f);
            int kbase = k0 + lc;
            int rem = K - kbase;
            const float* Ap = A + (size_t)(m0 + lr) * lda + kbase;
            if (rem >= 4) v = *(const float4*)Ap;
            else if (rem > 0) {
                v.x = Ap[0];
                if (rem > 1) v.y = Ap[1];
                if (rem > 2) v.z = Ap[2];
            }
            As[lc + 0][lr] = v.x; As[lc + 1][lr] = v.y;
            As[lc + 2][lr] = v.z; As[lc + 3][lr] = v.w;
        }
        {
            float4 v = make_float4(0.f, 0.f, 0.f, 0.f);
            int n = n0 + lr;
            int kbase = k0 + lc;
            int rem = K - kbase;
            if (n < N && rem > 0) {
                const float* Wp = W + (size_t)n * ldw + kbase;
                if (rem >= 4) v = *(const float4*)Wp;
                else {
                    v.x = Wp[0];
                    if (rem > 1) v.y = Wp[1];
                    if (rem > 2) v.z = Wp[2];
                }
            }
            Ws[lc + 0][lr] = v.x; Ws[lc + 1][lr] = v.y;
            Ws[lc + 2][lr] = v.z; Ws[lc + 3][lr] = v.w;
        }
        __syncthreads();
#pragma unroll
        for (int k = 0; k < 8; k++) {
            float a[8], bb[8];
            *(float4*)&a[0]  = *(const float4*)&As[k][ty * 8];
            *(float4*)&a[4]  = *(const float4*)&As[k][ty * 8 + 4];
            *(float4*)&bb[0] = *(const float4*)&Ws[k][tx * 8];
            *(float4*)&bb[4] = *(const float4*)&Ws[k][tx * 8 + 4];
#pragma unroll
            for (int i = 0; i < 8; i++)
#pragma unroll
                for (int j = 0; j < 8; j++)
                    acc[i][j] = fmaf(a[i], bb[j], acc[i][j]);
        }
        __syncthreads();
    }

    if (flags & 4) {
#pragma unroll
        for (int i = 0; i < 8; i++) {
            int m = m0 + ty * 8 + i;
#pragma unroll
            for (int j = 0; j < 8; j += 2) {
                int n = tx * 8 + j;
                float mu = acc[i][j] + bias[n];
                float lv = acc[i][j + 1] + bias[n + 1];
                int u = n >> 1;
                C[(size_t)m * ldc + u] = mu + expf(0.5f * lv) * eps[(size_t)m * 64 + u];
            }
            if (tx == 15) {
#pragma unroll
                for (int q = 0; q < 4; q++)
                    C[(size_t)m * ldc + 64 + q] = factors[(size_t)m * 4 + q];
            }
        }
        return;
    }

#pragma unroll
    for (int i = 0; i < 8; i++) {
        int m = m0 + ty * 8 + i;
#pragma unroll
        for (int j = 0; j < 8; j++) {
            int n = n0 + tx * 8 + j;
            if (n < N) {
                float v = acc[i][j];
                if (bias) v += bias[n];
                size_t off = (size_t)m * ldc + n;
                if (flags & 1) v += C[off];
                if (flags & 2) v = fmaxf(expf(v) - 1.0f, 0.0f);
                C[off] = v;
            }
        }
    }
}

// ---- encoder GRU scan: 2 batches/block, register weights, xp prefetch,
//      writes gaug (bf16 [hi|lo], Kaug=512) directly ----
__global__ __launch_bounds__(512) void gru_scan4_kernel(
    const float* __restrict__ xp_a, const float* __restrict__ xp_b, int xp_ld,
    const float* __restrict__ W_a,  const float* __restrict__ W_b,
    const float* __restrict__ bh_a, const float* __restrict__ bh_b,
    const float* __restrict__ init_a, const float* __restrict__ init_b,
    __nv_bfloat16* __restrict__ gaug)
{
    __shared__ float hc2[2 * 128];
    __shared__ float red[3 * 2 * 4 * 128];

    const int dir = blockIdx.x / S2P;
    const int jb  = blockIdx.x % S2P;
    const float* xp   = dir ? xp_b   : xp_a;
    const float* Whh  = dir ? W_b    : W_a;
    const float* bhh  = dir ? bh_b   : bh_a;
    const float* hini = dir ? init_b : init_a;
    const int colbase = dir ? 128 : 0;
    const int rev     = dir;
    const int b0 = jb * 2;

    const int tid = threadIdx.x;
    const int e  = tid & 127;
    const int kq = tid >> 7;

    float wr[32], wz[32], wn[32];
    {
        const float* r0 = Whh + (size_t)(0 * 128 + e) * 128 + kq * 32;
        const float* r1 = Whh + (size_t)(1 * 128 + e) * 128 + kq * 32;
        const float* r2 = Whh + (size_t)(2 * 128 + e) * 128 + kq * 32;
#pragma unroll
        for (int j4 = 0; j4 < 8; j4++) {
            float4 a = *(const float4*)(r0 + j4 * 4);
            float4 b = *(const float4*)(r1 + j4 * 4);
            float4 c = *(const float4*)(r2 + j4 * 4);
            wr[j4*4+0]=a.x; wr[j4*4+1]=a.y; wr[j4*4+2]=a.z; wr[j4*4+3]=a.w;
            wz[j4*4+0]=b.x; wz[j4*4+1]=b.y; wz[j4*4+2]=b.z; wz[j4*4+3]=b.w;
            wn[j4*4+0]=c.x; wn[j4*4+1]=c.y; wn[j4*4+2]=c.z; wn[j4*4+3]=c.w;
        }
    }
    const float br = bhh[e], bz = bhh[128 + e], bn = bhh[256 + e];

    if (kq < 2) hc2[2 * e + kq] = hini[e];
    __syncthreads();

    const float2* h2 = (const float2*)hc2 + kq * 32;

    float pr = 0.f, pz = 0.f, pn = 0.f;
    if (kq < 2) {
        int t0 = rev ? (TT - 1) : 0;
        const float* xr = xp + ((size_t)t0 * BB + b0 + kq) * xp_ld;
        pr = __ldg(xr + e); pz = __ldg(xr + 128 + e); pn = __ldg(xr + 256 + e);
    }

    for (int s = 0; s < TT; s++) {
        const int t = rev ? (TT - 1 - s) : s;
        float npr = 0.f, npz = 0.f, npn = 0.f;
        if (kq < 2 && s + 1 < TT) {
            int t2 = rev ? (TT - 2 - s) : (s + 1);
            const float* xr = xp + ((size_t)t2 * BB + b0 + kq) * xp_ld;
            npr = __ldg(xr + e); npz = __ldg(xr + 128 + e); npn = __ldg(xr + 256 + e);
        }

        float ar0 = 0.f, ar1 = 0.f, az0 = 0.f, az1 = 0.f, an0 = 0.f, an1 = 0.f;
#pragma unroll
        for (int j = 0; j < 32; j++) {
            float2 h = h2[j];
            ar0 = fmaf(wr[j], h.x, ar0); ar1 = fmaf(wr[j], h.y, ar1);
            az0 = fmaf(wz[j], h.x, az0); az1 = fmaf(wz[j], h.y, az1);
            an0 = fmaf(wn[j], h.x, an0); an1 = fmaf(wn[j], h.y, an1);
        }

        red[((0 * 2 + 0) * 4 + kq) * 128 + e] = ar0;
        red[((0 * 2 + 1) * 4 + kq) * 128 + e] = ar1;
        red[((1 * 2 + 0) * 4 + kq) * 128 + e] = az0;
        red[((1 * 2 + 1) * 4 + kq) * 128 + e] = az1;
        red[((2 * 2 + 0) * 4 + kq) * 128 + e] = an0;
        red[((2 * 2 + 1) * 4 + kq) * 128 + e] = an1;
        __syncthreads();

        if (kq < 2) {
            const int b = kq;
            const float* rr = red + ((0 * 2 + b) * 4) * 128 + e;
            const float* rz = red + ((1 * 2 + b) * 4) * 128 + e;
            const float* rn = red + ((2 * 2 + b) * 4) * 128 + e;
            float fr = rr[0] + rr[128] + rr[256] + rr[384];
            float fz = rz[0] + rz[128] + rz[256] + rz[384];
            float fn = rn[0] + rn[128] + rn[256] + rn[384];

            float hp = hc2[2 * e + b];
            float r = sigm(pr + fr + br);
            float z = sigm(pz + fz + bz);
            float n = tanhf(pn + r * (fn + bn));
            float hn = (1.0f - z) * n + z * hp;
            float c  = fminf(fmaxf(hn, -CLIPV), CLIPV);

            hc2[2 * e + b] = hn;

            size_t rbase = ((size_t)t * BB + b0 + b) * KAUG_G;
            __nv_bfloat16 hi = __float2bfloat16(c);
            __nv_bfloat16 lo = __float2bfloat16(c - __bfloat162float(hi));
            int col = colbase + e;
            gaug[rbase + col] = hi;
            gaug[rbase + 256 + col] = lo;
        }
        pr = npr; pz = npz; pn = npn;
        __syncthreads();
    }
}

// ---- controller GRU scan: 1 batch/block, xp prefetch ----
__global__ __launch_bounds__(512) void gru_scan1_kernel(
    const float* __restrict__ xp, int xp_ld,
    const float* __restrict__ Whh, const float* __restrict__ bhh,
    const float* __restrict__ hini,
    float* __restrict__ out, int out_ld)
{
    __shared__ float hc[128];
    __shared__ float red[3 * 4 * 128];
    const int b = blockIdx.x;
    const int tid = threadIdx.x;
    const int e = tid & 127;
    const int kq = tid >> 7;

    float wr[32], wz[32], wn[32];
    {
        const float* r0 = Whh + (size_t)(0 * 128 + e) * 128 + kq * 32;
        const float* r1 = Whh + (size_t)(1 * 128 + e) * 128 + kq * 32;
        const float* r2 = Whh + (size_t)(2 * 128 + e) * 128 + kq * 32;
#pragma unroll
        for (int j4 = 0; j4 < 8; j4++) {
            float4 a = *(const float4*)(r0 + j4 * 4);
            float4 bq = *(const float4*)(r1 + j4 * 4);
            float4 c = *(const float4*)(r2 + j4 * 4);
            wr[j4*4+0]=a.x;  wr[j4*4+1]=a.y;  wr[j4*4+2]=a.z;  wr[j4*4+3]=a.w;
            wz[j4*4+0]=bq.x; wz[j4*4+1]=bq.y; wz[j4*4+2]=bq.z; wz[j4*4+3]=bq.w;
            wn[j4*4+0]=c.x;  wn[j4*4+1]=c.y;  wn[j4*4+2]=c.z;  wn[j4*4+3]=c.w;
        }
    }
    const float br = bhh[e], bz = bhh[128 + e], bn = bhh[256 + e];

    if (kq == 0) hc[e] = hini[e];
    __syncthreads();

    const float4* h4 = (const float4*)hc + kq * 8;

    float pr = 0.f, pz = 0.f, pn = 0.f;
    if (kq == 0) {
        const float* xr = xp + ((size_t)0 * BB + b) * xp_ld;
        pr = __ldg(xr + e); pz = __ldg(xr + 128 + e); pn = __ldg(xr + 256 + e);
    }

    for (int s = 0; s < TT; s++) {
        float npr = 0.f, npz = 0.f, npn = 0.f;
        if (kq == 0 && s + 1 < TT) {
            const float* xr = xp + ((size_t)(s + 1) * BB + b) * xp_ld;
            npr = __ldg(xr + e); npz = __ldg(xr + 128 + e); npn = __ldg(xr + 256 + e);
        }

        float ar = 0.f, az = 0.f, an = 0.f;
#pragma unroll
        for (int j = 0; j < 8; j++) {
            float4 h = h4[j];
            ar = fmaf(wr[j*4+0], h.x, ar); ar = fmaf(wr[j*4+1], h.y, ar);
            ar = fmaf(wr[j*4+2], h.z, ar); ar = fmaf(wr[j*4+3], h.w, ar);
            az = fmaf(wz[j*4+0], h.x, az); az = fmaf(wz[j*4+1], h.y, az);
            az = fmaf(wz[j*4+2], h.z, az); az = fmaf(wz[j*4+3], h.w, az);
            an = fmaf(wn[j*4+0], h.x, an); an = fmaf(wn[j*4+1], h.y, an);
            an = fmaf(wn[j*4+2], h.z, an); an = fmaf(wn[j*4+3], h.w, an);
        }

        red[(0 * 4 + kq) * 128 + e] = ar;
        red[(1 * 4 + kq) * 128 + e] = az;
        red[(2 * 4 + kq) * 128 + e] = an;
        __syncthreads();

        if (kq == 0) {
            const float* rr = red + e;
            const float* rz = red + 4 * 128 + e;
            const float* rn = red + 8 * 128 + e;
            float fr = rr[0] + rr[128] + rr[256] + rr[384];
            float fz = rz[0] + rz[128] + rz[256] + rz[384];
            float fn = rn[0] + rn[128] + rn[256] + rn[384];

            float hp = hc[e];
            float r = sigm(pr + fr + br);
            float z = sigm(pz + fz + bz);
            float n = tanhf(pn + r * (fn + bn));
            float hn = (1.0f - z) * n + z * hp;
            float c  = fminf(fmaxf(hn, -CLIPV), CLIPV);
            hn = c;

            hc[e] = hn;
            out[((size_t)s * BB + b) * out_ld + e] = c;
        }
        pr = npr; pz = npz; pn = npn;
        __syncthreads();
    }
}

// ---- AR1 calcium ----
__global__ void calcium_kernel(const float* __restrict__ spk,
                               const float* __restrict__ gain,
                               const float* __restrict__ biasp,
                               const float* __restrict__ logtau,
                               float* __restrict__ out)
{
    int idx = blockIdx.x * blockDim.x + threadIdx.x;
    if (idx >= BB * NN) return;
    float decay = 1.0f - 1.0f / expf(logtau[0]);
    float gn = gain[0], bp = biasp[0];
    float c = 0.0f;
    for (int t = 0; t < TT; t++) {
        size_t off = (size_t)t * (BB * NN) + idx;
        c = c * decay + gn * spk[off] + bp;
        out[off] = c;
    }
}

extern "C" void kernel_launch(void* const* d_in, const int* in_sizes, int n_in,
                              void* d_out, int out_size)
{
    const float* x       = (const float*)d_in[0];
    const float* factors = (const float*)d_in[1];
    const float* eps     = (const float*)d_in[2];
    const float* eWihf   = (const float*)d_in[3];
    const float* eWhhf   = (const float*)d_in[4];
    const float* ebihf   = (const float*)d_in[5];
    const float* ebhhf   = (const float*)d_in[6];
    const float* eWihb   = (const float*)d_in[7];
    const float* eWhhb   = (const float*)d_in[8];
    const float* ebihb   = (const float*)d_in[9];
    const float* ebhhb   = (const float*)d_in[10];
    const float* einit   = (const float*)d_in[11];
    const float* cWih    = (const float*)d_in[12];
    const float* cWhh    = (const float*)d_in[13];
    const float* cbih    = (const float*)d_in[14];
    const float* cbhh    = (const float*)d_in[15];
    const float* cinit   = (const float*)d_in[16];
    const float* Wmu     = (const float*)d_in[17];
    const float* bmu     = (const float*)d_in[18];
    const float* Wlv     = (const float*)d_in[19];
    const float* blv     = (const float*)d_in[20];
    const float* Wspk    = (const float*)d_in[21];
    const float* bspk    = (const float*)d_in[22];
    const float* gain    = (const float*)d_in[23];
    const float* biasp   = (const float*)d_in[24];
    const float* logtau  = (const float*)d_in[25];
    float* out = (float*)d_out;

    float *p_xpall, *p_hc, *p_uf, *p_spk, *p_ball, *p_wml, *p_bml;
    __nv_bfloat16 *p_xaug, *p_gaug, *p_wall, *p_wga;
    cudaGetSymbolAddress((void**)&p_xpall, d_xpall);
    cudaGetSymbolAddress((void**)&p_hc,  d_hc);
    cudaGetSymbolAddress((void**)&p_uf,  d_uf);
    cudaGetSymbolAddress((void**)&p_spk, d_spk);
    cudaGetSymbolAddress((void**)&p_xaug, d_xaug);
    cudaGetSymbolAddress((void**)&p_gaug, d_gaug);
    cudaGetSymbolAddress((void**)&p_wall, d_wall);
    cudaGetSymbolAddress((void**)&p_wga, d_wga);
    cudaGetSymbolAddress((void**)&p_ball, d_ball);
    cudaGetSymbolAddress((void**)&p_wml, d_wml);
    cudaGetSymbolAddress((void**)&p_bml, d_bml);

    const int MB = MROWS / 128; // 500
    const int hg_smem = 2 * 24576 * (int)sizeof(__nv_bfloat16);  // 98304 B
    cudaFuncSetAttribute(hgemm_kernel, cudaFuncAttributeMaxDynamicSharedMemorySize, hg_smem);

    // ---- single combined aug + prep launch ----
    {
        AugParams P;
        int start = 0;
        P.job[0] = { x, NN, NN, MROWS, p_xaug, KAUG_X, start };
        start += (int)(((long long)MROWS * (KAUG_X / 8) + 255) / 256);
        P.job[1] = { eWihf, NN, NN, 384, p_wall, KAUG_X, start };
        start += (int)((384LL * (KAUG_X / 8) + 255) / 256);
        P.job[2] = { eWihb, NN, NN, 384, p_wall + (size_t)384 * KAUG_X, KAUG_X, start };
        start += (int)((384LL * (KAUG_X / 8) + 255) / 256);
        P.job[3] = { cWih + 2 * EE, 2 * EE + NN, NN, 384, p_wall + (size_t)768 * KAUG_X, KAUG_X, start };
        start += (int)((384LL * (KAUG_X / 8) + 255) / 256);
        P.job[4] = { cWih, 2 * EE + NN, 2 * EE, 384, p_wga, KAUG_G, start };
        start += (int)((384LL * (KAUG_G / 8) + 255) / 256);
        P.prep_start = start;
        start += 64;
        P.bf = ebihf; P.bb = ebihb; P.bc = cbih;
        P.Wmu = Wmu; P.bmu = bmu; P.Wlv = Wlv; P.blv = blv;
        P.ball = p_ball; P.wml = p_wml; P.bml = p_bml;
        aug_all_kernel<<<start, 256>>>(P);
    }

    // ---- fused projection GEMM: [xpf | xpb | cp-x] = xaug @ wall^T + ball ----
    hgemm_kernel<<<dim3(9, MB), 256, hg_smem>>>(p_xaug, p_wall, p_ball, p_xpall, 1152, KAUG_X, 0);

    // ---- bidirectional encoder scan (writes gaug [hi|lo] directly) ----
    gru_scan4_kernel<<<2 * S2P, 512>>>(
        p_xpall, p_xpall + 384, 1152, eWhhf, eWhhb, ebhhf, ebhhb, einit, einit + EE,
        p_gaug);

    // ---- controller projection, g part (accumulate into cp region) ----
    hgemm_kernel<<<dim3(3, MB), 256, hg_smem>>>(p_gaug, p_wga, (const float*)0, p_xpall + 768, 1152, KAUG_G, 1);

    // ---- controller scan ----
    gru_scan1_kernel<<<128, 512>>>(p_xpall + 768, 1152, cWhh, cbhh, cinit, p_hc, 128);

    // ---- fused mu/lv + sampling -> uf ----
    sgemm_kernel<<<dim3(1, MB), 256>>>(p_hc, 128, p_wml, 128, p_bml, p_uf, 68, 128, 128, 4, eps, factors);

    // ---- spike generator (fp32, fused exp-relu) ----
    sgemm_kernel<<<dim3(3, MB), 256>>>(p_uf, 68, Wspk, UU + FF, bspk, p_spk, 300, NN, UU + FF, 2,
                                       (const float*)0, (const float*)0);

    // ---- AR1 calcium ----
    calcium_kernel<<<(BB * NN + 255) / 256, 256>>>(p_spk, gain, biasp, logtau, out);
}